// round 4
// baseline (speedup 1.0000x reference)
#include <cuda_runtime.h>
#include <math.h>
#include <stdint.h>

// ---------------- problem constants ----------------
constexpr int cH   = 16;
constexpr int cDH  = 128;
constexpr int cRK  = 512;
constexpr int cRD  = 64;
constexpr int cB   = 2;
constexpr int cL   = 2048;
constexpr int cE   = 2048;
constexpr int cDQK = cDH + cRD;          // 192
constexpr int cNQ  = cH * cDQK;          // 3072
constexpr int cNKV = cRK + cRD;          // 576
constexpr int cNUP = cH * (2*cDH + cRD); // 5120
constexpr int cM   = cB * cL;            // 4096
constexpr int cBH  = cB * cH;            // 32

// ---------------- scratch ----------------
__device__ float g_qall[(size_t)cM * cNQ];
__device__ float g_kv  [(size_t)cM * cNKV];
__device__ float g_up  [(size_t)cM * cNUP];
__device__ float g_Q   [(size_t)cBH * cL * cDQK];
__device__ float g_K   [(size_t)cBH * cL * cDQK];
__device__ float g_V   [(size_t)cBH * cL * cDQK];
__device__ float g_AO  [(size_t)cM * cNQ];

// ---------------- tf32 helpers ----------------
__device__ __forceinline__ uint32_t f2tf32(float x) {
    uint32_t u;
    asm("cvt.rna.tf32.f32 %0, %1;" : "=r"(u) : "f"(x));
    return u;
}

__device__ __forceinline__ void mma_tf32(float* d, const uint32_t* a, const uint32_t* b) {
    asm volatile(
        "mma.sync.aligned.m16n8k8.row.col.f32.tf32.tf32.f32 "
        "{%0,%1,%2,%3},{%4,%5,%6,%7},{%8,%9},{%0,%1,%2,%3};"
        : "+f"(d[0]), "+f"(d[1]), "+f"(d[2]), "+f"(d[3])
        : "r"(a[0]), "r"(a[1]), "r"(a[2]), "r"(a[3]), "r"(b[0]), "r"(b[1]));
}

// ---------------- tf32 tensor-core GEMM (linear layers) ----------------
constexpr int TBM = 128, TBK = 16;

template<int TBN_, int WM, int WN>
__global__ void __launch_bounds__(256)
tgemm(const float* __restrict__ A, const float* __restrict__ B,
      float* __restrict__ C, int K, int lda, int ldb, int ldc, float alpha)
{
    constexpr int MI = WM / 16;
    constexpr int NJ = WN / 8;
    constexpr int WARPS_M = TBM / WM;
    constexpr int BPAD = 8;

    const int m0 = blockIdx.y * TBM;
    const int n0 = blockIdx.x * TBN_;

    __shared__ uint32_t As[2][TBM][TBK + 4];
    __shared__ uint32_t Bs[2][TBK][TBN_ + BPAD];

    const int tid  = threadIdx.x;
    const int lane = tid & 31;
    const int warp = tid >> 5;
    const int wm0 = (warp % WARPS_M) * WM;
    const int wn0 = (warp / WARPS_M) * WN;

    float acc[MI][NJ][4];
#pragma unroll
    for (int i = 0; i < MI; i++)
#pragma unroll
        for (int j = 0; j < NJ; j++)
#pragma unroll
            for (int r = 0; r < 4; r++) acc[i][j][r] = 0.0f;

    const int ar = tid >> 2, ac = (tid & 3) * 4;
    const int br = tid >> 4, bc128 = (tid & 15) * 8;
    const int bc64 = (tid & 15) * 4;

    float4 ra[2], rb[2];

    auto loadG = [&](int k0) {
        ra[0] = *reinterpret_cast<const float4*>(&A[(size_t)(m0 + ar) * lda + k0 + ac]);
        ra[1] = *reinterpret_cast<const float4*>(&A[(size_t)(m0 + ar + 64) * lda + k0 + ac]);
        if (TBN_ == 128) {
            rb[0] = *reinterpret_cast<const float4*>(&B[(size_t)(k0 + br) * ldb + n0 + bc128]);
            rb[1] = *reinterpret_cast<const float4*>(&B[(size_t)(k0 + br) * ldb + n0 + bc128 + 4]);
        } else {
            rb[0] = *reinterpret_cast<const float4*>(&B[(size_t)(k0 + br) * ldb + n0 + bc64]);
        }
    };
    auto storeS = [&](int buf) {
#pragma unroll
        for (int h = 0; h < 2; h++) {
            uint4 t = { f2tf32(ra[h].x), f2tf32(ra[h].y), f2tf32(ra[h].z), f2tf32(ra[h].w) };
            *reinterpret_cast<uint4*>(&As[buf][ar + h * 64][ac]) = t;
        }
        if (TBN_ == 128) {
            uint4 t0 = { f2tf32(rb[0].x), f2tf32(rb[0].y), f2tf32(rb[0].z), f2tf32(rb[0].w) };
            uint4 t1 = { f2tf32(rb[1].x), f2tf32(rb[1].y), f2tf32(rb[1].z), f2tf32(rb[1].w) };
            *reinterpret_cast<uint4*>(&Bs[buf][br][bc128]) = t0;
            *reinterpret_cast<uint4*>(&Bs[buf][br][bc128 + 4]) = t1;
        } else {
            uint4 t0 = { f2tf32(rb[0].x), f2tf32(rb[0].y), f2tf32(rb[0].z), f2tf32(rb[0].w) };
            *reinterpret_cast<uint4*>(&Bs[buf][br][bc64]) = t0;
        }
    };

    loadG(0);
    int buf = 0;
    for (int k0 = 0; k0 < K; k0 += TBK) {
        storeS(buf);
        __syncthreads();
        if (k0 + TBK < K) loadG(k0 + TBK);

#pragma unroll
        for (int s = 0; s < 2; s++) {
            const int kc = s * 8 + (lane & 3);
            uint32_t a[MI][4], b[NJ][2];
#pragma unroll
            for (int i = 0; i < MI; i++) {
                const int r0 = wm0 + i * 16 + (lane >> 2);
                a[i][0] = As[buf][r0][kc];
                a[i][1] = As[buf][r0 + 8][kc];
                a[i][2] = As[buf][r0][kc + 4];
                a[i][3] = As[buf][r0 + 8][kc + 4];
            }
#pragma unroll
            for (int j = 0; j < NJ; j++) {
                const int col = wn0 + j * 8 + (lane >> 2);
                b[j][0] = Bs[buf][s * 8 + (lane & 3)][col];
                b[j][1] = Bs[buf][s * 8 + 4 + (lane & 3)][col];
            }
#pragma unroll
            for (int i = 0; i < MI; i++)
#pragma unroll
                for (int j = 0; j < NJ; j++)
                    mma_tf32(acc[i][j], a[i], b[j]);
        }
        buf ^= 1;
    }

#pragma unroll
    for (int i = 0; i < MI; i++) {
#pragma unroll
        for (int j = 0; j < NJ; j++) {
            const int r = m0 + wm0 + i * 16 + (lane >> 2);
            const int c = n0 + wn0 + j * 8 + (lane & 3) * 2;
            float2 v0 = { alpha * acc[i][j][0], alpha * acc[i][j][1] };
            float2 v1 = { alpha * acc[i][j][2], alpha * acc[i][j][3] };
            *reinterpret_cast<float2*>(&C[(size_t)r * ldc + c]) = v0;
            *reinterpret_cast<float2*>(&C[(size_t)(r + 8) * ldc + c]) = v1;
        }
    }
}

// ---------------- fused flash attention (tf32 MMA, online softmax) ----------------
// CTA: one (bh, 64-q-row block). 4 warps, each owns 16 q rows.
// Loops over 64-key blocks up to the causal diagonal.
constexpr int FBR = 64;                 // q rows per CTA
constexpr int FBC = 64;                 // k cols per iteration
constexpr int QSTR = 204;               // word stride for Q/K/V tiles (bank-clean)
constexpr int PSTR = 72;                // word stride for P tile
constexpr int FSMEM = (3 * FBR * QSTR + FBR * PSTR) * 4;  // 175,104 B

__global__ void __launch_bounds__(128)
flash_attn_kernel(float scale)
{
    extern __shared__ uint32_t sh[];
    uint32_t* Qs = sh;
    uint32_t* Ks = Qs + FBR * QSTR;
    uint32_t* Vs = Ks + FBC * QSTR;
    uint32_t* Ps = Vs + FBC * QSTR;

    const int mb = (int)gridDim.x - 1 - (int)blockIdx.x;  // heavy blocks first
    const int bh = blockIdx.y;
    const int b = bh / cH, h = bh % cH;
    const int m0 = mb * FBR;
    const int tid = threadIdx.x;
    const int lane = tid & 31, warp = tid >> 5;
    const int wr = warp * 16;
    const int qr = lane >> 2, qc = lane & 3;

    const float* Qg = g_Q + (size_t)bh * cL * cDQK;
    const float* Kg = g_K + (size_t)bh * cL * cDQK;
    const float* Vg = g_V + (size_t)bh * cL * cDQK;

    // ---- load Q tile (64 x 192) as tf32 ----
    for (int i = tid; i < FBR * (cDQK / 4); i += 128) {
        int r = i / 48, c4 = (i % 48) * 4;
        float4 v = *reinterpret_cast<const float4*>(&Qg[(size_t)(m0 + r) * cDQK + c4]);
        uint4 t = { f2tf32(v.x), f2tf32(v.y), f2tf32(v.z), f2tf32(v.w) };
        *reinterpret_cast<uint4*>(&Qs[r * QSTR + c4]) = t;
    }

    float oacc[24][4];
#pragma unroll
    for (int j = 0; j < 24; j++)
#pragma unroll
        for (int e = 0; e < 4; e++) oacc[j][e] = 0.0f;
    float mrow[2] = { -1e30f, -1e30f };
    float lrow[2] = { 0.0f, 0.0f };

    for (int kb = 0; kb <= mb; kb++) {
        __syncthreads();   // protect Ks/Vs from previous iteration's readers
        for (int i = tid; i < FBC * (cDQK / 4); i += 128) {
            int r = i / 48, c4 = (i % 48) * 4;
            size_t go = (size_t)(kb * FBC + r) * cDQK + c4;
            float4 kv = *reinterpret_cast<const float4*>(&Kg[go]);
            float4 vv = *reinterpret_cast<const float4*>(&Vg[go]);
            uint4 tk = { f2tf32(kv.x), f2tf32(kv.y), f2tf32(kv.z), f2tf32(kv.w) };
            uint4 tv = { f2tf32(vv.x), f2tf32(vv.y), f2tf32(vv.z), f2tf32(vv.w) };
            *reinterpret_cast<uint4*>(&Ks[r * QSTR + c4]) = tk;
            *reinterpret_cast<uint4*>(&Vs[r * QSTR + c4]) = tv;
        }
        __syncthreads();

        // ---- S = Q @ K^T (16x64 per warp) ----
        float sacc[8][4];
#pragma unroll
        for (int j = 0; j < 8; j++)
#pragma unroll
            for (int e = 0; e < 4; e++) sacc[j][e] = 0.0f;

#pragma unroll
        for (int ks = 0; ks < 24; ks++) {
            const int kc = ks * 8 + qc;
            uint32_t a[4] = {
                Qs[(wr + qr) * QSTR + kc],
                Qs[(wr + 8 + qr) * QSTR + kc],
                Qs[(wr + qr) * QSTR + kc + 4],
                Qs[(wr + 8 + qr) * QSTR + kc + 4]
            };
#pragma unroll
            for (int j = 0; j < 8; j++) {
                uint32_t bf[2] = {
                    Ks[(j * 8 + qr) * QSTR + ks * 8 + qc],
                    Ks[(j * 8 + qr) * QSTR + ks * 8 + 4 + qc]
                };
                mma_tf32(sacc[j], a, bf);
            }
        }

        // ---- scale + causal mask + tile row-max ----
        const bool diag = (kb == mb);
        const int rowg0 = m0 + wr + qr;        // row for elements 0,1
        float tmax[2] = { -1e30f, -1e30f };
#pragma unroll
        for (int j = 0; j < 8; j++) {
#pragma unroll
            for (int e = 0; e < 4; e++) {
                float s = sacc[j][e] * scale;
                if (diag) {
                    int col = kb * FBC + j * 8 + 2 * qc + (e & 1);
                    int row = rowg0 + 8 * (e >> 1);
                    if (col > row) s = -1e30f;
                }
                sacc[j][e] = s;
                tmax[e >> 1] = fmaxf(tmax[e >> 1], s);
            }
        }
#pragma unroll
        for (int half = 0; half < 2; half++) {
            tmax[half] = fmaxf(tmax[half], __shfl_xor_sync(0xffffffffu, tmax[half], 1));
            tmax[half] = fmaxf(tmax[half], __shfl_xor_sync(0xffffffffu, tmax[half], 2));
        }

        float mnew[2], alpha[2], psum[2] = { 0.0f, 0.0f };
#pragma unroll
        for (int half = 0; half < 2; half++) {
            mnew[half] = fmaxf(mrow[half], tmax[half]);
            alpha[half] = __expf(mrow[half] - mnew[half]);
            mrow[half] = mnew[half];
        }

        // ---- P = exp(S - m), write tf32 into Ps ----
#pragma unroll
        for (int j = 0; j < 8; j++) {
            float p0 = __expf(sacc[j][0] - mnew[0]);
            float p1 = __expf(sacc[j][1] - mnew[0]);
            float p2 = __expf(sacc[j][2] - mnew[1]);
            float p3 = __expf(sacc[j][3] - mnew[1]);
            psum[0] += p0 + p1;
            psum[1] += p2 + p3;
            uint2 w0 = { f2tf32(p0), f2tf32(p1) };
            uint2 w1 = { f2tf32(p2), f2tf32(p3) };
            *reinterpret_cast<uint2*>(&Ps[(wr + qr) * PSTR + j * 8 + 2 * qc]) = w0;
            *reinterpret_cast<uint2*>(&Ps[(wr + 8 + qr) * PSTR + j * 8 + 2 * qc]) = w1;
        }
#pragma unroll
        for (int half = 0; half < 2; half++) {
            psum[half] += __shfl_xor_sync(0xffffffffu, psum[half], 1);
            psum[half] += __shfl_xor_sync(0xffffffffu, psum[half], 2);
            lrow[half] = lrow[half] * alpha[half] + psum[half];
        }

        // ---- rescale O ----
#pragma unroll
        for (int j = 0; j < 24; j++) {
            oacc[j][0] *= alpha[0];
            oacc[j][1] *= alpha[0];
            oacc[j][2] *= alpha[1];
            oacc[j][3] *= alpha[1];
        }

        __syncwarp();   // P visible within the warp

        // ---- O += P @ V (16x192 per warp, k=64) ----
#pragma unroll
        for (int ks = 0; ks < 8; ks++) {
            uint32_t a[4] = {
                Ps[(wr + qr) * PSTR + ks * 8 + qc],
                Ps[(wr + 8 + qr) * PSTR + ks * 8 + qc],
                Ps[(wr + qr) * PSTR + ks * 8 + 4 + qc],
                Ps[(wr + 8 + qr) * PSTR + ks * 8 + 4 + qc]
            };
#pragma unroll
            for (int j = 0; j < 24; j++) {
                uint32_t bf[2] = {
                    Vs[(ks * 8 + qc) * QSTR + j * 8 + qr],
                    Vs[(ks * 8 + 4 + qc) * QSTR + j * 8 + qr]
                };
                mma_tf32(oacc[j], a, bf);
            }
        }
        __syncwarp();   // P reads done before next iteration overwrites
    }

    // ---- epilogue: O /= l, write to g_AO (b, l, h*192 + d) ----
    const float inv0 = 1.0f / lrow[0];
    const float inv1 = 1.0f / lrow[1];
    const size_t base0 = ((size_t)b * cL + (m0 + wr + qr)) * cNQ + (size_t)h * cDQK;
    const size_t base1 = base0 + 8 * cNQ;
#pragma unroll
    for (int j = 0; j < 24; j++) {
        const int c = j * 8 + 2 * qc;
        float2 v0 = { oacc[j][0] * inv0, oacc[j][1] * inv0 };
        float2 v1 = { oacc[j][2] * inv1, oacc[j][3] * inv1 };
        *reinterpret_cast<float2*>(&g_AO[base0 + c]) = v0;
        *reinterpret_cast<float2*>(&g_AO[base1 + c]) = v1;
    }
}

// ---------------- RoPE ----------------
__global__ void rope_q_kernel(const float* __restrict__ cosT, const float* __restrict__ sinT)
{
    int idx = blockIdx.x * blockDim.x + threadIdx.x;
    if (idx >= cM * cH * (cRD / 2)) return;
    int i = idx % (cRD / 2);
    int h = (idx / (cRD / 2)) % cH;
    int row = idx / ((cRD / 2) * cH);
    int l = row % cL;
    float c = cosT[l * (cRD / 2) + i];
    float s = sinT[l * (cRD / 2) + i];
    float* p = &g_qall[(size_t)row * cNQ + h * cDQK + cDH + 2 * i];
    float x1 = p[0], x2 = p[1];
    p[0] = x1 * c - x2 * s;
    p[1] = x1 * s + x2 * c;
}

__global__ void rope_k_kernel(const float* __restrict__ cosT, const float* __restrict__ sinT)
{
    int idx = blockIdx.x * blockDim.x + threadIdx.x;
    if (idx >= cM * (cRD / 2)) return;
    int i = idx % (cRD / 2);
    int row = idx / (cRD / 2);
    int l = row % cL;
    float c = cosT[l * (cRD / 2) + i];
    float s = sinT[l * (cRD / 2) + i];
    float* p = &g_kv[(size_t)row * cNKV + cRK + 2 * i];
    float x1 = p[0], x2 = p[1];
    p[0] = x1 * c - x2 * s;
    p[1] = x1 * s + x2 * c;
}

// ---------------- gather Q/K/V ----------------
__global__ void build_qkv_kernel()
{
    size_t idx = (size_t)blockIdx.x * blockDim.x + threadIdx.x;
    const size_t total = (size_t)cBH * cL * cDQK;
    if (idx >= total) return;
    int d = (int)(idx % cDQK);
    int l = (int)((idx / cDQK) % cL);
    int bh = (int)(idx / ((size_t)cDQK * cL));
    int b = bh / cH, h = bh % cH;
    size_t row = (size_t)b * cL + l;

    g_Q[idx] = g_qall[row * cNQ + h * cDQK + d];
    float k, v;
    const size_t upo = row * cNUP + (size_t)h * (2 * cDH + cRD);
    if (d < cDH) {
        k = g_up[upo + d];
        v = g_up[upo + cDH + d];
    } else {
        k = g_kv[row * cNKV + cRK + (d - cDH)];
        v = g_up[upo + 2 * cDH + (d - cDH)];
    }
    g_K[idx] = k;
    g_V[idx] = v;
}

// ---------------- launch ----------------
extern "C" void kernel_launch(void* const* d_in, const int* in_sizes, int n_in,
                              void* d_out, int out_size)
{
    const float* x    = (const float*)d_in[0];
    const float* cosT = (const float*)d_in[1];
    const float* sinT = (const float*)d_in[2];
    const float* wq   = (const float*)d_in[3];
    const float* wkvd = (const float*)d_in[4];
    const float* wup  = (const float*)d_in[5];
    const float* wout = (const float*)d_in[6];
    float* out = (float*)d_out;

    float *p_qall, *p_kv, *p_up, *p_ao;
    cudaGetSymbolAddress((void**)&p_qall, g_qall);
    cudaGetSymbolAddress((void**)&p_kv,   g_kv);
    cudaGetSymbolAddress((void**)&p_up,   g_up);
    cudaGetSymbolAddress((void**)&p_ao,   g_AO);

    static bool attr_done = false;
    if (!attr_done) {
        cudaFuncSetAttribute(flash_attn_kernel,
                             cudaFuncAttributeMaxDynamicSharedMemorySize, FSMEM);
        attr_done = true;
    }

    const float scale = 1.0f / sqrtf((float)cDQK);

    // 1) q_all = x @ wq   (4096 x 3072 x 2048)
    tgemm<128, 64, 32><<<dim3(cNQ / 128, cM / TBM, 1), 256>>>(
        x, wq, p_qall, cE, cE, cNQ, cNQ, 1.0f);
    // 2) kv_lat = x @ wkv_down   (4096 x 576 x 2048)
    tgemm<64, 32, 32><<<dim3(cNKV / 64, cM / TBM, 1), 256>>>(
        x, wkvd, p_kv, cE, cE, cNKV, cNKV, 1.0f);
    // 3) RoPE
    rope_q_kernel<<<(cM * cH * (cRD / 2) + 255) / 256, 256>>>(cosT, sinT);
    rope_k_kernel<<<(cM * (cRD / 2) + 255) / 256, 256>>>(cosT, sinT);
    // 4) up = c_kv @ w_up   (4096 x 5120 x 512)
    tgemm<128, 64, 32><<<dim3(cNUP / 128, cM / TBM, 1), 256>>>(
        p_kv, wup, p_up, cRK, cNKV, cNUP, cNUP, 1.0f);
    // 5) gather
    {
        size_t total = (size_t)cBH * cL * cDQK;
        build_qkv_kernel<<<(unsigned)((total + 255) / 256), 256>>>();
    }
    // 6-8) fused flash attention -> g_AO
    flash_attn_kernel<<<dim3(cL / FBR, cBH), 128, FSMEM>>>(scale);
    // 9) out = AO @ w_out   (4096 x 2048 x 3072)
    tgemm<128, 64, 32><<<dim3(cE / 128, cM / TBM, 1), 256>>>(
        p_ao, wout, out, cNQ, cNQ, cE, cE, 1.0f);
}

// round 5
// speedup vs baseline: 1.2002x; 1.2002x over previous
#include <cuda_runtime.h>
#include <cuda_fp16.h>
#include <math.h>
#include <stdint.h>

// ---------------- problem constants ----------------
constexpr int cH   = 16;
constexpr int cDH  = 128;
constexpr int cRK  = 512;
constexpr int cRD  = 64;
constexpr int cB   = 2;
constexpr int cL   = 2048;
constexpr int cE   = 2048;
constexpr int cDQK = cDH + cRD;          // 192
constexpr int cNQ  = cH * cDQK;          // 3072
constexpr int cNKV = cRK + cRD;          // 576
constexpr int cNUP = cH * (2*cDH + cRD); // 5120
constexpr int cM   = cB * cL;            // 4096
constexpr int cBH  = cB * cH;            // 32

// ---------------- scratch ----------------
__device__ float  g_qall[(size_t)cM * cNQ];
__device__ float  g_kv  [(size_t)cM * cNKV];
__device__ float  g_up  [(size_t)cM * cNUP];
__device__ __half g_Qh  [(size_t)cBH * cL * cDQK];
__device__ __half g_Kh  [(size_t)cBH * cL * cDQK];
__device__ float  g_V   [(size_t)cBH * cL * cDQK];   // pre-rounded to tf32
__device__ float  g_AO  [(size_t)cM * cNQ];

// ---------------- helpers ----------------
__device__ __forceinline__ uint32_t f2tf32(float x) {
    uint32_t u;
    asm("cvt.rna.tf32.f32 %0, %1;" : "=r"(u) : "f"(x));
    return u;
}

__device__ __forceinline__ void mma_tf32(float* d, const uint32_t* a, const uint32_t* b) {
    asm volatile(
        "mma.sync.aligned.m16n8k8.row.col.f32.tf32.tf32.f32 "
        "{%0,%1,%2,%3},{%4,%5,%6,%7},{%8,%9},{%0,%1,%2,%3};"
        : "+f"(d[0]), "+f"(d[1]), "+f"(d[2]), "+f"(d[3])
        : "r"(a[0]), "r"(a[1]), "r"(a[2]), "r"(a[3]), "r"(b[0]), "r"(b[1]));
}

__device__ __forceinline__ void mma_f16(float* d, const uint32_t* a, const uint32_t* b) {
    asm volatile(
        "mma.sync.aligned.m16n8k16.row.col.f32.f16.f16.f32 "
        "{%0,%1,%2,%3},{%4,%5,%6,%7},{%8,%9},{%0,%1,%2,%3};"
        : "+f"(d[0]), "+f"(d[1]), "+f"(d[2]), "+f"(d[3])
        : "r"(a[0]), "r"(a[1]), "r"(a[2]), "r"(a[3]), "r"(b[0]), "r"(b[1]));
}

__device__ __forceinline__ void cpa16(uint32_t s, const void* g) {
    asm volatile("cp.async.cg.shared.global [%0], [%1], 16;\n" :: "r"(s), "l"(g));
}
__device__ __forceinline__ void cp_commit() {
    asm volatile("cp.async.commit_group;\n" ::: "memory");
}
template<int N>
__device__ __forceinline__ void cp_wait() {
    asm volatile("cp.async.wait_group %0;\n" :: "n"(N) : "memory");
}

// ---------------- tf32 tensor-core GEMM (linear layers) ----------------
constexpr int TBM = 128, TBK = 16;

template<int TBN_, int WM, int WN>
__global__ void __launch_bounds__(256)
tgemm(const float* __restrict__ A, const float* __restrict__ B,
      float* __restrict__ C, int K, int lda, int ldb, int ldc, float alpha)
{
    constexpr int MI = WM / 16;
    constexpr int NJ = WN / 8;
    constexpr int WARPS_M = TBM / WM;
    constexpr int BPAD = 8;

    const int m0 = blockIdx.y * TBM;
    const int n0 = blockIdx.x * TBN_;

    __shared__ uint32_t As[2][TBM][TBK + 4];
    __shared__ uint32_t Bs[2][TBK][TBN_ + BPAD];

    const int tid  = threadIdx.x;
    const int lane = tid & 31;
    const int warp = tid >> 5;
    const int wm0 = (warp % WARPS_M) * WM;
    const int wn0 = (warp / WARPS_M) * WN;

    float acc[MI][NJ][4];
#pragma unroll
    for (int i = 0; i < MI; i++)
#pragma unroll
        for (int j = 0; j < NJ; j++)
#pragma unroll
            for (int r = 0; r < 4; r++) acc[i][j][r] = 0.0f;

    const int ar = tid >> 2, ac = (tid & 3) * 4;
    const int br = tid >> 4, bc128 = (tid & 15) * 8;
    const int bc64 = (tid & 15) * 4;

    float4 ra[2], rb[2];

    auto loadG = [&](int k0) {
        ra[0] = *reinterpret_cast<const float4*>(&A[(size_t)(m0 + ar) * lda + k0 + ac]);
        ra[1] = *reinterpret_cast<const float4*>(&A[(size_t)(m0 + ar + 64) * lda + k0 + ac]);
        if (TBN_ == 128) {
            rb[0] = *reinterpret_cast<const float4*>(&B[(size_t)(k0 + br) * ldb + n0 + bc128]);
            rb[1] = *reinterpret_cast<const float4*>(&B[(size_t)(k0 + br) * ldb + n0 + bc128 + 4]);
        } else {
            rb[0] = *reinterpret_cast<const float4*>(&B[(size_t)(k0 + br) * ldb + n0 + bc64]);
        }
    };
    auto storeS = [&](int buf) {
#pragma unroll
        for (int h = 0; h < 2; h++) {
            uint4 t = { f2tf32(ra[h].x), f2tf32(ra[h].y), f2tf32(ra[h].z), f2tf32(ra[h].w) };
            *reinterpret_cast<uint4*>(&As[buf][ar + h * 64][ac]) = t;
        }
        if (TBN_ == 128) {
            uint4 t0 = { f2tf32(rb[0].x), f2tf32(rb[0].y), f2tf32(rb[0].z), f2tf32(rb[0].w) };
            uint4 t1 = { f2tf32(rb[1].x), f2tf32(rb[1].y), f2tf32(rb[1].z), f2tf32(rb[1].w) };
            *reinterpret_cast<uint4*>(&Bs[buf][br][bc128]) = t0;
            *reinterpret_cast<uint4*>(&Bs[buf][br][bc128 + 4]) = t1;
        } else {
            uint4 t0 = { f2tf32(rb[0].x), f2tf32(rb[0].y), f2tf32(rb[0].z), f2tf32(rb[0].w) };
            *reinterpret_cast<uint4*>(&Bs[buf][br][bc64]) = t0;
        }
    };

    loadG(0);
    int buf = 0;
    for (int k0 = 0; k0 < K; k0 += TBK) {
        storeS(buf);
        __syncthreads();
        if (k0 + TBK < K) loadG(k0 + TBK);

#pragma unroll
        for (int s = 0; s < 2; s++) {
            const int kc = s * 8 + (lane & 3);
            uint32_t a[MI][4], b[NJ][2];
#pragma unroll
            for (int i = 0; i < MI; i++) {
                const int r0 = wm0 + i * 16 + (lane >> 2);
                a[i][0] = As[buf][r0][kc];
                a[i][1] = As[buf][r0 + 8][kc];
                a[i][2] = As[buf][r0][kc + 4];
                a[i][3] = As[buf][r0 + 8][kc + 4];
            }
#pragma unroll
            for (int j = 0; j < NJ; j++) {
                const int col = wn0 + j * 8 + (lane >> 2);
                b[j][0] = Bs[buf][s * 8 + (lane & 3)][col];
                b[j][1] = Bs[buf][s * 8 + 4 + (lane & 3)][col];
            }
#pragma unroll
            for (int i = 0; i < MI; i++)
#pragma unroll
                for (int j = 0; j < NJ; j++)
                    mma_tf32(acc[i][j], a[i], b[j]);
        }
        buf ^= 1;
    }

#pragma unroll
    for (int i = 0; i < MI; i++) {
#pragma unroll
        for (int j = 0; j < NJ; j++) {
            const int r = m0 + wm0 + i * 16 + (lane >> 2);
            const int c = n0 + wn0 + j * 8 + (lane & 3) * 2;
            float2 v0 = { alpha * acc[i][j][0], alpha * acc[i][j][1] };
            float2 v1 = { alpha * acc[i][j][2], alpha * acc[i][j][3] };
            *reinterpret_cast<float2*>(&C[(size_t)r * ldc + c]) = v0;
            *reinterpret_cast<float2*>(&C[(size_t)(r + 8) * ldc + c]) = v1;
        }
    }
}

// ---------------- fused flash attention ----------------
// fp16 QK^T (m16n8k16) + tf32 PV (m16n8k8), online softmax.
// CTA: (bh, 64 q rows), 4 warps x 16 rows. K/V cp.async double-buffered.
constexpr int FBR = 64;
constexpr int FBC = 64;
constexpr int QSTR2 = 100;              // uint32 (half2) stride for Q/K rows (96 data + 4 pad)
constexpr int VSTR = 204;               // word stride for V rows (192 data + 12 pad)
constexpr int PSTR = 72;                // word stride for P tile
constexpr int FW_Q = FBR * QSTR2;                    // 6400
constexpr int FW_K = FBC * QSTR2;                    // 6400 per buffer
constexpr int FW_V = FBC * VSTR;                     // 13056 per buffer
constexpr int FW_P = FBR * PSTR;                     // 4608
constexpr int FSMEM = (FW_Q + 2 * FW_K + 2 * FW_V + FW_P) * 4;  // 199,680 B

__global__ void __launch_bounds__(128)
flash_attn_kernel(float scale)
{
    extern __shared__ uint32_t sh[];
    uint32_t* Qs = sh;                       // half2 words
    uint32_t* Ks = Qs + FW_Q;                // 2 buffers, half2 words
    uint32_t* Vs = Ks + 2 * FW_K;            // 2 buffers, tf32 words
    uint32_t* Ps = Vs + 2 * FW_V;            // tf32 words

    const int mb = (int)gridDim.x - 1 - (int)blockIdx.x;   // heavy blocks first
    const int bh = blockIdx.y;
    const int b = bh / cH, h = bh % cH;
    const int m0 = mb * FBR;
    const int tid = threadIdx.x;
    const int lane = tid & 31, warp = tid >> 5;
    const int wr = warp * 16;
    const int qr = lane >> 2, qc = lane & 3;

    const __half* Qg = g_Qh + (size_t)bh * cL * cDQK;
    const __half* Kg = g_Kh + (size_t)bh * cL * cDQK;
    const float*  Vg = g_V  + (size_t)bh * cL * cDQK;

    const uint32_t ks_addr = (uint32_t)__cvta_generic_to_shared(Ks);
    const uint32_t vs_addr = (uint32_t)__cvta_generic_to_shared(Vs);

    auto prefetchKV = [&](int kb, int pbuf) {
        const char* Kr = (const char*)(Kg + (size_t)(kb * FBC) * cDQK);
        const char* Vr = (const char*)(Vg + (size_t)(kb * FBC) * cDQK);
        const uint32_t kb_s = ks_addr + pbuf * (FW_K * 4);
        const uint32_t vb_s = vs_addr + pbuf * (FW_V * 4);
#pragma unroll
        for (int n = 0; n < 12; n++) {            // K: 64 rows x 384B = 1536 chunks
            int idx = tid + n * 128;
            int r = idx / 24, c = idx % 24;
            cpa16(kb_s + r * (QSTR2 * 4) + c * 16, Kr + r * 384 + c * 16);
        }
#pragma unroll
        for (int n = 0; n < 24; n++) {            // V: 64 rows x 768B = 3072 chunks
            int idx = tid + n * 128;
            int r = idx / 48, c = idx % 48;
            cpa16(vb_s + r * (VSTR * 4) + c * 16, Vr + r * 768 + c * 16);
        }
        cp_commit();
    };

    prefetchKV(0, 0);

    // ---- load Q tile (64 x 192 fp16), overlapped with first prefetch ----
    for (int i = tid; i < FBR * 24; i += 128) {   // 24 x 16B per row
        int r = i / 24, c = i % 24;
        float4 v = *reinterpret_cast<const float4*>(
            (const char*)Qg + ((size_t)(m0 + r) * cDQK) * 2 + c * 16);
        *reinterpret_cast<float4*>((char*)Qs + r * (QSTR2 * 4) + c * 16) = v;
    }

    float oacc[24][4];
#pragma unroll
    for (int j = 0; j < 24; j++)
#pragma unroll
        for (int e = 0; e < 4; e++) oacc[j][e] = 0.0f;
    float mrow[2] = { -1e30f, -1e30f };
    float lrow[2] = { 0.0f, 0.0f };

    int buf = 0;
    for (int kb = 0; kb <= mb; kb++) {
        if (kb < mb) {
            prefetchKV(kb + 1, buf ^ 1);
            cp_wait<1>();
        } else {
            cp_wait<0>();
        }
        __syncthreads();

        const uint32_t* Kb = Ks + buf * FW_K;
        const uint32_t* Vb = Vs + buf * FW_V;

        // ---- S = Q @ K^T (fp16 m16n8k16; 16x64 per warp) ----
        float sacc[8][4];
#pragma unroll
        for (int j = 0; j < 8; j++)
#pragma unroll
            for (int e = 0; e < 4; e++) sacc[j][e] = 0.0f;

#pragma unroll
        for (int ks = 0; ks < 12; ks++) {
            const int kc = ks * 8 + qc;
            uint32_t a[4] = {
                Qs[(wr + qr) * QSTR2 + kc],
                Qs[(wr + 8 + qr) * QSTR2 + kc],
                Qs[(wr + qr) * QSTR2 + kc + 4],
                Qs[(wr + 8 + qr) * QSTR2 + kc + 4]
            };
#pragma unroll
            for (int j = 0; j < 8; j++) {
                uint32_t bf[2] = {
                    Kb[(j * 8 + qr) * QSTR2 + kc],
                    Kb[(j * 8 + qr) * QSTR2 + kc + 4]
                };
                mma_f16(sacc[j], a, bf);
            }
        }

        // ---- scale + causal mask + tile row-max ----
        const bool diag = (kb == mb);
        const int rowg0 = m0 + wr + qr;
        float tmax[2] = { -1e30f, -1e30f };
#pragma unroll
        for (int j = 0; j < 8; j++) {
#pragma unroll
            for (int e = 0; e < 4; e++) {
                float s = sacc[j][e] * scale;
                if (diag) {
                    int col = kb * FBC + j * 8 + 2 * qc + (e & 1);
                    int row = rowg0 + 8 * (e >> 1);
                    if (col > row) s = -1e30f;
                }
                sacc[j][e] = s;
                tmax[e >> 1] = fmaxf(tmax[e >> 1], s);
            }
        }
#pragma unroll
        for (int half = 0; half < 2; half++) {
            tmax[half] = fmaxf(tmax[half], __shfl_xor_sync(0xffffffffu, tmax[half], 1));
            tmax[half] = fmaxf(tmax[half], __shfl_xor_sync(0xffffffffu, tmax[half], 2));
        }

        float mnew[2], alf[2], psum[2] = { 0.0f, 0.0f };
#pragma unroll
        for (int half = 0; half < 2; half++) {
            mnew[half] = fmaxf(mrow[half], tmax[half]);
            alf[half] = __expf(mrow[half] - mnew[half]);
            mrow[half] = mnew[half];
        }

        // ---- P = exp(S - m) -> tf32 into Ps ----
#pragma unroll
        for (int j = 0; j < 8; j++) {
            float p0 = __expf(sacc[j][0] - mnew[0]);
            float p1 = __expf(sacc[j][1] - mnew[0]);
            float p2 = __expf(sacc[j][2] - mnew[1]);
            float p3 = __expf(sacc[j][3] - mnew[1]);
            psum[0] += p0 + p1;
            psum[1] += p2 + p3;
            uint2 w0 = { f2tf32(p0), f2tf32(p1) };
            uint2 w1 = { f2tf32(p2), f2tf32(p3) };
            *reinterpret_cast<uint2*>(&Ps[(wr + qr) * PSTR + j * 8 + 2 * qc]) = w0;
            *reinterpret_cast<uint2*>(&Ps[(wr + 8 + qr) * PSTR + j * 8 + 2 * qc]) = w1;
        }
#pragma unroll
        for (int half = 0; half < 2; half++) {
            psum[half] += __shfl_xor_sync(0xffffffffu, psum[half], 1);
            psum[half] += __shfl_xor_sync(0xffffffffu, psum[half], 2);
            lrow[half] = lrow[half] * alf[half] + psum[half];
        }

        // ---- rescale O ----
#pragma unroll
        for (int j = 0; j < 24; j++) {
            oacc[j][0] *= alf[0];
            oacc[j][1] *= alf[0];
            oacc[j][2] *= alf[1];
            oacc[j][3] *= alf[1];
        }

        __syncwarp();

        // ---- O += P @ V (tf32; 16x192 per warp, k=64) ----
#pragma unroll
        for (int ks = 0; ks < 8; ks++) {
            uint32_t a[4] = {
                Ps[(wr + qr) * PSTR + ks * 8 + qc],
                Ps[(wr + 8 + qr) * PSTR + ks * 8 + qc],
                Ps[(wr + qr) * PSTR + ks * 8 + 4 + qc],
                Ps[(wr + 8 + qr) * PSTR + ks * 8 + 4 + qc]
            };
#pragma unroll
            for (int j = 0; j < 24; j++) {
                uint32_t bf[2] = {
                    Vb[(ks * 8 + qc) * VSTR + j * 8 + qr],
                    Vb[(ks * 8 + 4 + qc) * VSTR + j * 8 + qr]
                };
                mma_tf32(oacc[j], a, bf);
            }
        }
        __syncthreads();   // all reads of buf done before it is overwritten
        buf ^= 1;
    }

    // ---- epilogue ----
    const float inv0 = 1.0f / lrow[0];
    const float inv1 = 1.0f / lrow[1];
    const size_t base0 = ((size_t)b * cL + (m0 + wr + qr)) * cNQ + (size_t)h * cDQK;
    const size_t base1 = base0 + 8 * cNQ;
#pragma unroll
    for (int j = 0; j < 24; j++) {
        const int c = j * 8 + 2 * qc;
        float2 v0 = { oacc[j][0] * inv0, oacc[j][1] * inv0 };
        float2 v1 = { oacc[j][2] * inv1, oacc[j][3] * inv1 };
        *reinterpret_cast<float2*>(&g_AO[base0 + c]) = v0;
        *reinterpret_cast<float2*>(&g_AO[base1 + c]) = v1;
    }
}

// ---------------- RoPE ----------------
__global__ void rope_q_kernel(const float* __restrict__ cosT, const float* __restrict__ sinT)
{
    int idx = blockIdx.x * blockDim.x + threadIdx.x;
    if (idx >= cM * cH * (cRD / 2)) return;
    int i = idx % (cRD / 2);
    int h = (idx / (cRD / 2)) % cH;
    int row = idx / ((cRD / 2) * cH);
    int l = row % cL;
    float c = cosT[l * (cRD / 2) + i];
    float s = sinT[l * (cRD / 2) + i];
    float* p = &g_qall[(size_t)row * cNQ + h * cDQK + cDH + 2 * i];
    float x1 = p[0], x2 = p[1];
    p[0] = x1 * c - x2 * s;
    p[1] = x1 * s + x2 * c;
}

__global__ void rope_k_kernel(const float* __restrict__ cosT, const float* __restrict__ sinT)
{
    int idx = blockIdx.x * blockDim.x + threadIdx.x;
    if (idx >= cM * (cRD / 2)) return;
    int i = idx % (cRD / 2);
    int row = idx / (cRD / 2);
    int l = row % cL;
    float c = cosT[l * (cRD / 2) + i];
    float s = sinT[l * (cRD / 2) + i];
    float* p = &g_kv[(size_t)row * cNKV + cRK + 2 * i];
    float x1 = p[0], x2 = p[1];
    p[0] = x1 * c - x2 * s;
    p[1] = x1 * s + x2 * c;
}

// ---------------- gather Q/K/V (pre-convert: Q,K -> fp16, V -> tf32) ----------------
__global__ void build_qkv_kernel()
{
    size_t idx = (size_t)blockIdx.x * blockDim.x + threadIdx.x;
    const size_t total = (size_t)cBH * cL * cDQK;
    if (idx >= total) return;
    int d = (int)(idx % cDQK);
    int l = (int)((idx / cDQK) % cL);
    int bh = (int)(idx / ((size_t)cDQK * cL));
    int b = bh / cH, h = bh % cH;
    size_t row = (size_t)b * cL + l;

    float q = g_qall[row * cNQ + h * cDQK + d];
    float k, v;
    const size_t upo = row * cNUP + (size_t)h * (2 * cDH + cRD);
    if (d < cDH) {
        k = g_up[upo + d];
        v = g_up[upo + cDH + d];
    } else {
        k = g_kv[row * cNKV + cRK + (d - cDH)];
        v = g_up[upo + 2 * cDH + (d - cDH)];
    }
    g_Qh[idx] = __float2half_rn(q);
    g_Kh[idx] = __float2half_rn(k);
    g_V[idx]  = __uint_as_float(f2tf32(v));
}

// ---------------- launch ----------------
extern "C" void kernel_launch(void* const* d_in, const int* in_sizes, int n_in,
                              void* d_out, int out_size)
{
    const float* x    = (const float*)d_in[0];
    const float* cosT = (const float*)d_in[1];
    const float* sinT = (const float*)d_in[2];
    const float* wq   = (const float*)d_in[3];
    const float* wkvd = (const float*)d_in[4];
    const float* wup  = (const float*)d_in[5];
    const float* wout = (const float*)d_in[6];
    float* out = (float*)d_out;

    float *p_qall, *p_kv, *p_up, *p_ao;
    cudaGetSymbolAddress((void**)&p_qall, g_qall);
    cudaGetSymbolAddress((void**)&p_kv,   g_kv);
    cudaGetSymbolAddress((void**)&p_up,   g_up);
    cudaGetSymbolAddress((void**)&p_ao,   g_AO);

    cudaFuncSetAttribute(flash_attn_kernel,
                         cudaFuncAttributeMaxDynamicSharedMemorySize, FSMEM);

    const float scale = 1.0f / sqrtf((float)cDQK);

    // 1) q_all = x @ wq   (4096 x 3072 x 2048)
    tgemm<128, 64, 32><<<dim3(cNQ / 128, cM / TBM, 1), 256>>>(
        x, wq, p_qall, cE, cE, cNQ, cNQ, 1.0f);
    // 2) kv_lat = x @ wkv_down   (4096 x 576 x 2048)
    tgemm<64, 32, 32><<<dim3(cNKV / 64, cM / TBM, 1), 256>>>(
        x, wkvd, p_kv, cE, cE, cNKV, cNKV, 1.0f);
    // 3) RoPE
    rope_q_kernel<<<(cM * cH * (cRD / 2) + 255) / 256, 256>>>(cosT, sinT);
    rope_k_kernel<<<(cM * (cRD / 2) + 255) / 256, 256>>>(cosT, sinT);
    // 4) up = c_kv @ w_up   (4096 x 5120 x 512)
    tgemm<128, 64, 32><<<dim3(cNUP / 128, cM / TBM, 1), 256>>>(
        p_kv, wup, p_up, cRK, cNKV, cNUP, cNUP, 1.0f);
    // 5) gather + precision pre-convert
    {
        size_t total = (size_t)cBH * cL * cDQK;
        build_qkv_kernel<<<(unsigned)((total + 255) / 256), 256>>>();
    }
    // 6-8) fused flash attention -> g_AO
    flash_attn_kernel<<<dim3(cL / FBR, cBH), 128, FSMEM>>>(scale);
    // 9) out = AO @ w_out   (4096 x 2048 x 3072)
    tgemm<128, 64, 32><<<dim3(cE / 128, cM / TBM, 1), 256>>>(
        p_ao, wout, out, cNQ, cNQ, cE, cE, 1.0f);
}

// round 6
// speedup vs baseline: 2.3121x; 1.9264x over previous
#include <cuda_runtime.h>
#include <cuda_fp16.h>
#include <math.h>
#include <stdint.h>

// ---------------- problem constants ----------------
constexpr int cH   = 16;
constexpr int cDH  = 128;
constexpr int cRK  = 512;
constexpr int cRD  = 64;
constexpr int cB   = 2;
constexpr int cL   = 2048;
constexpr int cE   = 2048;
constexpr int cDQK = cDH + cRD;          // 192
constexpr int cNQ  = cH * cDQK;          // 3072
constexpr int cNKV = cRK + cRD;          // 576
constexpr int cNUP = cH * (2*cDH + cRD); // 5120
constexpr int cM   = cB * cL;            // 4096
constexpr int cBH  = cB * cH;            // 32

// ---------------- scratch (half everywhere) ----------------
__device__ __half g_xh   [(size_t)cM * cE];
__device__ __half g_wqT  [(size_t)cNQ * cE];
__device__ __half g_wkvT [(size_t)cNKV * cE];
__device__ __half g_wupT [(size_t)cNUP * cRK];
__device__ __half g_woT  [(size_t)cE * cNQ];
__device__ __half g_qallh[(size_t)cM * cNQ];
__device__ __half g_kvh  [(size_t)cM * cNKV];
__device__ __half g_uph  [(size_t)cM * cNUP];
__device__ __half g_Qh   [(size_t)cBH * cL * cDQK];
__device__ __half g_Kh   [(size_t)cBH * cL * cDQK];
__device__ __half g_Vh   [(size_t)cBH * cL * cDQK];
__device__ __half g_AOh  [(size_t)cM * cNQ];

// ---------------- low-level helpers ----------------
__device__ __forceinline__ void mma_f16(float* d, const uint32_t* a, const uint32_t* b) {
    asm volatile(
        "mma.sync.aligned.m16n8k16.row.col.f32.f16.f16.f32 "
        "{%0,%1,%2,%3},{%4,%5,%6,%7},{%8,%9},{%0,%1,%2,%3};"
        : "+f"(d[0]), "+f"(d[1]), "+f"(d[2]), "+f"(d[3])
        : "r"(a[0]), "r"(a[1]), "r"(a[2]), "r"(a[3]), "r"(b[0]), "r"(b[1]));
}
__device__ __forceinline__ void cpa16(uint32_t s, const void* g) {
    asm volatile("cp.async.cg.shared.global [%0], [%1], 16;\n" :: "r"(s), "l"(g));
}
__device__ __forceinline__ void cp_commit() {
    asm volatile("cp.async.commit_group;\n" ::: "memory");
}
template<int N>
__device__ __forceinline__ void cp_wait() {
    asm volatile("cp.async.wait_group %0;\n" :: "n"(N) : "memory");
}
__device__ __forceinline__ void ldm_x4_t(uint32_t& d0, uint32_t& d1, uint32_t& d2, uint32_t& d3,
                                         uint32_t addr) {
    asm volatile("ldmatrix.sync.aligned.m8n8.x4.trans.shared.b16 {%0,%1,%2,%3},[%4];"
                 : "=r"(d0), "=r"(d1), "=r"(d2), "=r"(d3) : "r"(addr));
}
__device__ __forceinline__ uint32_t pack_h2(float a, float b) {
    __half2 h = __floats2half2_rn(a, b);
    return *reinterpret_cast<uint32_t*>(&h);
}

// ---------------- fp16 tensor-core GEMM: C = A[M,K] @ B^T  (B given as [N][K]) ----------------
// TBM=128, TBN in {128,64}, TBK=16, 256 threads, cp.async double buffer.
constexpr int GSTR = 12;   // words per 16-half k-row (8 data + 4 pad) -> conflict-free frags

template<int TBN_, int WM, int WN, bool OUTF>
__global__ void __launch_bounds__(256, 2)
tgemm_h(const __half* __restrict__ A, const __half* __restrict__ B,
        void* __restrict__ Cout, int K, int lda, int ldb, int ldc)
{
    constexpr int MI = WM / 16;
    constexpr int NJ = WN / 8;
    constexpr int WARPS_M = 128 / WM;

    const int m0 = blockIdx.y * 128;
    const int n0 = blockIdx.x * TBN_;

    __shared__ uint32_t As[2][128 * GSTR];
    __shared__ uint32_t Bs[2][TBN_ * GSTR];

    const int tid  = threadIdx.x;
    const int lane = tid & 31;
    const int warp = tid >> 5;
    const int wm0 = (warp % WARPS_M) * WM;
    const int wn0 = (warp / WARPS_M) * WN;
    const int qr = lane >> 2, qc = lane & 3;

    const uint32_t as_base = (uint32_t)__cvta_generic_to_shared(&As[0][0]);
    const uint32_t bs_base = (uint32_t)__cvta_generic_to_shared(&Bs[0][0]);
    const int ra = tid >> 1, ca = tid & 1;       // A: 128 rows x 2 chunks

    auto issueTile = [&](int k0, int buf) {
        cpa16(as_base + buf * (128 * GSTR * 4) + ra * (GSTR * 4) + ca * 16,
              (const char*)A + ((size_t)(m0 + ra) * lda + k0) * 2 + ca * 16);
        if (TBN_ == 128) {
            cpa16(bs_base + buf * (TBN_ * GSTR * 4) + ra * (GSTR * 4) + ca * 16,
                  (const char*)B + ((size_t)(n0 + ra) * ldb + k0) * 2 + ca * 16);
        } else {
            if (tid < 128)
                cpa16(bs_base + buf * (TBN_ * GSTR * 4) + ra * (GSTR * 4) + ca * 16,
                      (const char*)B + ((size_t)(n0 + ra) * ldb + k0) * 2 + ca * 16);
        }
        cp_commit();
    };

    float acc[MI][NJ][4];
#pragma unroll
    for (int i = 0; i < MI; i++)
#pragma unroll
        for (int j = 0; j < NJ; j++)
#pragma unroll
            for (int r = 0; r < 4; r++) acc[i][j][r] = 0.0f;

    const int NT = K / 16;
    issueTile(0, 0);
    int buf = 0;
    for (int kt = 0; kt < NT; kt++) {
        if (kt + 1 < NT) {
            issueTile((kt + 1) * 16, buf ^ 1);
            cp_wait<1>();
        } else {
            cp_wait<0>();
        }
        __syncthreads();

        const uint32_t* Ab = As[buf];
        const uint32_t* Bb = Bs[buf];
        uint32_t a[MI][4], b[NJ][2];
#pragma unroll
        for (int i = 0; i < MI; i++) {
            const int r0 = wm0 + i * 16 + qr;
            a[i][0] = Ab[r0 * GSTR + qc];
            a[i][1] = Ab[(r0 + 8) * GSTR + qc];
            a[i][2] = Ab[r0 * GSTR + qc + 4];
            a[i][3] = Ab[(r0 + 8) * GSTR + qc + 4];
        }
#pragma unroll
        for (int j = 0; j < NJ; j++) {
            const int c0 = wn0 + j * 8 + qr;
            b[j][0] = Bb[c0 * GSTR + qc];
            b[j][1] = Bb[c0 * GSTR + qc + 4];
        }
#pragma unroll
        for (int i = 0; i < MI; i++)
#pragma unroll
            for (int j = 0; j < NJ; j++)
                mma_f16(acc[i][j], a[i], b[j]);
        __syncthreads();
        buf ^= 1;
    }

#pragma unroll
    for (int i = 0; i < MI; i++) {
#pragma unroll
        for (int j = 0; j < NJ; j++) {
            const int r = m0 + wm0 + i * 16 + qr;
            const int c = n0 + wn0 + j * 8 + 2 * qc;
            if (OUTF) {
                float* C = (float*)Cout;
                float2 v0 = { acc[i][j][0], acc[i][j][1] };
                float2 v1 = { acc[i][j][2], acc[i][j][3] };
                *reinterpret_cast<float2*>(&C[(size_t)r * ldc + c]) = v0;
                *reinterpret_cast<float2*>(&C[(size_t)(r + 8) * ldc + c]) = v1;
            } else {
                __half* C = (__half*)Cout;
                *reinterpret_cast<__half2*>(&C[(size_t)r * ldc + c]) =
                    __floats2half2_rn(acc[i][j][0], acc[i][j][1]);
                *reinterpret_cast<__half2*>(&C[(size_t)(r + 8) * ldc + c]) =
                    __floats2half2_rn(acc[i][j][2], acc[i][j][3]);
            }
        }
    }
}

// ---------------- fused flash attention v2 (all fp16 MMA) ----------------
// CTA: (bh, 128 q rows), 8 warps x 16 rows, FBC=64 keys/iter, cp.async double buffer.
constexpr int FBR = 128;
constexpr int FBC = 64;
constexpr int FQW = 100;                         // words per 192-half row (96 + 4 pad)
constexpr int FW_Q = FBR * FQW;                  // 12800
constexpr int FW_KV = FBC * FQW;                 // 6400 per buffer
constexpr int FSMEM = (FW_Q + 4 * FW_KV) * 4;    // 153,600 B

__global__ void __launch_bounds__(256, 1)
flash_attn_kernel(float scale)
{
    extern __shared__ uint32_t sh[];
    uint32_t* Qs = sh;
    uint32_t* Ks = Qs + FW_Q;       // 2 buffers
    uint32_t* Vs = Ks + 2 * FW_KV;  // 2 buffers

    const int mb = (int)gridDim.x - 1 - (int)blockIdx.x;   // heavy blocks first
    const int bh = blockIdx.y;
    const int b = bh / cH, h = bh % cH;
    const int m0 = mb * FBR;
    const int tid = threadIdx.x;
    const int lane = tid & 31, warp = tid >> 5;
    const int wr = warp * 16;
    const int qr = lane >> 2, qc = lane & 3;

    const __half* Qg = g_Qh + (size_t)bh * cL * cDQK;
    const __half* Kg = g_Kh + (size_t)bh * cL * cDQK;
    const __half* Vg = g_Vh + (size_t)bh * cL * cDQK;

    const uint32_t ks_addr = (uint32_t)__cvta_generic_to_shared(Ks);
    const uint32_t vs_addr = (uint32_t)__cvta_generic_to_shared(Vs);

    auto prefetchKV = [&](int kb, int pbuf) {
        const char* Kr = (const char*)(Kg + (size_t)(kb * FBC) * cDQK);
        const char* Vr = (const char*)(Vg + (size_t)(kb * FBC) * cDQK);
        const uint32_t kb_s = ks_addr + pbuf * (FW_KV * 4);
        const uint32_t vb_s = vs_addr + pbuf * (FW_KV * 4);
#pragma unroll
        for (int n = 0; n < 6; n++) {             // 64 rows x 24 chunks = 1536
            int idx = tid + n * 256;
            int r = idx / 24, c = idx % 24;
            cpa16(kb_s + r * (FQW * 4) + c * 16, Kr + r * 384 + c * 16);
            cpa16(vb_s + r * (FQW * 4) + c * 16, Vr + r * 384 + c * 16);
        }
        cp_commit();
    };

    prefetchKV(0, 0);

    // Q tile: 128 rows x 24 chunks (16B)
    for (int n = 0; n < 12; n++) {
        int idx = tid + n * 256;
        int r = idx / 24, c = idx % 24;
        uint4 v = *reinterpret_cast<const uint4*>(
            (const char*)Qg + (size_t)(m0 + r) * 384 + c * 16);
        *reinterpret_cast<uint4*>((char*)Qs + r * (FQW * 4) + c * 16) = v;
    }

    float oacc[24][4];
#pragma unroll
    for (int j = 0; j < 24; j++)
#pragma unroll
        for (int e = 0; e < 4; e++) oacc[j][e] = 0.0f;
    float mrow[2] = { -1e30f, -1e30f };
    float lrow[2] = { 0.0f, 0.0f };

    const int kbmax = 2 * mb + 1;
    const int rowg0 = m0 + wr + qr;
    int buf = 0;
    for (int kb = 0; kb <= kbmax; kb++) {
        if (kb < kbmax) {
            prefetchKV(kb + 1, buf ^ 1);
            cp_wait<1>();
        } else {
            cp_wait<0>();
        }
        __syncthreads();

        const bool skip = (kb * FBC > m0 + wr + 15);   // warp tile fully masked
        if (!skip) {
            const uint32_t* Kb = Ks + buf * FW_KV;
            const uint32_t vbuf = vs_addr + buf * (FW_KV * 4);

            // ---- S = Q @ K^T (fp16 m16n8k16) ----
            float sacc[8][4];
#pragma unroll
            for (int j = 0; j < 8; j++)
#pragma unroll
                for (int e = 0; e < 4; e++) sacc[j][e] = 0.0f;

#pragma unroll
            for (int ks = 0; ks < 12; ks++) {
                const int kc = ks * 8 + qc;
                uint32_t a[4] = {
                    Qs[(wr + qr) * FQW + kc],
                    Qs[(wr + 8 + qr) * FQW + kc],
                    Qs[(wr + qr) * FQW + kc + 4],
                    Qs[(wr + 8 + qr) * FQW + kc + 4]
                };
#pragma unroll
                for (int j = 0; j < 8; j++) {
                    uint32_t bf[2] = {
                        Kb[(j * 8 + qr) * FQW + kc],
                        Kb[(j * 8 + qr) * FQW + kc + 4]
                    };
                    mma_f16(sacc[j], a, bf);
                }
            }

            // ---- scale + causal mask + row max ----
            const bool diag = (kb * FBC + FBC - 1 > m0 + wr);
            float tmax[2] = { -1e30f, -1e30f };
#pragma unroll
            for (int j = 0; j < 8; j++) {
#pragma unroll
                for (int e = 0; e < 4; e++) {
                    float s = sacc[j][e] * scale;
                    if (diag) {
                        int col = kb * FBC + j * 8 + 2 * qc + (e & 1);
                        int row = rowg0 + 8 * (e >> 1);
                        if (col > row) s = -1e30f;
                    }
                    sacc[j][e] = s;
                    tmax[e >> 1] = fmaxf(tmax[e >> 1], s);
                }
            }
#pragma unroll
            for (int half = 0; half < 2; half++) {
                tmax[half] = fmaxf(tmax[half], __shfl_xor_sync(0xffffffffu, tmax[half], 1));
                tmax[half] = fmaxf(tmax[half], __shfl_xor_sync(0xffffffffu, tmax[half], 2));
            }

            float mnew[2], alf[2], psum[2] = { 0.0f, 0.0f };
#pragma unroll
            for (int half = 0; half < 2; half++) {
                mnew[half] = fmaxf(mrow[half], tmax[half]);
                alf[half] = __expf(mrow[half] - mnew[half]);
                mrow[half] = mnew[half];
            }

            // ---- P = exp(S - m) in place ----
#pragma unroll
            for (int j = 0; j < 8; j++) {
                sacc[j][0] = __expf(sacc[j][0] - mnew[0]);
                sacc[j][1] = __expf(sacc[j][1] - mnew[0]);
                sacc[j][2] = __expf(sacc[j][2] - mnew[1]);
                sacc[j][3] = __expf(sacc[j][3] - mnew[1]);
                psum[0] += sacc[j][0] + sacc[j][1];
                psum[1] += sacc[j][2] + sacc[j][3];
            }
#pragma unroll
            for (int half = 0; half < 2; half++) {
                psum[half] += __shfl_xor_sync(0xffffffffu, psum[half], 1);
                psum[half] += __shfl_xor_sync(0xffffffffu, psum[half], 2);
                lrow[half] = lrow[half] * alf[half] + psum[half];
            }

            // ---- rescale O ----
#pragma unroll
            for (int j = 0; j < 24; j++) {
                oacc[j][0] *= alf[0];
                oacc[j][1] *= alf[0];
                oacc[j][2] *= alf[1];
                oacc[j][3] *= alf[1];
            }

            // ---- O += P @ V : P repacked in registers, V via ldmatrix.trans ----
            const int g = lane >> 3, lj = lane & 7;
            const uint32_t vrow_base = vbuf + ((g & 1) * 8 + lj) * (FQW * 4) + (g >> 1) * 16;
#pragma unroll
            for (int ks2 = 0; ks2 < 4; ks2++) {
                uint32_t pa[4] = {
                    pack_h2(sacc[2 * ks2][0],     sacc[2 * ks2][1]),
                    pack_h2(sacc[2 * ks2][2],     sacc[2 * ks2][3]),
                    pack_h2(sacc[2 * ks2 + 1][0], sacc[2 * ks2 + 1][1]),
                    pack_h2(sacc[2 * ks2 + 1][2], sacc[2 * ks2 + 1][3])
                };
                const uint32_t krow = vrow_base + ks2 * 16 * (FQW * 4);
#pragma unroll
                for (int jp = 0; jp < 12; jp++) {
                    uint32_t d0, d1, d2, d3;
                    ldm_x4_t(d0, d1, d2, d3, krow + jp * 32);
                    uint32_t b0[2] = { d0, d1 };
                    uint32_t b1[2] = { d2, d3 };
                    mma_f16(oacc[2 * jp], pa, b0);
                    mma_f16(oacc[2 * jp + 1], pa, b1);
                }
            }
        }
        __syncthreads();
        buf ^= 1;
    }

    // ---- epilogue: O /= l -> half ----
    const float inv0 = 1.0f / lrow[0];
    const float inv1 = 1.0f / lrow[1];
    const size_t base0 = ((size_t)b * cL + (m0 + wr + qr)) * cNQ + (size_t)h * cDQK;
    const size_t base1 = base0 + 8 * cNQ;
#pragma unroll
    for (int j = 0; j < 24; j++) {
        const int c = j * 8 + 2 * qc;
        *reinterpret_cast<__half2*>(&g_AOh[base0 + c]) =
            __floats2half2_rn(oacc[j][0] * inv0, oacc[j][1] * inv0);
        *reinterpret_cast<__half2*>(&g_AOh[base1 + c]) =
            __floats2half2_rn(oacc[j][2] * inv1, oacc[j][3] * inv1);
    }
}

// ---------------- prep kernels ----------------
__global__ void f2h_kernel(const float* __restrict__ s, __half* __restrict__ d, size_t n)
{
    size_t i = ((size_t)blockIdx.x * blockDim.x + threadIdx.x) * 4;
    if (i >= n) return;
    float4 v = *reinterpret_cast<const float4*>(&s[i]);
    __half2 h0 = __floats2half2_rn(v.x, v.y);
    __half2 h1 = __floats2half2_rn(v.z, v.w);
    *reinterpret_cast<__half2*>(&d[i]) = h0;
    *reinterpret_cast<__half2*>(&d[i + 2]) = h1;
}

// dst[C][R] (half) = transpose of src[R][C] (float)
__global__ void transpose_h_kernel(const float* __restrict__ src, __half* __restrict__ dst,
                                   int R, int C)
{
    __shared__ float t[32][33];
    const int c0 = blockIdx.x * 32, r0 = blockIdx.y * 32;
    const int x = threadIdx.x, y = threadIdx.y;
#pragma unroll
    for (int dy = 0; dy < 32; dy += 8)
        t[y + dy][x] = src[(size_t)(r0 + y + dy) * C + c0 + x];
    __syncthreads();
#pragma unroll
    for (int dy = 0; dy < 32; dy += 8)
        dst[(size_t)(c0 + y + dy) * R + r0 + x] = __float2half_rn(t[x][y + dy]);
}

// ---------------- RoPE on half ----------------
__global__ void rope_q_kernel(const float* __restrict__ cosT, const float* __restrict__ sinT)
{
    int idx = blockIdx.x * blockDim.x + threadIdx.x;
    if (idx >= cM * cH * (cRD / 2)) return;
    int i = idx % (cRD / 2);
    int h = (idx / (cRD / 2)) % cH;
    int row = idx / ((cRD / 2) * cH);
    int l = row % cL;
    float c = cosT[l * (cRD / 2) + i];
    float s = sinT[l * (cRD / 2) + i];
    __half2* p = reinterpret_cast<__half2*>(&g_qallh[(size_t)row * cNQ + h * cDQK + cDH + 2 * i]);
    float2 v = __half22float2(*p);
    *p = __floats2half2_rn(v.x * c - v.y * s, v.x * s + v.y * c);
}

__global__ void rope_k_kernel(const float* __restrict__ cosT, const float* __restrict__ sinT)
{
    int idx = blockIdx.x * blockDim.x + threadIdx.x;
    if (idx >= cM * (cRD / 2)) return;
    int i = idx % (cRD / 2);
    int row = idx / (cRD / 2);
    int l = row % cL;
    float c = cosT[l * (cRD / 2) + i];
    float s = sinT[l * (cRD / 2) + i];
    __half2* p = reinterpret_cast<__half2*>(&g_kvh[(size_t)row * cNKV + cRK + 2 * i]);
    float2 v = __half22float2(*p);
    *p = __floats2half2_rn(v.x * c - v.y * s, v.x * s + v.y * c);
}

// ---------------- gather Q/K/V (half2 copies) ----------------
__global__ void build_qkv_kernel()
{
    size_t idx = (size_t)blockIdx.x * blockDim.x + threadIdx.x;
    const size_t total = (size_t)cBH * cL * (cDQK / 2);
    if (idx >= total) return;
    int d2 = (int)(idx % (cDQK / 2));
    int l = (int)((idx / (cDQK / 2)) % cL);
    int bh = (int)(idx / ((size_t)(cDQK / 2) * cL));
    int b = bh / cH, h = bh % cH;
    size_t row = (size_t)b * cL + l;
    int d = 2 * d2;

    const __half2* qs = reinterpret_cast<const __half2*>(&g_qallh[row * cNQ + h * cDQK + d]);
    __half2 q = *qs;
    __half2 k, v;
    const size_t upo = row * cNUP + (size_t)h * (2 * cDH + cRD);
    if (d < cDH) {
        k = *reinterpret_cast<const __half2*>(&g_uph[upo + d]);
        v = *reinterpret_cast<const __half2*>(&g_uph[upo + cDH + d]);
    } else {
        k = *reinterpret_cast<const __half2*>(&g_kvh[row * cNKV + cRK + (d - cDH)]);
        v = *reinterpret_cast<const __half2*>(&g_uph[upo + 2 * cDH + (d - cDH)]);
    }
    reinterpret_cast<__half2*>(g_Qh)[idx] = q;
    reinterpret_cast<__half2*>(g_Kh)[idx] = k;
    reinterpret_cast<__half2*>(g_Vh)[idx] = v;
}

// ---------------- launch ----------------
extern "C" void kernel_launch(void* const* d_in, const int* in_sizes, int n_in,
                              void* d_out, int out_size)
{
    const float* x    = (const float*)d_in[0];
    const float* cosT = (const float*)d_in[1];
    const float* sinT = (const float*)d_in[2];
    const float* wq   = (const float*)d_in[3];
    const float* wkvd = (const float*)d_in[4];
    const float* wup  = (const float*)d_in[5];
    const float* wout = (const float*)d_in[6];
    float* out = (float*)d_out;

    __half *p_xh, *p_wqT, *p_wkvT, *p_wupT, *p_woT;
    __half *p_qall, *p_kv, *p_up, *p_ao;
    cudaGetSymbolAddress((void**)&p_xh,   g_xh);
    cudaGetSymbolAddress((void**)&p_wqT,  g_wqT);
    cudaGetSymbolAddress((void**)&p_wkvT, g_wkvT);
    cudaGetSymbolAddress((void**)&p_wupT, g_wupT);
    cudaGetSymbolAddress((void**)&p_woT,  g_woT);
    cudaGetSymbolAddress((void**)&p_qall, g_qallh);
    cudaGetSymbolAddress((void**)&p_kv,   g_kvh);
    cudaGetSymbolAddress((void**)&p_up,   g_uph);
    cudaGetSymbolAddress((void**)&p_ao,   g_AOh);

    cudaFuncSetAttribute(flash_attn_kernel,
                         cudaFuncAttributeMaxDynamicSharedMemorySize, FSMEM);

    const float scale = 1.0f / sqrtf((float)cDQK);
    dim3 tblk(32, 8);

    // 0) converts + weight transposes
    f2h_kernel<<<(unsigned)(((size_t)cM * cE / 4 + 255) / 256), 256>>>(x, p_xh, (size_t)cM * cE);
    transpose_h_kernel<<<dim3(cNQ / 32, cE / 32), tblk>>>(wq, p_wqT, cE, cNQ);
    transpose_h_kernel<<<dim3(cNKV / 32, cE / 32), tblk>>>(wkvd, p_wkvT, cE, cNKV);
    transpose_h_kernel<<<dim3(cNUP / 32, cRK / 32), tblk>>>(wup, p_wupT, cRK, cNUP);
    transpose_h_kernel<<<dim3(cE / 32, cNQ / 32), tblk>>>(wout, p_woT, cNQ, cE);

    // 1) q_all = x @ wq
    tgemm_h<128, 64, 32, false><<<dim3(cNQ / 128, cM / 128), 256>>>(
        p_xh, p_wqT, p_qall, cE, cE, cE, cNQ);
    // 2) kv_lat = x @ wkv_down
    tgemm_h<64, 32, 32, false><<<dim3(cNKV / 64, cM / 128), 256>>>(
        p_xh, p_wkvT, p_kv, cE, cE, cE, cNKV);
    // 3) RoPE
    rope_q_kernel<<<(cM * cH * (cRD / 2) + 255) / 256, 256>>>(cosT, sinT);
    rope_k_kernel<<<(cM * (cRD / 2) + 255) / 256, 256>>>(cosT, sinT);
    // 4) up = c_kv @ w_up
    tgemm_h<128, 64, 32, false><<<dim3(cNUP / 128, cM / 128), 256>>>(
        p_kv, p_wupT, p_up, cRK, cNKV, cRK, cNUP);
    // 5) gather
    {
        size_t total = (size_t)cBH * cL * (cDQK / 2);
        build_qkv_kernel<<<(unsigned)((total + 255) / 256), 256>>>();
    }
    // 6-8) fused flash attention -> g_AOh
    flash_attn_kernel<<<dim3(cL / FBR, cBH), 256, FSMEM>>>(scale);
    // 9) out = AO @ w_out (fp32 output)
    tgemm_h<128, 64, 32, true><<<dim3(cE / 128, cM / 128), 256>>>(
        p_ao, p_woT, out, cNQ, cNQ, cNQ, cE);
}

// round 7
// speedup vs baseline: 2.5850x; 1.1180x over previous
#include <cuda_runtime.h>
#include <cuda_fp16.h>
#include <math.h>
#include <stdint.h>

// ---------------- problem constants ----------------
constexpr int cH   = 16;
constexpr int cDH  = 128;
constexpr int cRK  = 512;
constexpr int cRD  = 64;
constexpr int cB   = 2;
constexpr int cL   = 2048;
constexpr int cE   = 2048;
constexpr int cDQK = cDH + cRD;          // 192
constexpr int cNQ  = cH * cDQK;          // 3072
constexpr int cNKV = cRK + cRD;          // 576
constexpr int cNUP = cH * (2*cDH + cRD); // 5120
constexpr int cM   = cB * cL;            // 4096
constexpr int cBH  = cB * cH;            // 32

// ---------------- scratch (half everywhere) ----------------
__device__ __half g_xh   [(size_t)cM * cE];
__device__ __half g_wqT  [(size_t)cNQ * cE];
__device__ __half g_wkvT [(size_t)cNKV * cE];
__device__ __half g_wupT [(size_t)cNUP * cRK];
__device__ __half g_woT  [(size_t)cE * cNQ];
__device__ __half g_qallh[(size_t)cM * cNQ];
__device__ __half g_kvh  [(size_t)cM * cNKV];
__device__ __half g_uph  [(size_t)cM * cNUP];
__device__ __half g_Qh   [(size_t)cBH * cL * cDQK];
__device__ __half g_Kh   [(size_t)cBH * cL * cDQK];
__device__ __half g_Vh   [(size_t)cBH * cL * cDQK];
__device__ __half g_AOh  [(size_t)cM * cNQ];

// ---------------- low-level helpers ----------------
__device__ __forceinline__ void mma_f16(float* d, const uint32_t* a, const uint32_t* b) {
    asm volatile(
        "mma.sync.aligned.m16n8k16.row.col.f32.f16.f16.f32 "
        "{%0,%1,%2,%3},{%4,%5,%6,%7},{%8,%9},{%0,%1,%2,%3};"
        : "+f"(d[0]), "+f"(d[1]), "+f"(d[2]), "+f"(d[3])
        : "r"(a[0]), "r"(a[1]), "r"(a[2]), "r"(a[3]), "r"(b[0]), "r"(b[1]));
}
__device__ __forceinline__ void cpa16(uint32_t s, const void* g) {
    asm volatile("cp.async.cg.shared.global [%0], [%1], 16;\n" :: "r"(s), "l"(g));
}
__device__ __forceinline__ void cp_commit() {
    asm volatile("cp.async.commit_group;\n" ::: "memory");
}
template<int N>
__device__ __forceinline__ void cp_wait() {
    asm volatile("cp.async.wait_group %0;\n" :: "n"(N) : "memory");
}
__device__ __forceinline__ void ldm_x4(uint32_t& d0, uint32_t& d1, uint32_t& d2, uint32_t& d3,
                                       uint32_t addr) {
    asm volatile("ldmatrix.sync.aligned.m8n8.x4.shared.b16 {%0,%1,%2,%3},[%4];"
                 : "=r"(d0), "=r"(d1), "=r"(d2), "=r"(d3) : "r"(addr));
}
__device__ __forceinline__ void ldm_x4_t(uint32_t& d0, uint32_t& d1, uint32_t& d2, uint32_t& d3,
                                         uint32_t addr) {
    asm volatile("ldmatrix.sync.aligned.m8n8.x4.trans.shared.b16 {%0,%1,%2,%3},[%4];"
                 : "=r"(d0), "=r"(d1), "=r"(d2), "=r"(d3) : "r"(addr));
}
__device__ __forceinline__ uint32_t pack_h2(float a, float b) {
    __half2 h = __floats2half2_rn(a, b);
    return *reinterpret_cast<uint32_t*>(&h);
}

// ---------------- fp16 GEMM v2: C = A[M,K] @ B^T (B as [N][K]) ----------------
// TBK=32, 3-stage cp.async pipeline, ldmatrix fragment feeds, 256 threads.
constexpr int GAW = 20;   // words per 32-half row (16 data + 4 pad); 80 B, ldmatrix-conflict-free

template<int TBN_, int WM, int WN, bool OUTF>
__global__ void __launch_bounds__(256, 2)
tgemm_h2(const __half* __restrict__ A, const __half* __restrict__ B,
         void* __restrict__ Cout, int K, int lda, int ldb, int ldc)
{
    constexpr int MI = WM / 16;
    constexpr int NJ = WN / 8;
    constexpr int WARPS_M = 128 / WM;
    constexpr int STAGE_W = (128 + TBN_) * GAW;   // words per stage

    extern __shared__ uint32_t smem[];

    const int m0 = blockIdx.y * 128;
    const int n0 = blockIdx.x * TBN_;

    const int tid  = threadIdx.x;
    const int lane = tid & 31;
    const int warp = tid >> 5;
    const int wm0 = (warp % WARPS_M) * WM;
    const int wn0 = (warp / WARPS_M) * WN;
    const int lr = lane & 7, lm = lane >> 3;

    const uint32_t sbase = (uint32_t)__cvta_generic_to_shared(smem);

    // cp.async maps: A: 128 rows x 4 chunks (16B) = 512; B: TBN x 4 chunks
    const int r2 = tid >> 1;                     // 0..127
    const int c2 = (tid & 1) * 2;                // chunks {0,1} or {2,3}

    auto issueTile = [&](int k0, int st) {
        const uint32_t abase = sbase + st * (STAGE_W * 4);
        const uint32_t bbase = abase + 128 * (GAW * 4);
#pragma unroll
        for (int c = 0; c < 2; c++) {
            cpa16(abase + r2 * (GAW * 4) + (c2 + c) * 16,
                  (const char*)A + ((size_t)(m0 + r2) * lda + k0) * 2 + (c2 + c) * 16);
        }
        if (TBN_ == 128) {
#pragma unroll
            for (int c = 0; c < 2; c++) {
                cpa16(bbase + r2 * (GAW * 4) + (c2 + c) * 16,
                      (const char*)B + ((size_t)(n0 + r2) * ldb + k0) * 2 + (c2 + c) * 16);
            }
        } else {
            int rb = tid >> 2, cb = tid & 3;     // 64 rows x 4 chunks
            cpa16(bbase + rb * (GAW * 4) + cb * 16,
                  (const char*)B + ((size_t)(n0 + rb) * ldb + k0) * 2 + cb * 16);
        }
        cp_commit();
    };

    float acc[MI][NJ][4];
#pragma unroll
    for (int i = 0; i < MI; i++)
#pragma unroll
        for (int j = 0; j < NJ; j++)
#pragma unroll
            for (int r = 0; r < 4; r++) acc[i][j][r] = 0.0f;

    const int NT = K / 32;
    issueTile(0, 0);
    issueTile(32, 1);

    for (int kt = 0; kt < NT; kt++) {
        if (kt == NT - 1) cp_wait<0>(); else cp_wait<1>();
        __syncthreads();
        if (kt + 2 < NT) issueTile((kt + 2) * 32, (kt + 2) % 3);

        const int st = kt % 3;
        const uint32_t abase = sbase + st * (STAGE_W * 4);
        const uint32_t bbase = abase + 128 * (GAW * 4);

#pragma unroll
        for (int s = 0; s < 2; s++) {
            uint32_t a[MI][4], b[NJ][2];
#pragma unroll
            for (int i = 0; i < MI; i++) {
                // mats: m0: rows+0,k0 | m1: rows+8,k0 | m2: rows+0,k8 | m3: rows+8,k8
                uint32_t addr = abase +
                    (uint32_t)(wm0 + i * 16 + (lm & 1) * 8 + lr) * (GAW * 4) +
                    s * 32 + (lm >> 1) * 16;
                ldm_x4(a[i][0], a[i][1], a[i][2], a[i][3], addr);
            }
#pragma unroll
            for (int p = 0; p < NJ / 2; p++) {
                // mats: m0:(j0,k0) m1:(j0,k8) m2:(j1,k0) m3:(j1,k8)
                uint32_t addr = bbase +
                    (uint32_t)(wn0 + p * 16 + (lm >> 1) * 8 + lr) * (GAW * 4) +
                    s * 32 + (lm & 1) * 16;
                ldm_x4(b[2 * p][0], b[2 * p][1], b[2 * p + 1][0], b[2 * p + 1][1], addr);
            }
#pragma unroll
            for (int i = 0; i < MI; i++)
#pragma unroll
                for (int j = 0; j < NJ; j++)
                    mma_f16(acc[i][j], a[i], b[j]);
        }
    }

    const int qr = lane >> 2, qc = lane & 3;
#pragma unroll
    for (int i = 0; i < MI; i++) {
#pragma unroll
        for (int j = 0; j < NJ; j++) {
            const int r = m0 + wm0 + i * 16 + qr;
            const int c = n0 + wn0 + j * 8 + 2 * qc;
            if (OUTF) {
                float* C = (float*)Cout;
                float2 v0 = { acc[i][j][0], acc[i][j][1] };
                float2 v1 = { acc[i][j][2], acc[i][j][3] };
                *reinterpret_cast<float2*>(&C[(size_t)r * ldc + c]) = v0;
                *reinterpret_cast<float2*>(&C[(size_t)(r + 8) * ldc + c]) = v1;
            } else {
                __half* C = (__half*)Cout;
                *reinterpret_cast<__half2*>(&C[(size_t)r * ldc + c]) =
                    __floats2half2_rn(acc[i][j][0], acc[i][j][1]);
                *reinterpret_cast<__half2*>(&C[(size_t)(r + 8) * ldc + c]) =
                    __floats2half2_rn(acc[i][j][2], acc[i][j][3]);
            }
        }
    }
}

constexpr int SM_G128 = (128 + 128) * GAW * 4 * 3;   // 61,440 B
constexpr int SM_G64  = (128 + 64)  * GAW * 4 * 3;   // 46,080 B

// ---------------- fused flash attention (unchanged from R6 winner) ----------------
constexpr int FBR = 128;
constexpr int FBC = 64;
constexpr int FQW = 100;
constexpr int FW_Q = FBR * FQW;
constexpr int FW_KV = FBC * FQW;
constexpr int FSMEM = (FW_Q + 4 * FW_KV) * 4;

__global__ void __launch_bounds__(256, 1)
flash_attn_kernel(float scale)
{
    extern __shared__ uint32_t sh[];
    uint32_t* Qs = sh;
    uint32_t* Ks = Qs + FW_Q;
    uint32_t* Vs = Ks + 2 * FW_KV;

    const int mb = (int)gridDim.x - 1 - (int)blockIdx.x;
    const int bh = blockIdx.y;
    const int b = bh / cH, h = bh % cH;
    const int m0 = mb * FBR;
    const int tid = threadIdx.x;
    const int lane = tid & 31, warp = tid >> 5;
    const int wr = warp * 16;
    const int qr = lane >> 2, qc = lane & 3;

    const __half* Qg = g_Qh + (size_t)bh * cL * cDQK;
    const __half* Kg = g_Kh + (size_t)bh * cL * cDQK;
    const __half* Vg = g_Vh + (size_t)bh * cL * cDQK;

    const uint32_t ks_addr = (uint32_t)__cvta_generic_to_shared(Ks);
    const uint32_t vs_addr = (uint32_t)__cvta_generic_to_shared(Vs);

    auto prefetchKV = [&](int kb, int pbuf) {
        const char* Kr = (const char*)(Kg + (size_t)(kb * FBC) * cDQK);
        const char* Vr = (const char*)(Vg + (size_t)(kb * FBC) * cDQK);
        const uint32_t kb_s = ks_addr + pbuf * (FW_KV * 4);
        const uint32_t vb_s = vs_addr + pbuf * (FW_KV * 4);
#pragma unroll
        for (int n = 0; n < 6; n++) {
            int idx = tid + n * 256;
            int r = idx / 24, c = idx % 24;
            cpa16(kb_s + r * (FQW * 4) + c * 16, Kr + r * 384 + c * 16);
            cpa16(vb_s + r * (FQW * 4) + c * 16, Vr + r * 384 + c * 16);
        }
        cp_commit();
    };

    prefetchKV(0, 0);

    for (int n = 0; n < 12; n++) {
        int idx = tid + n * 256;
        int r = idx / 24, c = idx % 24;
        uint4 v = *reinterpret_cast<const uint4*>(
            (const char*)Qg + (size_t)(m0 + r) * 384 + c * 16);
        *reinterpret_cast<uint4*>((char*)Qs + r * (FQW * 4) + c * 16) = v;
    }

    float oacc[24][4];
#pragma unroll
    for (int j = 0; j < 24; j++)
#pragma unroll
        for (int e = 0; e < 4; e++) oacc[j][e] = 0.0f;
    float mrow[2] = { -1e30f, -1e30f };
    float lrow[2] = { 0.0f, 0.0f };

    const int kbmax = 2 * mb + 1;
    const int rowg0 = m0 + wr + qr;
    int buf = 0;
    for (int kb = 0; kb <= kbmax; kb++) {
        if (kb < kbmax) {
            prefetchKV(kb + 1, buf ^ 1);
            cp_wait<1>();
        } else {
            cp_wait<0>();
        }
        __syncthreads();

        const bool skip = (kb * FBC > m0 + wr + 15);
        if (!skip) {
            const uint32_t* Kb = Ks + buf * FW_KV;
            const uint32_t vbuf = vs_addr + buf * (FW_KV * 4);

            float sacc[8][4];
#pragma unroll
            for (int j = 0; j < 8; j++)
#pragma unroll
                for (int e = 0; e < 4; e++) sacc[j][e] = 0.0f;

#pragma unroll
            for (int ks = 0; ks < 12; ks++) {
                const int kc = ks * 8 + qc;
                uint32_t a[4] = {
                    Qs[(wr + qr) * FQW + kc],
                    Qs[(wr + 8 + qr) * FQW + kc],
                    Qs[(wr + qr) * FQW + kc + 4],
                    Qs[(wr + 8 + qr) * FQW + kc + 4]
                };
#pragma unroll
                for (int j = 0; j < 8; j++) {
                    uint32_t bf[2] = {
                        Kb[(j * 8 + qr) * FQW + kc],
                        Kb[(j * 8 + qr) * FQW + kc + 4]
                    };
                    mma_f16(sacc[j], a, bf);
                }
            }

            const bool diag = (kb * FBC + FBC - 1 > m0 + wr);
            float tmax[2] = { -1e30f, -1e30f };
#pragma unroll
            for (int j = 0; j < 8; j++) {
#pragma unroll
                for (int e = 0; e < 4; e++) {
                    float s = sacc[j][e] * scale;
                    if (diag) {
                        int col = kb * FBC + j * 8 + 2 * qc + (e & 1);
                        int row = rowg0 + 8 * (e >> 1);
                        if (col > row) s = -1e30f;
                    }
                    sacc[j][e] = s;
                    tmax[e >> 1] = fmaxf(tmax[e >> 1], s);
                }
            }
#pragma unroll
            for (int half = 0; half < 2; half++) {
                tmax[half] = fmaxf(tmax[half], __shfl_xor_sync(0xffffffffu, tmax[half], 1));
                tmax[half] = fmaxf(tmax[half], __shfl_xor_sync(0xffffffffu, tmax[half], 2));
            }

            float mnew[2], alf[2], psum[2] = { 0.0f, 0.0f };
#pragma unroll
            for (int half = 0; half < 2; half++) {
                mnew[half] = fmaxf(mrow[half], tmax[half]);
                alf[half] = __expf(mrow[half] - mnew[half]);
                mrow[half] = mnew[half];
            }

#pragma unroll
            for (int j = 0; j < 8; j++) {
                sacc[j][0] = __expf(sacc[j][0] - mnew[0]);
                sacc[j][1] = __expf(sacc[j][1] - mnew[0]);
                sacc[j][2] = __expf(sacc[j][2] - mnew[1]);
                sacc[j][3] = __expf(sacc[j][3] - mnew[1]);
                psum[0] += sacc[j][0] + sacc[j][1];
                psum[1] += sacc[j][2] + sacc[j][3];
            }
#pragma unroll
            for (int half = 0; half < 2; half++) {
                psum[half] += __shfl_xor_sync(0xffffffffu, psum[half], 1);
                psum[half] += __shfl_xor_sync(0xffffffffu, psum[half], 2);
                lrow[half] = lrow[half] * alf[half] + psum[half];
            }

#pragma unroll
            for (int j = 0; j < 24; j++) {
                oacc[j][0] *= alf[0];
                oacc[j][1] *= alf[0];
                oacc[j][2] *= alf[1];
                oacc[j][3] *= alf[1];
            }

            const int g = lane >> 3, lj = lane & 7;
            const uint32_t vrow_base = vbuf + ((g & 1) * 8 + lj) * (FQW * 4) + (g >> 1) * 16;
#pragma unroll
            for (int ks2 = 0; ks2 < 4; ks2++) {
                uint32_t pa[4] = {
                    pack_h2(sacc[2 * ks2][0],     sacc[2 * ks2][1]),
                    pack_h2(sacc[2 * ks2][2],     sacc[2 * ks2][3]),
                    pack_h2(sacc[2 * ks2 + 1][0], sacc[2 * ks2 + 1][1]),
                    pack_h2(sacc[2 * ks2 + 1][2], sacc[2 * ks2 + 1][3])
                };
                const uint32_t krow = vrow_base + ks2 * 16 * (FQW * 4);
#pragma unroll
                for (int jp = 0; jp < 12; jp++) {
                    uint32_t d0, d1, d2, d3;
                    ldm_x4_t(d0, d1, d2, d3, krow + jp * 32);
                    uint32_t b0[2] = { d0, d1 };
                    uint32_t b1[2] = { d2, d3 };
                    mma_f16(oacc[2 * jp], pa, b0);
                    mma_f16(oacc[2 * jp + 1], pa, b1);
                }
            }
        }
        __syncthreads();
        buf ^= 1;
    }

    const float inv0 = 1.0f / lrow[0];
    const float inv1 = 1.0f / lrow[1];
    const size_t base0 = ((size_t)b * cL + (m0 + wr + qr)) * cNQ + (size_t)h * cDQK;
    const size_t base1 = base0 + 8 * cNQ;
#pragma unroll
    for (int j = 0; j < 24; j++) {
        const int c = j * 8 + 2 * qc;
        *reinterpret_cast<__half2*>(&g_AOh[base0 + c]) =
            __floats2half2_rn(oacc[j][0] * inv0, oacc[j][1] * inv0);
        *reinterpret_cast<__half2*>(&g_AOh[base1 + c]) =
            __floats2half2_rn(oacc[j][2] * inv1, oacc[j][3] * inv1);
    }
}

// ---------------- prep kernels ----------------
__global__ void f2h_kernel(const float* __restrict__ s, __half* __restrict__ d, size_t n)
{
    size_t i = ((size_t)blockIdx.x * blockDim.x + threadIdx.x) * 4;
    if (i >= n) return;
    float4 v = *reinterpret_cast<const float4*>(&s[i]);
    *reinterpret_cast<__half2*>(&d[i]) = __floats2half2_rn(v.x, v.y);
    *reinterpret_cast<__half2*>(&d[i + 2]) = __floats2half2_rn(v.z, v.w);
}

__global__ void transpose_h_kernel(const float* __restrict__ src, __half* __restrict__ dst,
                                   int R, int C)
{
    __shared__ float t[32][33];
    const int c0 = blockIdx.x * 32, r0 = blockIdx.y * 32;
    const int x = threadIdx.x, y = threadIdx.y;
#pragma unroll
    for (int dy = 0; dy < 32; dy += 8)
        t[y + dy][x] = src[(size_t)(r0 + y + dy) * C + c0 + x];
    __syncthreads();
#pragma unroll
    for (int dy = 0; dy < 32; dy += 8)
        dst[(size_t)(c0 + y + dy) * R + r0 + x] = __float2half_rn(t[x][y + dy]);
}

// ---------------- RoPE on half ----------------
__global__ void rope_q_kernel(const float* __restrict__ cosT, const float* __restrict__ sinT)
{
    int idx = blockIdx.x * blockDim.x + threadIdx.x;
    if (idx >= cM * cH * (cRD / 2)) return;
    int i = idx % (cRD / 2);
    int h = (idx / (cRD / 2)) % cH;
    int row = idx / ((cRD / 2) * cH);
    int l = row % cL;
    float c = cosT[l * (cRD / 2) + i];
    float s = sinT[l * (cRD / 2) + i];
    __half2* p = reinterpret_cast<__half2*>(&g_qallh[(size_t)row * cNQ + h * cDQK + cDH + 2 * i]);
    float2 v = __half22float2(*p);
    *p = __floats2half2_rn(v.x * c - v.y * s, v.x * s + v.y * c);
}

__global__ void rope_k_kernel(const float* __restrict__ cosT, const float* __restrict__ sinT)
{
    int idx = blockIdx.x * blockDim.x + threadIdx.x;
    if (idx >= cM * (cRD / 2)) return;
    int i = idx % (cRD / 2);
    int row = idx / (cRD / 2);
    int l = row % cL;
    float c = cosT[l * (cRD / 2) + i];
    float s = sinT[l * (cRD / 2) + i];
    __half2* p = reinterpret_cast<__half2*>(&g_kvh[(size_t)row * cNKV + cRK + 2 * i]);
    float2 v = __half22float2(*p);
    *p = __floats2half2_rn(v.x * c - v.y * s, v.x * s + v.y * c);
}

// ---------------- gather Q/K/V ----------------
__global__ void build_qkv_kernel()
{
    size_t idx = (size_t)blockIdx.x * blockDim.x + threadIdx.x;
    const size_t total = (size_t)cBH * cL * (cDQK / 2);
    if (idx >= total) return;
    int d2 = (int)(idx % (cDQK / 2));
    int l = (int)((idx / (cDQK / 2)) % cL);
    int bh = (int)(idx / ((size_t)(cDQK / 2) * cL));
    int b = bh / cH, h = bh % cH;
    size_t row = (size_t)b * cL + l;
    int d = 2 * d2;

    __half2 q = *reinterpret_cast<const __half2*>(&g_qallh[row * cNQ + h * cDQK + d]);
    __half2 k, v;
    const size_t upo = row * cNUP + (size_t)h * (2 * cDH + cRD);
    if (d < cDH) {
        k = *reinterpret_cast<const __half2*>(&g_uph[upo + d]);
        v = *reinterpret_cast<const __half2*>(&g_uph[upo + cDH + d]);
    } else {
        k = *reinterpret_cast<const __half2*>(&g_kvh[row * cNKV + cRK + (d - cDH)]);
        v = *reinterpret_cast<const __half2*>(&g_uph[upo + 2 * cDH + (d - cDH)]);
    }
    reinterpret_cast<__half2*>(g_Qh)[idx] = q;
    reinterpret_cast<__half2*>(g_Kh)[idx] = k;
    reinterpret_cast<__half2*>(g_Vh)[idx] = v;
}

// ---------------- launch ----------------
extern "C" void kernel_launch(void* const* d_in, const int* in_sizes, int n_in,
                              void* d_out, int out_size)
{
    const float* x    = (const float*)d_in[0];
    const float* cosT = (const float*)d_in[1];
    const float* sinT = (const float*)d_in[2];
    const float* wq   = (const float*)d_in[3];
    const float* wkvd = (const float*)d_in[4];
    const float* wup  = (const float*)d_in[5];
    const float* wout = (const float*)d_in[6];
    float* out = (float*)d_out;

    __half *p_xh, *p_wqT, *p_wkvT, *p_wupT, *p_woT;
    __half *p_qall, *p_kv, *p_up, *p_ao;
    cudaGetSymbolAddress((void**)&p_xh,   g_xh);
    cudaGetSymbolAddress((void**)&p_wqT,  g_wqT);
    cudaGetSymbolAddress((void**)&p_wkvT, g_wkvT);
    cudaGetSymbolAddress((void**)&p_wupT, g_wupT);
    cudaGetSymbolAddress((void**)&p_woT,  g_woT);
    cudaGetSymbolAddress((void**)&p_qall, g_qallh);
    cudaGetSymbolAddress((void**)&p_kv,   g_kvh);
    cudaGetSymbolAddress((void**)&p_up,   g_uph);
    cudaGetSymbolAddress((void**)&p_ao,   g_AOh);

    cudaFuncSetAttribute(flash_attn_kernel,
                         cudaFuncAttributeMaxDynamicSharedMemorySize, FSMEM);
    cudaFuncSetAttribute((const void*)tgemm_h2<128, 64, 32, false>,
                         cudaFuncAttributeMaxDynamicSharedMemorySize, SM_G128);
    cudaFuncSetAttribute((const void*)tgemm_h2<64, 32, 32, false>,
                         cudaFuncAttributeMaxDynamicSharedMemorySize, SM_G64);
    cudaFuncSetAttribute((const void*)tgemm_h2<128, 64, 32, true>,
                         cudaFuncAttributeMaxDynamicSharedMemorySize, SM_G128);

    const float scale = 1.0f / sqrtf((float)cDQK);
    dim3 tblk(32, 8);

    // 0) converts + weight transposes
    f2h_kernel<<<(unsigned)(((size_t)cM * cE / 4 + 255) / 256), 256>>>(x, p_xh, (size_t)cM * cE);
    transpose_h_kernel<<<dim3(cNQ / 32, cE / 32), tblk>>>(wq, p_wqT, cE, cNQ);
    transpose_h_kernel<<<dim3(cNKV / 32, cE / 32), tblk>>>(wkvd, p_wkvT, cE, cNKV);
    transpose_h_kernel<<<dim3(cNUP / 32, cRK / 32), tblk>>>(wup, p_wupT, cRK, cNUP);
    transpose_h_kernel<<<dim3(cE / 32, cNQ / 32), tblk>>>(wout, p_woT, cNQ, cE);

    // 1) q_all = x @ wq
    tgemm_h2<128, 64, 32, false><<<dim3(cNQ / 128, cM / 128), 256, SM_G128>>>(
        p_xh, p_wqT, p_qall, cE, cE, cE, cNQ);
    // 2) kv_lat = x @ wkv_down
    tgemm_h2<64, 32, 32, false><<<dim3(cNKV / 64, cM / 128), 256, SM_G64>>>(
        p_xh, p_wkvT, p_kv, cE, cE, cE, cNKV);
    // 3) RoPE
    rope_q_kernel<<<(cM * cH * (cRD / 2) + 255) / 256, 256>>>(cosT, sinT);
    rope_k_kernel<<<(cM * (cRD / 2) + 255) / 256, 256>>>(cosT, sinT);
    // 4) up = c_kv @ w_up
    tgemm_h2<128, 64, 32, false><<<dim3(cNUP / 128, cM / 128), 256, SM_G128>>>(
        p_kv, p_wupT, p_up, cRK, cNKV, cRK, cNUP);
    // 5) gather
    {
        size_t total = (size_t)cBH * cL * (cDQK / 2);
        build_qkv_kernel<<<(unsigned)((total + 255) / 256), 256>>>();
    }
    // 6-8) fused flash attention
    flash_attn_kernel<<<dim3(cL / FBR, cBH), 256, FSMEM>>>(scale);
    // 9) out = AO @ w_out (fp32 output)
    tgemm_h2<128, 64, 32, true><<<dim3(cE / 128, cM / 128), 256, SM_G128>>>(
        p_ao, p_woT, out, cNQ, cNQ, cNQ, cE);
}

// round 8
// speedup vs baseline: 2.6328x; 1.0185x over previous
#include <cuda_runtime.h>
#include <cuda_fp16.h>
#include <math.h>
#include <stdint.h>

// ---------------- problem constants ----------------
constexpr int cH   = 16;
constexpr int cDH  = 128;
constexpr int cRK  = 512;
constexpr int cRD  = 64;
constexpr int cB   = 2;
constexpr int cL   = 2048;
constexpr int cE   = 2048;
constexpr int cDQK = cDH + cRD;          // 192
constexpr int cNQ  = cH * cDQK;          // 3072
constexpr int cNKV = cRK + cRD;          // 576
constexpr int cNUP = cH * (2*cDH + cRD); // 5120
constexpr int cM   = cB * cL;            // 4096
constexpr int cBH  = cB * cH;            // 32

// ---------------- scratch (half everywhere) ----------------
__device__ __half g_xh   [(size_t)cM * cE];
__device__ __half g_wqT  [(size_t)cNQ * cE];
__device__ __half g_wkvT [(size_t)cNKV * cE];
__device__ __half g_wupT [(size_t)cNUP * cRK];
__device__ __half g_woT  [(size_t)cE * cNQ];
__device__ __half g_qallh[(size_t)cM * cNQ];
__device__ __half g_kvh  [(size_t)cM * cNKV];
__device__ __half g_uph  [(size_t)cM * cNUP];
__device__ __half g_Qh   [(size_t)cBH * cL * cDQK];
__device__ __half g_Kh   [(size_t)cBH * cL * cDQK];
__device__ __half g_Vh   [(size_t)cBH * cL * cDQK];
__device__ __half g_AOh  [(size_t)cM * cNQ];

// ---------------- low-level helpers ----------------
__device__ __forceinline__ void mma_f16(float* d, const uint32_t* a, const uint32_t* b) {
    asm volatile(
        "mma.sync.aligned.m16n8k16.row.col.f32.f16.f16.f32 "
        "{%0,%1,%2,%3},{%4,%5,%6,%7},{%8,%9},{%0,%1,%2,%3};"
        : "+f"(d[0]), "+f"(d[1]), "+f"(d[2]), "+f"(d[3])
        : "r"(a[0]), "r"(a[1]), "r"(a[2]), "r"(a[3]), "r"(b[0]), "r"(b[1]));
}
__device__ __forceinline__ void cpa16(uint32_t s, const void* g) {
    asm volatile("cp.async.cg.shared.global [%0], [%1], 16;\n" :: "r"(s), "l"(g));
}
__device__ __forceinline__ void cp_commit() {
    asm volatile("cp.async.commit_group;\n" ::: "memory");
}
template<int N>
__device__ __forceinline__ void cp_wait() {
    asm volatile("cp.async.wait_group %0;\n" :: "n"(N) : "memory");
}
__device__ __forceinline__ void ldm_x4(uint32_t& d0, uint32_t& d1, uint32_t& d2, uint32_t& d3,
                                       uint32_t addr) {
    asm volatile("ldmatrix.sync.aligned.m8n8.x4.shared.b16 {%0,%1,%2,%3},[%4];"
                 : "=r"(d0), "=r"(d1), "=r"(d2), "=r"(d3) : "r"(addr));
}
__device__ __forceinline__ void ldm_x4_t(uint32_t& d0, uint32_t& d1, uint32_t& d2, uint32_t& d3,
                                         uint32_t addr) {
    asm volatile("ldmatrix.sync.aligned.m8n8.x4.trans.shared.b16 {%0,%1,%2,%3},[%4];"
                 : "=r"(d0), "=r"(d1), "=r"(d2), "=r"(d3) : "r"(addr));
}
__device__ __forceinline__ uint32_t pack_h2(float a, float b) {
    __half2 h = __floats2half2_rn(a, b);
    return *reinterpret_cast<uint32_t*>(&h);
}

// ---------------- fp16 GEMM v2 (unchanged R7 winner) ----------------
constexpr int GAW = 20;

template<int TBN_, int WM, int WN, bool OUTF>
__global__ void __launch_bounds__(256, 2)
tgemm_h2(const __half* __restrict__ A, const __half* __restrict__ B,
         void* __restrict__ Cout, int K, int lda, int ldb, int ldc)
{
    constexpr int MI = WM / 16;
    constexpr int NJ = WN / 8;
    constexpr int WARPS_M = 128 / WM;
    constexpr int STAGE_W = (128 + TBN_) * GAW;

    extern __shared__ uint32_t smem[];

    const int m0 = blockIdx.y * 128;
    const int n0 = blockIdx.x * TBN_;

    const int tid  = threadIdx.x;
    const int lane = tid & 31;
    const int warp = tid >> 5;
    const int wm0 = (warp % WARPS_M) * WM;
    const int wn0 = (warp / WARPS_M) * WN;
    const int lr = lane & 7, lm = lane >> 3;

    const uint32_t sbase = (uint32_t)__cvta_generic_to_shared(smem);

    const int r2 = tid >> 1;
    const int c2 = (tid & 1) * 2;

    auto issueTile = [&](int k0, int st) {
        const uint32_t abase = sbase + st * (STAGE_W * 4);
        const uint32_t bbase = abase + 128 * (GAW * 4);
#pragma unroll
        for (int c = 0; c < 2; c++) {
            cpa16(abase + r2 * (GAW * 4) + (c2 + c) * 16,
                  (const char*)A + ((size_t)(m0 + r2) * lda + k0) * 2 + (c2 + c) * 16);
        }
        if (TBN_ == 128) {
#pragma unroll
            for (int c = 0; c < 2; c++) {
                cpa16(bbase + r2 * (GAW * 4) + (c2 + c) * 16,
                      (const char*)B + ((size_t)(n0 + r2) * ldb + k0) * 2 + (c2 + c) * 16);
            }
        } else {
            int rb = tid >> 2, cb = tid & 3;
            cpa16(bbase + rb * (GAW * 4) + cb * 16,
                  (const char*)B + ((size_t)(n0 + rb) * ldb + k0) * 2 + cb * 16);
        }
        cp_commit();
    };

    float acc[MI][NJ][4];
#pragma unroll
    for (int i = 0; i < MI; i++)
#pragma unroll
        for (int j = 0; j < NJ; j++)
#pragma unroll
            for (int r = 0; r < 4; r++) acc[i][j][r] = 0.0f;

    const int NT = K / 32;
    issueTile(0, 0);
    issueTile(32, 1);

    for (int kt = 0; kt < NT; kt++) {
        if (kt == NT - 1) cp_wait<0>(); else cp_wait<1>();
        __syncthreads();
        if (kt + 2 < NT) issueTile((kt + 2) * 32, (kt + 2) % 3);

        const int st = kt % 3;
        const uint32_t abase = sbase + st * (STAGE_W * 4);
        const uint32_t bbase = abase + 128 * (GAW * 4);

#pragma unroll
        for (int s = 0; s < 2; s++) {
            uint32_t a[MI][4], b[NJ][2];
#pragma unroll
            for (int i = 0; i < MI; i++) {
                uint32_t addr = abase +
                    (uint32_t)(wm0 + i * 16 + (lm & 1) * 8 + lr) * (GAW * 4) +
                    s * 32 + (lm >> 1) * 16;
                ldm_x4(a[i][0], a[i][1], a[i][2], a[i][3], addr);
            }
#pragma unroll
            for (int p = 0; p < NJ / 2; p++) {
                uint32_t addr = bbase +
                    (uint32_t)(wn0 + p * 16 + (lm >> 1) * 8 + lr) * (GAW * 4) +
                    s * 32 + (lm & 1) * 16;
                ldm_x4(b[2 * p][0], b[2 * p][1], b[2 * p + 1][0], b[2 * p + 1][1], addr);
            }
#pragma unroll
            for (int i = 0; i < MI; i++)
#pragma unroll
                for (int j = 0; j < NJ; j++)
                    mma_f16(acc[i][j], a[i], b[j]);
        }
    }

    const int qr = lane >> 2, qc = lane & 3;
#pragma unroll
    for (int i = 0; i < MI; i++) {
#pragma unroll
        for (int j = 0; j < NJ; j++) {
            const int r = m0 + wm0 + i * 16 + qr;
            const int c = n0 + wn0 + j * 8 + 2 * qc;
            if (OUTF) {
                float* C = (float*)Cout;
                float2 v0 = { acc[i][j][0], acc[i][j][1] };
                float2 v1 = { acc[i][j][2], acc[i][j][3] };
                *reinterpret_cast<float2*>(&C[(size_t)r * ldc + c]) = v0;
                *reinterpret_cast<float2*>(&C[(size_t)(r + 8) * ldc + c]) = v1;
            } else {
                __half* C = (__half*)Cout;
                *reinterpret_cast<__half2*>(&C[(size_t)r * ldc + c]) =
                    __floats2half2_rn(acc[i][j][0], acc[i][j][1]);
                *reinterpret_cast<__half2*>(&C[(size_t)(r + 8) * ldc + c]) =
                    __floats2half2_rn(acc[i][j][2], acc[i][j][3]);
            }
        }
    }
}

constexpr int SM_G128 = (128 + 128) * GAW * 4 * 3;
constexpr int SM_G64  = (128 + 64)  * GAW * 4 * 3;

// ---------------- fused flash attention v3 ----------------
// Q fragments hoisted to registers (loop-invariant); K fragments via ldmatrix.x4.
constexpr int FBR = 128;
constexpr int FBC = 64;
constexpr int FQW = 100;
constexpr int FW_Q = FBR * FQW;
constexpr int FW_KV = FBC * FQW;
constexpr int FSMEM = (FW_Q + 4 * FW_KV) * 4;

__global__ void __launch_bounds__(256, 1)
flash_attn_kernel(float scale)
{
    extern __shared__ uint32_t sh[];
    uint32_t* Qs = sh;
    uint32_t* Ks = Qs + FW_Q;
    uint32_t* Vs = Ks + 2 * FW_KV;

    const int mb = (int)gridDim.x - 1 - (int)blockIdx.x;
    const int bh = blockIdx.y;
    const int b = bh / cH, h = bh % cH;
    const int m0 = mb * FBR;
    const int tid = threadIdx.x;
    const int lane = tid & 31, warp = tid >> 5;
    const int wr = warp * 16;
    const int qr = lane >> 2, qc = lane & 3;
    const int lr = lane & 7, lm = lane >> 3;

    const __half* Qg = g_Qh + (size_t)bh * cL * cDQK;
    const __half* Kg = g_Kh + (size_t)bh * cL * cDQK;
    const __half* Vg = g_Vh + (size_t)bh * cL * cDQK;

    const uint32_t qs_addr = (uint32_t)__cvta_generic_to_shared(Qs);
    const uint32_t ks_addr = (uint32_t)__cvta_generic_to_shared(Ks);
    const uint32_t vs_addr = (uint32_t)__cvta_generic_to_shared(Vs);

    auto prefetchKV = [&](int kb, int pbuf) {
        const char* Kr = (const char*)(Kg + (size_t)(kb * FBC) * cDQK);
        const char* Vr = (const char*)(Vg + (size_t)(kb * FBC) * cDQK);
        const uint32_t kb_s = ks_addr + pbuf * (FW_KV * 4);
        const uint32_t vb_s = vs_addr + pbuf * (FW_KV * 4);
#pragma unroll
        for (int n = 0; n < 6; n++) {
            int idx = tid + n * 256;
            int r = idx / 24, c = idx % 24;
            cpa16(kb_s + r * (FQW * 4) + c * 16, Kr + r * 384 + c * 16);
            cpa16(vb_s + r * (FQW * 4) + c * 16, Vr + r * 384 + c * 16);
        }
        cp_commit();
    };

    prefetchKV(0, 0);

    // Q tile -> smem
    for (int n = 0; n < 12; n++) {
        int idx = tid + n * 256;
        int r = idx / 24, c = idx % 24;
        uint4 v = *reinterpret_cast<const uint4*>(
            (const char*)Qg + (size_t)(m0 + r) * 384 + c * 16);
        *reinterpret_cast<uint4*>((char*)Qs + r * (FQW * 4) + c * 16) = v;
    }
    __syncthreads();

    // ---- hoist Q fragments into registers (loop-invariant) ----
    uint32_t qa[12][4];
#pragma unroll
    for (int ks = 0; ks < 12; ks++) {
        uint32_t addr = qs_addr +
            (uint32_t)(wr + (lm & 1) * 8 + lr) * (FQW * 4) +
            ks * 32 + (lm >> 1) * 16;
        ldm_x4(qa[ks][0], qa[ks][1], qa[ks][2], qa[ks][3], addr);
    }

    float oacc[24][4];
#pragma unroll
    for (int j = 0; j < 24; j++)
#pragma unroll
        for (int e = 0; e < 4; e++) oacc[j][e] = 0.0f;
    float mrow[2] = { -1e30f, -1e30f };
    float lrow[2] = { 0.0f, 0.0f };

    const int kbmax = 2 * mb + 1;
    const int rowg0 = m0 + wr + qr;
    int buf = 0;
    for (int kb = 0; kb <= kbmax; kb++) {
        if (kb < kbmax) {
            prefetchKV(kb + 1, buf ^ 1);
            cp_wait<1>();
        } else {
            cp_wait<0>();
        }
        __syncthreads();

        const bool skip = (kb * FBC > m0 + wr + 15);
        if (!skip) {
            const uint32_t kbuf = ks_addr + buf * (FW_KV * 4);
            const uint32_t vbuf = vs_addr + buf * (FW_KV * 4);

            // ---- S = Q @ K^T (K frags via ldmatrix.x4) ----
            float sacc[8][4];
#pragma unroll
            for (int j = 0; j < 8; j++)
#pragma unroll
                for (int e = 0; e < 4; e++) sacc[j][e] = 0.0f;

#pragma unroll
            for (int ks = 0; ks < 12; ks++) {
#pragma unroll
                for (int p = 0; p < 4; p++) {
                    uint32_t b2[4];
                    uint32_t addr = kbuf +
                        (uint32_t)(p * 16 + (lm >> 1) * 8 + lr) * (FQW * 4) +
                        ks * 32 + (lm & 1) * 16;
                    ldm_x4(b2[0], b2[1], b2[2], b2[3], addr);
                    uint32_t b0[2] = { b2[0], b2[1] };
                    uint32_t b1[2] = { b2[2], b2[3] };
                    mma_f16(sacc[2 * p], qa[ks], b0);
                    mma_f16(sacc[2 * p + 1], qa[ks], b1);
                }
            }

            const bool diag = (kb * FBC + FBC - 1 > m0 + wr);
            float tmax[2] = { -1e30f, -1e30f };
#pragma unroll
            for (int j = 0; j < 8; j++) {
#pragma unroll
                for (int e = 0; e < 4; e++) {
                    float s = sacc[j][e] * scale;
                    if (diag) {
                        int col = kb * FBC + j * 8 + 2 * qc + (e & 1);
                        int row = rowg0 + 8 * (e >> 1);
                        if (col > row) s = -1e30f;
                    }
                    sacc[j][e] = s;
                    tmax[e >> 1] = fmaxf(tmax[e >> 1], s);
                }
            }
#pragma unroll
            for (int half = 0; half < 2; half++) {
                tmax[half] = fmaxf(tmax[half], __shfl_xor_sync(0xffffffffu, tmax[half], 1));
                tmax[half] = fmaxf(tmax[half], __shfl_xor_sync(0xffffffffu, tmax[half], 2));
            }

            float mnew[2], alf[2], psum[2] = { 0.0f, 0.0f };
#pragma unroll
            for (int half = 0; half < 2; half++) {
                mnew[half] = fmaxf(mrow[half], tmax[half]);
                alf[half] = __expf(mrow[half] - mnew[half]);
                mrow[half] = mnew[half];
            }

#pragma unroll
            for (int j = 0; j < 8; j++) {
                sacc[j][0] = __expf(sacc[j][0] - mnew[0]);
                sacc[j][1] = __expf(sacc[j][1] - mnew[0]);
                sacc[j][2] = __expf(sacc[j][2] - mnew[1]);
                sacc[j][3] = __expf(sacc[j][3] - mnew[1]);
                psum[0] += sacc[j][0] + sacc[j][1];
                psum[1] += sacc[j][2] + sacc[j][3];
            }
#pragma unroll
            for (int half = 0; half < 2; half++) {
                psum[half] += __shfl_xor_sync(0xffffffffu, psum[half], 1);
                psum[half] += __shfl_xor_sync(0xffffffffu, psum[half], 2);
                lrow[half] = lrow[half] * alf[half] + psum[half];
            }

#pragma unroll
            for (int j = 0; j < 24; j++) {
                oacc[j][0] *= alf[0];
                oacc[j][1] *= alf[0];
                oacc[j][2] *= alf[1];
                oacc[j][3] *= alf[1];
            }

            const int g = lane >> 3, lj = lane & 7;
            const uint32_t vrow_base = vbuf + ((g & 1) * 8 + lj) * (FQW * 4) + (g >> 1) * 16;
#pragma unroll
            for (int ks2 = 0; ks2 < 4; ks2++) {
                uint32_t pa[4] = {
                    pack_h2(sacc[2 * ks2][0],     sacc[2 * ks2][1]),
                    pack_h2(sacc[2 * ks2][2],     sacc[2 * ks2][3]),
                    pack_h2(sacc[2 * ks2 + 1][0], sacc[2 * ks2 + 1][1]),
                    pack_h2(sacc[2 * ks2 + 1][2], sacc[2 * ks2 + 1][3])
                };
                const uint32_t krow = vrow_base + ks2 * 16 * (FQW * 4);
#pragma unroll
                for (int jp = 0; jp < 12; jp++) {
                    uint32_t d0, d1, d2, d3;
                    ldm_x4_t(d0, d1, d2, d3, krow + jp * 32);
                    uint32_t b0[2] = { d0, d1 };
                    uint32_t b1[2] = { d2, d3 };
                    mma_f16(oacc[2 * jp], pa, b0);
                    mma_f16(oacc[2 * jp + 1], pa, b1);
                }
            }
        }
        __syncthreads();
        buf ^= 1;
    }

    const float inv0 = 1.0f / lrow[0];
    const float inv1 = 1.0f / lrow[1];
    const size_t base0 = ((size_t)b * cL + (m0 + wr + qr)) * cNQ + (size_t)h * cDQK;
    const size_t base1 = base0 + 8 * cNQ;
#pragma unroll
    for (int j = 0; j < 24; j++) {
        const int c = j * 8 + 2 * qc;
        *reinterpret_cast<__half2*>(&g_AOh[base0 + c]) =
            __floats2half2_rn(oacc[j][0] * inv0, oacc[j][1] * inv0);
        *reinterpret_cast<__half2*>(&g_AOh[base1 + c]) =
            __floats2half2_rn(oacc[j][2] * inv1, oacc[j][3] * inv1);
    }
}

// ---------------- prep kernels ----------------
__global__ void f2h_kernel(const float* __restrict__ s, __half* __restrict__ d, size_t n)
{
    size_t i = ((size_t)blockIdx.x * blockDim.x + threadIdx.x) * 4;
    if (i >= n) return;
    float4 v = *reinterpret_cast<const float4*>(&s[i]);
    *reinterpret_cast<__half2*>(&d[i]) = __floats2half2_rn(v.x, v.y);
    *reinterpret_cast<__half2*>(&d[i + 2]) = __floats2half2_rn(v.z, v.w);
}

__global__ void transpose_h_kernel(const float* __restrict__ src, __half* __restrict__ dst,
                                   int R, int C)
{
    __shared__ float t[32][33];
    const int c0 = blockIdx.x * 32, r0 = blockIdx.y * 32;
    const int x = threadIdx.x, y = threadIdx.y;
#pragma unroll
    for (int dy = 0; dy < 32; dy += 8)
        t[y + dy][x] = src[(size_t)(r0 + y + dy) * C + c0 + x];
    __syncthreads();
#pragma unroll
    for (int dy = 0; dy < 32; dy += 8)
        dst[(size_t)(c0 + y + dy) * R + r0 + x] = __float2half_rn(t[x][y + dy]);
}

// ---------------- RoPE on half ----------------
__global__ void rope_q_kernel(const float* __restrict__ cosT, const float* __restrict__ sinT)
{
    int idx = blockIdx.x * blockDim.x + threadIdx.x;
    if (idx >= cM * cH * (cRD / 2)) return;
    int i = idx % (cRD / 2);
    int h = (idx / (cRD / 2)) % cH;
    int row = idx / ((cRD / 2) * cH);
    int l = row % cL;
    float c = cosT[l * (cRD / 2) + i];
    float s = sinT[l * (cRD / 2) + i];
    __half2* p = reinterpret_cast<__half2*>(&g_qallh[(size_t)row * cNQ + h * cDQK + cDH + 2 * i]);
    float2 v = __half22float2(*p);
    *p = __floats2half2_rn(v.x * c - v.y * s, v.x * s + v.y * c);
}

__global__ void rope_k_kernel(const float* __restrict__ cosT, const float* __restrict__ sinT)
{
    int idx = blockIdx.x * blockDim.x + threadIdx.x;
    if (idx >= cM * (cRD / 2)) return;
    int i = idx % (cRD / 2);
    int row = idx / (cRD / 2);
    int l = row % cL;
    float c = cosT[l * (cRD / 2) + i];
    float s = sinT[l * (cRD / 2) + i];
    __half2* p = reinterpret_cast<__half2*>(&g_kvh[(size_t)row * cNKV + cRK + 2 * i]);
    float2 v = __half22float2(*p);
    *p = __floats2half2_rn(v.x * c - v.y * s, v.x * s + v.y * c);
}

// ---------------- gather Q/K/V ----------------
__global__ void build_qkv_kernel()
{
    size_t idx = (size_t)blockIdx.x * blockDim.x + threadIdx.x;
    const size_t total = (size_t)cBH * cL * (cDQK / 2);
    if (idx >= total) return;
    int d2 = (int)(idx % (cDQK / 2));
    int l = (int)((idx / (cDQK / 2)) % cL);
    int bh = (int)(idx / ((size_t)(cDQK / 2) * cL));
    int b = bh / cH, h = bh % cH;
    size_t row = (size_t)b * cL + l;
    int d = 2 * d2;

    __half2 q = *reinterpret_cast<const __half2*>(&g_qallh[row * cNQ + h * cDQK + d]);
    __half2 k, v;
    const size_t upo = row * cNUP + (size_t)h * (2 * cDH + cRD);
    if (d < cDH) {
        k = *reinterpret_cast<const __half2*>(&g_uph[upo + d]);
        v = *reinterpret_cast<const __half2*>(&g_uph[upo + cDH + d]);
    } else {
        k = *reinterpret_cast<const __half2*>(&g_kvh[row * cNKV + cRK + (d - cDH)]);
        v = *reinterpret_cast<const __half2*>(&g_uph[upo + 2 * cDH + (d - cDH)]);
    }
    reinterpret_cast<__half2*>(g_Qh)[idx] = q;
    reinterpret_cast<__half2*>(g_Kh)[idx] = k;
    reinterpret_cast<__half2*>(g_Vh)[idx] = v;
}

// ---------------- launch ----------------
extern "C" void kernel_launch(void* const* d_in, const int* in_sizes, int n_in,
                              void* d_out, int out_size)
{
    const float* x    = (const float*)d_in[0];
    const float* cosT = (const float*)d_in[1];
    const float* sinT = (const float*)d_in[2];
    const float* wq   = (const float*)d_in[3];
    const float* wkvd = (const float*)d_in[4];
    const float* wup  = (const float*)d_in[5];
    const float* wout = (const float*)d_in[6];
    float* out = (float*)d_out;

    __half *p_xh, *p_wqT, *p_wkvT, *p_wupT, *p_woT;
    __half *p_qall, *p_kv, *p_up, *p_ao;
    cudaGetSymbolAddress((void**)&p_xh,   g_xh);
    cudaGetSymbolAddress((void**)&p_wqT,  g_wqT);
    cudaGetSymbolAddress((void**)&p_wkvT, g_wkvT);
    cudaGetSymbolAddress((void**)&p_wupT, g_wupT);
    cudaGetSymbolAddress((void**)&p_woT,  g_woT);
    cudaGetSymbolAddress((void**)&p_qall, g_qallh);
    cudaGetSymbolAddress((void**)&p_kv,   g_kvh);
    cudaGetSymbolAddress((void**)&p_up,   g_uph);
    cudaGetSymbolAddress((void**)&p_ao,   g_AOh);

    cudaFuncSetAttribute(flash_attn_kernel,
                         cudaFuncAttributeMaxDynamicSharedMemorySize, FSMEM);
    cudaFuncSetAttribute((const void*)tgemm_h2<128, 64, 32, false>,
                         cudaFuncAttributeMaxDynamicSharedMemorySize, SM_G128);
    cudaFuncSetAttribute((const void*)tgemm_h2<64, 32, 32, false>,
                         cudaFuncAttributeMaxDynamicSharedMemorySize, SM_G64);
    cudaFuncSetAttribute((const void*)tgemm_h2<128, 64, 32, true>,
                         cudaFuncAttributeMaxDynamicSharedMemorySize, SM_G128);

    const float scale = 1.0f / sqrtf((float)cDQK);
    dim3 tblk(32, 8);

    // 0) converts + weight transposes
    f2h_kernel<<<(unsigned)(((size_t)cM * cE / 4 + 255) / 256), 256>>>(x, p_xh, (size_t)cM * cE);
    transpose_h_kernel<<<dim3(cNQ / 32, cE / 32), tblk>>>(wq, p_wqT, cE, cNQ);
    transpose_h_kernel<<<dim3(cNKV / 32, cE / 32), tblk>>>(wkvd, p_wkvT, cE, cNKV);
    transpose_h_kernel<<<dim3(cNUP / 32, cRK / 32), tblk>>>(wup, p_wupT, cRK, cNUP);
    transpose_h_kernel<<<dim3(cE / 32, cNQ / 32), tblk>>>(wout, p_woT, cNQ, cE);

    // 1) q_all = x @ wq
    tgemm_h2<128, 64, 32, false><<<dim3(cNQ / 128, cM / 128), 256, SM_G128>>>(
        p_xh, p_wqT, p_qall, cE, cE, cE, cNQ);
    // 2) kv_lat = x @ wkv_down
    tgemm_h2<64, 32, 32, false><<<dim3(cNKV / 64, cM / 128), 256, SM_G64>>>(
        p_xh, p_wkvT, p_kv, cE, cE, cE, cNKV);
    // 3) RoPE
    rope_q_kernel<<<(cM * cH * (cRD / 2) + 255) / 256, 256>>>(cosT, sinT);
    rope_k_kernel<<<(cM * (cRD / 2) + 255) / 256, 256>>>(cosT, sinT);
    // 4) up = c_kv @ w_up
    tgemm_h2<128, 64, 32, false><<<dim3(cNUP / 128, cM / 128), 256, SM_G128>>>(
        p_kv, p_wupT, p_up, cRK, cNKV, cRK, cNUP);
    // 5) gather
    {
        size_t total = (size_t)cBH * cL * (cDQK / 2);
        build_qkv_kernel<<<(unsigned)((total + 255) / 256), 256>>>();
    }
    // 6-8) fused flash attention
    flash_attn_kernel<<<dim3(cL / FBR, cBH), 256, FSMEM>>>(scale);
    // 9) out = AO @ w_out (fp32 output)
    tgemm_h2<128, 64, 32, true><<<dim3(cE / 128, cM / 128), 256, SM_G128>>>(
        p_ao, p_woT, out, cNQ, cNQ, cNQ, cE);
}

// round 9
// speedup vs baseline: 2.6530x; 1.0077x over previous
#include <cuda_runtime.h>
#include <cuda_fp16.h>
#include <math.h>
#include <stdint.h>

// ---------------- problem constants ----------------
constexpr int cH   = 16;
constexpr int cDH  = 128;
constexpr int cRK  = 512;
constexpr int cRD  = 64;
constexpr int cB   = 2;
constexpr int cL   = 2048;
constexpr int cE   = 2048;
constexpr int cDQK = cDH + cRD;          // 192
constexpr int cNQ  = cH * cDQK;          // 3072
constexpr int cNKV = cRK + cRD;          // 576
constexpr int cNUP = cH * (2*cDH + cRD); // 5120
constexpr int cM   = cB * cL;            // 4096
constexpr int cBH  = cB * cH;            // 32
constexpr int PGRID = 296;               // persistent grid (2 per SM x 148)

// ---------------- scratch (half everywhere) ----------------
__device__ __half g_xh   [(size_t)cM * cE];
__device__ __half g_wqT  [(size_t)cNQ * cE];
__device__ __half g_wkvT [(size_t)cNKV * cE];
__device__ __half g_wupT [(size_t)cNUP * cRK];
__device__ __half g_woT  [(size_t)cE * cNQ];
__device__ __half g_qallh[(size_t)cM * cNQ];
__device__ __half g_kvh  [(size_t)cM * cNKV];
__device__ __half g_uph  [(size_t)cM * cNUP];
__device__ __half g_Qh   [(size_t)cBH * cL * cDQK];
__device__ __half g_Kh   [(size_t)cBH * cL * cDQK];
__device__ __half g_Vh   [(size_t)cBH * cL * cDQK];
__device__ __half g_AOh  [(size_t)cM * cNQ];

// ---------------- low-level helpers ----------------
__device__ __forceinline__ void mma_f16(float* d, const uint32_t* a, const uint32_t* b) {
    asm volatile(
        "mma.sync.aligned.m16n8k16.row.col.f32.f16.f16.f32 "
        "{%0,%1,%2,%3},{%4,%5,%6,%7},{%8,%9},{%0,%1,%2,%3};"
        : "+f"(d[0]), "+f"(d[1]), "+f"(d[2]), "+f"(d[3])
        : "r"(a[0]), "r"(a[1]), "r"(a[2]), "r"(a[3]), "r"(b[0]), "r"(b[1]));
}
__device__ __forceinline__ void cpa16(uint32_t s, const void* g) {
    asm volatile("cp.async.cg.shared.global [%0], [%1], 16;\n" :: "r"(s), "l"(g));
}
__device__ __forceinline__ void cp_commit() {
    asm volatile("cp.async.commit_group;\n" ::: "memory");
}
template<int N>
__device__ __forceinline__ void cp_wait() {
    asm volatile("cp.async.wait_group %0;\n" :: "n"(N) : "memory");
}
__device__ __forceinline__ void ldm_x4(uint32_t& d0, uint32_t& d1, uint32_t& d2, uint32_t& d3,
                                       uint32_t addr) {
    asm volatile("ldmatrix.sync.aligned.m8n8.x4.shared.b16 {%0,%1,%2,%3},[%4];"
                 : "=r"(d0), "=r"(d1), "=r"(d2), "=r"(d3) : "r"(addr));
}
__device__ __forceinline__ void ldm_x4_t(uint32_t& d0, uint32_t& d1, uint32_t& d2, uint32_t& d3,
                                         uint32_t addr) {
    asm volatile("ldmatrix.sync.aligned.m8n8.x4.trans.shared.b16 {%0,%1,%2,%3},[%4];"
                 : "=r"(d0), "=r"(d1), "=r"(d2), "=r"(d3) : "r"(addr));
}
__device__ __forceinline__ uint32_t pack_h2(float a, float b) {
    __half2 h = __floats2half2_rn(a, b);
    return *reinterpret_cast<uint32_t*>(&h);
}

// ---------------- fp16 GEMM v3: persistent CTAs ----------------
constexpr int GAW = 20;

template<int TBN_, int WM, int WN, bool OUTF>
__global__ void __launch_bounds__(256, 2)
tgemm_h3(const __half* __restrict__ A, const __half* __restrict__ B,
         void* __restrict__ Cout, int K, int lda, int ldb, int ldc,
         int tilesM, int tilesN)
{
    constexpr int MI = WM / 16;
    constexpr int NJ = WN / 8;
    constexpr int WARPS_M = 128 / WM;
    constexpr int STAGE_W = (128 + TBN_) * GAW;

    extern __shared__ uint32_t smem[];

    const int tid  = threadIdx.x;
    const int lane = tid & 31;
    const int warp = tid >> 5;
    const int wm0 = (warp % WARPS_M) * WM;
    const int wn0 = (warp / WARPS_M) * WN;
    const int lr = lane & 7, lm = lane >> 3;
    const int qr = lane >> 2, qc = lane & 3;

    const uint32_t sbase = (uint32_t)__cvta_generic_to_shared(smem);
    const int r2 = tid >> 1;
    const int c2 = (tid & 1) * 2;

    const int NT = K / 32;
    const int ntiles = tilesM * tilesN;

    for (int t = blockIdx.x; t < ntiles; t += gridDim.x) {
        const int m0 = (t / tilesN) * 128;
        const int n0 = (t % tilesN) * TBN_;

        auto issueTile = [&](int k0, int st) {
            const uint32_t abase = sbase + st * (STAGE_W * 4);
            const uint32_t bbase = abase + 128 * (GAW * 4);
#pragma unroll
            for (int c = 0; c < 2; c++) {
                cpa16(abase + r2 * (GAW * 4) + (c2 + c) * 16,
                      (const char*)A + ((size_t)(m0 + r2) * lda + k0) * 2 + (c2 + c) * 16);
            }
            if (TBN_ == 128) {
#pragma unroll
                for (int c = 0; c < 2; c++) {
                    cpa16(bbase + r2 * (GAW * 4) + (c2 + c) * 16,
                          (const char*)B + ((size_t)(n0 + r2) * ldb + k0) * 2 + (c2 + c) * 16);
                }
            } else {
                int rb = tid >> 2, cb = tid & 3;
                cpa16(bbase + rb * (GAW * 4) + cb * 16,
                      (const char*)B + ((size_t)(n0 + rb) * ldb + k0) * 2 + cb * 16);
            }
            cp_commit();
        };

        float acc[MI][NJ][4];
#pragma unroll
        for (int i = 0; i < MI; i++)
#pragma unroll
            for (int j = 0; j < NJ; j++)
#pragma unroll
                for (int r = 0; r < 4; r++) acc[i][j][r] = 0.0f;

        issueTile(0, 0);
        issueTile(32, 1);

        for (int kt = 0; kt < NT; kt++) {
            if (kt == NT - 1) cp_wait<0>(); else cp_wait<1>();
            __syncthreads();
            if (kt + 2 < NT) issueTile((kt + 2) * 32, (kt + 2) % 3);

            const int st = kt % 3;
            const uint32_t abase = sbase + st * (STAGE_W * 4);
            const uint32_t bbase = abase + 128 * (GAW * 4);

#pragma unroll
            for (int s = 0; s < 2; s++) {
                uint32_t a[MI][4], b[NJ][2];
#pragma unroll
                for (int i = 0; i < MI; i++) {
                    uint32_t addr = abase +
                        (uint32_t)(wm0 + i * 16 + (lm & 1) * 8 + lr) * (GAW * 4) +
                        s * 32 + (lm >> 1) * 16;
                    ldm_x4(a[i][0], a[i][1], a[i][2], a[i][3], addr);
                }
#pragma unroll
                for (int p = 0; p < NJ / 2; p++) {
                    uint32_t addr = bbase +
                        (uint32_t)(wn0 + p * 16 + (lm >> 1) * 8 + lr) * (GAW * 4) +
                        s * 32 + (lm & 1) * 16;
                    ldm_x4(b[2 * p][0], b[2 * p][1], b[2 * p + 1][0], b[2 * p + 1][1], addr);
                }
#pragma unroll
                for (int i = 0; i < MI; i++)
#pragma unroll
                    for (int j = 0; j < NJ; j++)
                        mma_f16(acc[i][j], a[i], b[j]);
            }
        }

#pragma unroll
        for (int i = 0; i < MI; i++) {
#pragma unroll
            for (int j = 0; j < NJ; j++) {
                const int r = m0 + wm0 + i * 16 + qr;
                const int c = n0 + wn0 + j * 8 + 2 * qc;
                if (OUTF) {
                    float* C = (float*)Cout;
                    float2 v0 = { acc[i][j][0], acc[i][j][1] };
                    float2 v1 = { acc[i][j][2], acc[i][j][3] };
                    *reinterpret_cast<float2*>(&C[(size_t)r * ldc + c]) = v0;
                    *reinterpret_cast<float2*>(&C[(size_t)(r + 8) * ldc + c]) = v1;
                } else {
                    __half* C = (__half*)Cout;
                    *reinterpret_cast<__half2*>(&C[(size_t)r * ldc + c]) =
                        __floats2half2_rn(acc[i][j][0], acc[i][j][1]);
                    *reinterpret_cast<__half2*>(&C[(size_t)(r + 8) * ldc + c]) =
                        __floats2half2_rn(acc[i][j][2], acc[i][j][3]);
                }
            }
        }
        __syncthreads();   // protect stage buffers before next tile's prologue
    }
}

constexpr int SM_G128 = (128 + 128) * GAW * 4 * 3;   // 61,440 B
constexpr int SM_G64  = (128 + 64)  * GAW * 4 * 3;   // 46,080 B

// ---------------- fused flash attention v4: 3-stage KV, 1 sync/iter ----------------
constexpr int FBR = 128;
constexpr int FBC = 64;
constexpr int FQW = 100;
constexpr int FW_Q = FBR * FQW;                  // 12800 words
constexpr int FW_KV = FBC * FQW;                 // 6400 words (K or V)
constexpr int FSTG = 2 * FW_KV;                  // one stage: K then V
constexpr int FSMEM = (FW_Q + 3 * FSTG) * 4;     // 204,800 B

__global__ void __launch_bounds__(256, 1)
flash_attn_kernel(float scale)
{
    extern __shared__ uint32_t sh[];
    uint32_t* Qs = sh;

    const int mb = (int)gridDim.x - 1 - (int)blockIdx.x;
    const int bh = blockIdx.y;
    const int b = bh / cH, h = bh % cH;
    const int m0 = mb * FBR;
    const int tid = threadIdx.x;
    const int lane = tid & 31, warp = tid >> 5;
    const int wr = warp * 16;
    const int qr = lane >> 2, qc = lane & 3;
    const int lr = lane & 7, lm = lane >> 3;

    const __half* Qg = g_Qh + (size_t)bh * cL * cDQK;
    const __half* Kg = g_Kh + (size_t)bh * cL * cDQK;
    const __half* Vg = g_Vh + (size_t)bh * cL * cDQK;

    const uint32_t qs_addr = (uint32_t)__cvta_generic_to_shared(Qs);
    const uint32_t st_addr = qs_addr + FW_Q * 4;

    auto prefetchKV = [&](int kb, int st) {
        const char* Kr = (const char*)(Kg + (size_t)(kb * FBC) * cDQK);
        const char* Vr = (const char*)(Vg + (size_t)(kb * FBC) * cDQK);
        const uint32_t kb_s = st_addr + st * (FSTG * 4);
        const uint32_t vb_s = kb_s + FW_KV * 4;
#pragma unroll
        for (int n = 0; n < 6; n++) {
            int idx = tid + n * 256;
            int r = idx / 24, c = idx % 24;
            cpa16(kb_s + r * (FQW * 4) + c * 16, Kr + r * 384 + c * 16);
            cpa16(vb_s + r * (FQW * 4) + c * 16, Vr + r * 384 + c * 16);
        }
        cp_commit();
    };

    const int kbmax = 2 * mb + 1;

    prefetchKV(0, 0);
    // Q tile -> smem
    for (int n = 0; n < 12; n++) {
        int idx = tid + n * 256;
        int r = idx / 24, c = idx % 24;
        uint4 v = *reinterpret_cast<const uint4*>(
            (const char*)Qg + (size_t)(m0 + r) * 384 + c * 16);
        *reinterpret_cast<uint4*>((char*)Qs + r * (FQW * 4) + c * 16) = v;
    }
    if (1 <= kbmax) prefetchKV(1, 1);
    __syncthreads();

    // hoist Q fragments (loop-invariant)
    uint32_t qa[12][4];
#pragma unroll
    for (int ks = 0; ks < 12; ks++) {
        uint32_t addr = qs_addr +
            (uint32_t)(wr + (lm & 1) * 8 + lr) * (FQW * 4) +
            ks * 32 + (lm >> 1) * 16;
        ldm_x4(qa[ks][0], qa[ks][1], qa[ks][2], qa[ks][3], addr);
    }

    float oacc[24][4];
#pragma unroll
    for (int j = 0; j < 24; j++)
#pragma unroll
        for (int e = 0; e < 4; e++) oacc[j][e] = 0.0f;
    float mrow[2] = { -1e30f, -1e30f };
    float lrow[2] = { 0.0f, 0.0f };

    const int rowg0 = m0 + wr + qr;
    for (int kb = 0; kb <= kbmax; kb++) {
        if (kb < kbmax) cp_wait<1>(); else cp_wait<0>();
        __syncthreads();
        if (kb + 2 <= kbmax) prefetchKV(kb + 2, (kb + 2) % 3);

        const bool skip = (kb * FBC > m0 + wr + 15);
        if (!skip) {
            const uint32_t kbuf = st_addr + (kb % 3) * (FSTG * 4);
            const uint32_t vbuf = kbuf + FW_KV * 4;

            // ---- S = Q @ K^T ----
            float sacc[8][4];
#pragma unroll
            for (int j = 0; j < 8; j++)
#pragma unroll
                for (int e = 0; e < 4; e++) sacc[j][e] = 0.0f;

#pragma unroll
            for (int ks = 0; ks < 12; ks++) {
#pragma unroll
                for (int p = 0; p < 4; p++) {
                    uint32_t b2[4];
                    uint32_t addr = kbuf +
                        (uint32_t)(p * 16 + (lm >> 1) * 8 + lr) * (FQW * 4) +
                        ks * 32 + (lm & 1) * 16;
                    ldm_x4(b2[0], b2[1], b2[2], b2[3], addr);
                    uint32_t b0[2] = { b2[0], b2[1] };
                    uint32_t b1[2] = { b2[2], b2[3] };
                    mma_f16(sacc[2 * p], qa[ks], b0);
                    mma_f16(sacc[2 * p + 1], qa[ks], b1);
                }
            }

            const bool diag = (kb * FBC + FBC - 1 > m0 + wr);
            float tmax[2] = { -1e30f, -1e30f };
#pragma unroll
            for (int j = 0; j < 8; j++) {
#pragma unroll
                for (int e = 0; e < 4; e++) {
                    float s = sacc[j][e] * scale;
                    if (diag) {
                        int col = kb * FBC + j * 8 + 2 * qc + (e & 1);
                        int row = rowg0 + 8 * (e >> 1);
                        if (col > row) s = -1e30f;
                    }
                    sacc[j][e] = s;
                    tmax[e >> 1] = fmaxf(tmax[e >> 1], s);
                }
            }
#pragma unroll
            for (int half = 0; half < 2; half++) {
                tmax[half] = fmaxf(tmax[half], __shfl_xor_sync(0xffffffffu, tmax[half], 1));
                tmax[half] = fmaxf(tmax[half], __shfl_xor_sync(0xffffffffu, tmax[half], 2));
            }

            float mnew[2], alf[2], psum[2] = { 0.0f, 0.0f };
#pragma unroll
            for (int half = 0; half < 2; half++) {
                mnew[half] = fmaxf(mrow[half], tmax[half]);
                alf[half] = __expf(mrow[half] - mnew[half]);
                mrow[half] = mnew[half];
            }

#pragma unroll
            for (int j = 0; j < 8; j++) {
                sacc[j][0] = __expf(sacc[j][0] - mnew[0]);
                sacc[j][1] = __expf(sacc[j][1] - mnew[0]);
                sacc[j][2] = __expf(sacc[j][2] - mnew[1]);
                sacc[j][3] = __expf(sacc[j][3] - mnew[1]);
                psum[0] += sacc[j][0] + sacc[j][1];
                psum[1] += sacc[j][2] + sacc[j][3];
            }
#pragma unroll
            for (int half = 0; half < 2; half++) {
                psum[half] += __shfl_xor_sync(0xffffffffu, psum[half], 1);
                psum[half] += __shfl_xor_sync(0xffffffffu, psum[half], 2);
                lrow[half] = lrow[half] * alf[half] + psum[half];
            }

#pragma unroll
            for (int j = 0; j < 24; j++) {
                oacc[j][0] *= alf[0];
                oacc[j][1] *= alf[0];
                oacc[j][2] *= alf[1];
                oacc[j][3] *= alf[1];
            }

            const int g = lane >> 3, lj = lane & 7;
            const uint32_t vrow_base = vbuf + ((g & 1) * 8 + lj) * (FQW * 4) + (g >> 1) * 16;
#pragma unroll
            for (int ks2 = 0; ks2 < 4; ks2++) {
                uint32_t pa[4] = {
                    pack_h2(sacc[2 * ks2][0],     sacc[2 * ks2][1]),
                    pack_h2(sacc[2 * ks2][2],     sacc[2 * ks2][3]),
                    pack_h2(sacc[2 * ks2 + 1][0], sacc[2 * ks2 + 1][1]),
                    pack_h2(sacc[2 * ks2 + 1][2], sacc[2 * ks2 + 1][3])
                };
                const uint32_t krow = vrow_base + ks2 * 16 * (FQW * 4);
#pragma unroll
                for (int jp = 0; jp < 12; jp++) {
                    uint32_t d0, d1, d2, d3;
                    ldm_x4_t(d0, d1, d2, d3, krow + jp * 32);
                    uint32_t b0[2] = { d0, d1 };
                    uint32_t b1[2] = { d2, d3 };
                    mma_f16(oacc[2 * jp], pa, b0);
                    mma_f16(oacc[2 * jp + 1], pa, b1);
                }
            }
        }
        // no trailing sync: 3-stage ring + issue-after-sync makes overwrite safe
    }

    const float inv0 = 1.0f / lrow[0];
    const float inv1 = 1.0f / lrow[1];
    const size_t base0 = ((size_t)b * cL + (m0 + wr + qr)) * cNQ + (size_t)h * cDQK;
    const size_t base1 = base0 + 8 * cNQ;
#pragma unroll
    for (int j = 0; j < 24; j++) {
        const int c = j * 8 + 2 * qc;
        *reinterpret_cast<__half2*>(&g_AOh[base0 + c]) =
            __floats2half2_rn(oacc[j][0] * inv0, oacc[j][1] * inv0);
        *reinterpret_cast<__half2*>(&g_AOh[base1 + c]) =
            __floats2half2_rn(oacc[j][2] * inv1, oacc[j][3] * inv1);
    }
}

// ---------------- prep kernels ----------------
__global__ void f2h_kernel(const float* __restrict__ s, __half* __restrict__ d, size_t n)
{
    size_t i = ((size_t)blockIdx.x * blockDim.x + threadIdx.x) * 4;
    if (i >= n) return;
    float4 v = *reinterpret_cast<const float4*>(&s[i]);
    *reinterpret_cast<__half2*>(&d[i]) = __floats2half2_rn(v.x, v.y);
    *reinterpret_cast<__half2*>(&d[i + 2]) = __floats2half2_rn(v.z, v.w);
}

__global__ void transpose_h_kernel(const float* __restrict__ src, __half* __restrict__ dst,
                                   int R, int C)
{
    __shared__ float t[32][33];
    const int c0 = blockIdx.x * 32, r0 = blockIdx.y * 32;
    const int x = threadIdx.x, y = threadIdx.y;
#pragma unroll
    for (int dy = 0; dy < 32; dy += 8)
        t[y + dy][x] = src[(size_t)(r0 + y + dy) * C + c0 + x];
    __syncthreads();
#pragma unroll
    for (int dy = 0; dy < 32; dy += 8)
        dst[(size_t)(c0 + y + dy) * R + r0 + x] = __float2half_rn(t[x][y + dy]);
}

// ---------------- gather Q/K/V with fused RoPE ----------------
__global__ void build_qkv_kernel(const float* __restrict__ cosT, const float* __restrict__ sinT)
{
    size_t idx = (size_t)blockIdx.x * blockDim.x + threadIdx.x;
    const size_t total = (size_t)cBH * cL * (cDQK / 2);
    if (idx >= total) return;
    int d2 = (int)(idx % (cDQK / 2));
    int l = (int)((idx / (cDQK / 2)) % cL);
    int bh = (int)(idx / ((size_t)(cDQK / 2) * cL));
    int b = bh / cH, h = bh % cH;
    size_t row = (size_t)b * cL + l;
    int d = 2 * d2;

    __half2 q, k, v;
    const size_t upo = row * cNUP + (size_t)h * (2 * cDH + cRD);
    if (d < cDH) {
        q = *reinterpret_cast<const __half2*>(&g_qallh[row * cNQ + h * cDQK + d]);
        k = *reinterpret_cast<const __half2*>(&g_uph[upo + d]);
        v = *reinterpret_cast<const __half2*>(&g_uph[upo + cDH + d]);
    } else {
        int i = (d - cDH) >> 1;
        float c = cosT[l * (cRD / 2) + i];
        float s = sinT[l * (cRD / 2) + i];
        float2 qv = __half22float2(
            *reinterpret_cast<const __half2*>(&g_qallh[row * cNQ + h * cDQK + d]));
        q = __floats2half2_rn(qv.x * c - qv.y * s, qv.x * s + qv.y * c);
        float2 kv2 = __half22float2(
            *reinterpret_cast<const __half2*>(&g_kvh[row * cNKV + cRK + (d - cDH)]));
        k = __floats2half2_rn(kv2.x * c - kv2.y * s, kv2.x * s + kv2.y * c);
        v = *reinterpret_cast<const __half2*>(&g_uph[upo + 2 * cDH + (d - cDH)]);
    }
    reinterpret_cast<__half2*>(g_Qh)[idx] = q;
    reinterpret_cast<__half2*>(g_Kh)[idx] = k;
    reinterpret_cast<__half2*>(g_Vh)[idx] = v;
}

// ---------------- launch ----------------
extern "C" void kernel_launch(void* const* d_in, const int* in_sizes, int n_in,
                              void* d_out, int out_size)
{
    const float* x    = (const float*)d_in[0];
    const float* cosT = (const float*)d_in[1];
    const float* sinT = (const float*)d_in[2];
    const float* wq   = (const float*)d_in[3];
    const float* wkvd = (const float*)d_in[4];
    const float* wup  = (const float*)d_in[5];
    const float* wout = (const float*)d_in[6];
    float* out = (float*)d_out;

    __half *p_xh, *p_wqT, *p_wkvT, *p_wupT, *p_woT;
    __half *p_qall, *p_kv, *p_up, *p_ao;
    cudaGetSymbolAddress((void**)&p_xh,   g_xh);
    cudaGetSymbolAddress((void**)&p_wqT,  g_wqT);
    cudaGetSymbolAddress((void**)&p_wkvT, g_wkvT);
    cudaGetSymbolAddress((void**)&p_wupT, g_wupT);
    cudaGetSymbolAddress((void**)&p_woT,  g_woT);
    cudaGetSymbolAddress((void**)&p_qall, g_qallh);
    cudaGetSymbolAddress((void**)&p_kv,   g_kvh);
    cudaGetSymbolAddress((void**)&p_up,   g_uph);
    cudaGetSymbolAddress((void**)&p_ao,   g_AOh);

    cudaFuncSetAttribute(flash_attn_kernel,
                         cudaFuncAttributeMaxDynamicSharedMemorySize, FSMEM);
    cudaFuncSetAttribute((const void*)tgemm_h3<128, 64, 32, false>,
                         cudaFuncAttributeMaxDynamicSharedMemorySize, SM_G128);
    cudaFuncSetAttribute((const void*)tgemm_h3<64, 32, 32, false>,
                         cudaFuncAttributeMaxDynamicSharedMemorySize, SM_G64);
    cudaFuncSetAttribute((const void*)tgemm_h3<128, 64, 32, true>,
                         cudaFuncAttributeMaxDynamicSharedMemorySize, SM_G128);

    const float scale = 1.0f / sqrtf((float)cDQK);
    dim3 tblk(32, 8);

    // 0) converts + weight transposes
    f2h_kernel<<<(unsigned)(((size_t)cM * cE / 4 + 255) / 256), 256>>>(x, p_xh, (size_t)cM * cE);
    transpose_h_kernel<<<dim3(cNQ / 32, cE / 32), tblk>>>(wq, p_wqT, cE, cNQ);
    transpose_h_kernel<<<dim3(cNKV / 32, cE / 32), tblk>>>(wkvd, p_wkvT, cE, cNKV);
    transpose_h_kernel<<<dim3(cNUP / 32, cRK / 32), tblk>>>(wup, p_wupT, cRK, cNUP);
    transpose_h_kernel<<<dim3(cE / 32, cNQ / 32), tblk>>>(wout, p_woT, cNQ, cE);

    // 1) q_all = x @ wq   (tiles 32 x 24)
    tgemm_h3<128, 64, 32, false><<<PGRID, 256, SM_G128>>>(
        p_xh, p_wqT, p_qall, cE, cE, cE, cNQ, cM / 128, cNQ / 128);
    // 2) kv_lat = x @ wkv_down   (tiles 32 x 9)
    tgemm_h3<64, 32, 32, false><<<PGRID, 256, SM_G64>>>(
        p_xh, p_wkvT, p_kv, cE, cE, cE, cNKV, cM / 128, cNKV / 64);
    // 3) up = c_kv @ w_up   (tiles 32 x 40)
    tgemm_h3<128, 64, 32, false><<<PGRID, 256, SM_G128>>>(
        p_kv, p_wupT, p_up, cRK, cNKV, cRK, cNUP, cM / 128, cNUP / 128);
    // 4) gather + fused RoPE
    {
        size_t total = (size_t)cBH * cL * (cDQK / 2);
        build_qkv_kernel<<<(unsigned)((total + 255) / 256), 256>>>(cosT, sinT);
    }
    // 5) fused flash attention
    flash_attn_kernel<<<dim3(cL / FBR, cBH), 256, FSMEM>>>(scale);
    // 6) out = AO @ w_out (fp32 output, tiles 32 x 16)
    tgemm_h3<128, 64, 32, true><<<PGRID, 256, SM_G128>>>(
        p_ao, p_woT, out, cNQ, cNQ, cNQ, cE, cM / 128, cE / 128);
}

// round 11
// speedup vs baseline: 2.7048x; 1.0195x over previous
#include <cuda_runtime.h>
#include <cuda_fp16.h>
#include <math.h>
#include <stdint.h>

// ---------------- problem constants ----------------
constexpr int cH   = 16;
constexpr int cDH  = 128;
constexpr int cRK  = 512;
constexpr int cRD  = 64;
constexpr int cB   = 2;
constexpr int cL   = 2048;
constexpr int cE   = 2048;
constexpr int cDQK = cDH + cRD;          // 192
constexpr int cNQ  = cH * cDQK;          // 3072
constexpr int cNKV = cRK + cRD;          // 576
constexpr int cNUP = cH * (2*cDH + cRD); // 5120 (per-head block of 320)
constexpr int cM   = cB * cL;            // 4096
constexpr int cBH  = cB * cH;            // 32
constexpr int PGRID = 296;               // persistent grid (2 per SM x 148)

// ---------------- scratch (half everywhere) ----------------
__device__ __half g_xh   [(size_t)cM * cE];
__device__ __half g_wqT  [(size_t)cNQ * cE];
__device__ __half g_wkvT [(size_t)cNKV * cE];
__device__ __half g_wupT [(size_t)cNUP * cRK];
__device__ __half g_woT  [(size_t)cE * cNQ];
__device__ __half g_qallh[(size_t)cM * cNQ];
__device__ __half g_kvh  [(size_t)cM * cNKV];
__device__ __half g_uph  [(size_t)cM * cNUP];
__device__ __half g_AOh  [(size_t)cM * cNQ];

// ---------------- low-level helpers ----------------
__device__ __forceinline__ void mma_f16(float* d, const uint32_t* a, const uint32_t* b) {
    asm volatile(
        "mma.sync.aligned.m16n8k16.row.col.f32.f16.f16.f32 "
        "{%0,%1,%2,%3},{%4,%5,%6,%7},{%8,%9},{%0,%1,%2,%3};"
        : "+f"(d[0]), "+f"(d[1]), "+f"(d[2]), "+f"(d[3])
        : "r"(a[0]), "r"(a[1]), "r"(a[2]), "r"(a[3]), "r"(b[0]), "r"(b[1]));
}
__device__ __forceinline__ void cpa16(uint32_t s, const void* g) {
    asm volatile("cp.async.cg.shared.global [%0], [%1], 16;\n" :: "r"(s), "l"(g));
}
__device__ __forceinline__ void cp_commit() {
    asm volatile("cp.async.commit_group;\n" ::: "memory");
}
template<int N>
__device__ __forceinline__ void cp_wait() {
    asm volatile("cp.async.wait_group %0;\n" :: "n"(N) : "memory");
}
__device__ __forceinline__ void ldm_x4(uint32_t& d0, uint32_t& d1, uint32_t& d2, uint32_t& d3,
                                       uint32_t addr) {
    asm volatile("ldmatrix.sync.aligned.m8n8.x4.shared.b16 {%0,%1,%2,%3},[%4];"
                 : "=r"(d0), "=r"(d1), "=r"(d2), "=r"(d3) : "r"(addr));
}
__device__ __forceinline__ void ldm_x4_t(uint32_t& d0, uint32_t& d1, uint32_t& d2, uint32_t& d3,
                                         uint32_t addr) {
    asm volatile("ldmatrix.sync.aligned.m8n8.x4.trans.shared.b16 {%0,%1,%2,%3},[%4];"
                 : "=r"(d0), "=r"(d1), "=r"(d2), "=r"(d3) : "r"(addr));
}
__device__ __forceinline__ uint32_t pack_h2(float a, float b) {
    __half2 h = __floats2half2_rn(a, b);
    return *reinterpret_cast<uint32_t*>(&h);
}

// ---------------- fp16 GEMM v3: persistent CTAs (R9 winner, unchanged) ----------------
constexpr int GAW = 20;

template<int TBN_, int WM, int WN, bool OUTF>
__global__ void __launch_bounds__(256, 2)
tgemm_h3(const __half* __restrict__ A, const __half* __restrict__ B,
         void* __restrict__ Cout, int K, int lda, int ldb, int ldc,
         int tilesM, int tilesN)
{
    constexpr int MI = WM / 16;
    constexpr int NJ = WN / 8;
    constexpr int WARPS_M = 128 / WM;
    constexpr int STAGE_W = (128 + TBN_) * GAW;

    extern __shared__ uint32_t smem[];

    const int tid  = threadIdx.x;
    const int lane = tid & 31;
    const int warp = tid >> 5;
    const int wm0 = (warp % WARPS_M) * WM;
    const int wn0 = (warp / WARPS_M) * WN;
    const int lr = lane & 7, lm = lane >> 3;
    const int qr = lane >> 2, qc = lane & 3;

    const uint32_t sbase = (uint32_t)__cvta_generic_to_shared(smem);
    const int r2 = tid >> 1;
    const int c2 = (tid & 1) * 2;

    const int NT = K / 32;
    const int ntiles = tilesM * tilesN;

    for (int t = blockIdx.x; t < ntiles; t += gridDim.x) {
        const int m0 = (t / tilesN) * 128;
        const int n0 = (t % tilesN) * TBN_;

        auto issueTile = [&](int k0, int st) {
            const uint32_t abase = sbase + st * (STAGE_W * 4);
            const uint32_t bbase = abase + 128 * (GAW * 4);
#pragma unroll
            for (int c = 0; c < 2; c++) {
                cpa16(abase + r2 * (GAW * 4) + (c2 + c) * 16,
                      (const char*)A + ((size_t)(m0 + r2) * lda + k0) * 2 + (c2 + c) * 16);
            }
            if (TBN_ == 128) {
#pragma unroll
                for (int c = 0; c < 2; c++) {
                    cpa16(bbase + r2 * (GAW * 4) + (c2 + c) * 16,
                          (const char*)B + ((size_t)(n0 + r2) * ldb + k0) * 2 + (c2 + c) * 16);
                }
            } else {
                int rb = tid >> 2, cb = tid & 3;
                cpa16(bbase + rb * (GAW * 4) + cb * 16,
                      (const char*)B + ((size_t)(n0 + rb) * ldb + k0) * 2 + cb * 16);
            }
            cp_commit();
        };

        float acc[MI][NJ][4];
#pragma unroll
        for (int i = 0; i < MI; i++)
#pragma unroll
            for (int j = 0; j < NJ; j++)
#pragma unroll
                for (int r = 0; r < 4; r++) acc[i][j][r] = 0.0f;

        issueTile(0, 0);
        issueTile(32, 1);

        for (int kt = 0; kt < NT; kt++) {
            if (kt == NT - 1) cp_wait<0>(); else cp_wait<1>();
            __syncthreads();
            if (kt + 2 < NT) issueTile((kt + 2) * 32, (kt + 2) % 3);

            const int st = kt % 3;
            const uint32_t abase = sbase + st * (STAGE_W * 4);
            const uint32_t bbase = abase + 128 * (GAW * 4);

#pragma unroll
            for (int s = 0; s < 2; s++) {
                uint32_t a[MI][4], b[NJ][2];
#pragma unroll
                for (int i = 0; i < MI; i++) {
                    uint32_t addr = abase +
                        (uint32_t)(wm0 + i * 16 + (lm & 1) * 8 + lr) * (GAW * 4) +
                        s * 32 + (lm >> 1) * 16;
                    ldm_x4(a[i][0], a[i][1], a[i][2], a[i][3], addr);
                }
#pragma unroll
                for (int p = 0; p < NJ / 2; p++) {
                    uint32_t addr = bbase +
                        (uint32_t)(wn0 + p * 16 + (lm >> 1) * 8 + lr) * (GAW * 4) +
                        s * 32 + (lm & 1) * 16;
                    ldm_x4(b[2 * p][0], b[2 * p][1], b[2 * p + 1][0], b[2 * p + 1][1], addr);
                }
#pragma unroll
                for (int i = 0; i < MI; i++)
#pragma unroll
                    for (int j = 0; j < NJ; j++)
                        mma_f16(acc[i][j], a[i], b[j]);
            }
        }

#pragma unroll
        for (int i = 0; i < MI; i++) {
#pragma unroll
            for (int j = 0; j < NJ; j++) {
                const int r = m0 + wm0 + i * 16 + qr;
                const int c = n0 + wn0 + j * 8 + 2 * qc;
                if (OUTF) {
                    float* C = (float*)Cout;
                    float2 v0 = { acc[i][j][0], acc[i][j][1] };
                    float2 v1 = { acc[i][j][2], acc[i][j][3] };
                    *reinterpret_cast<float2*>(&C[(size_t)r * ldc + c]) = v0;
                    *reinterpret_cast<float2*>(&C[(size_t)(r + 8) * ldc + c]) = v1;
                } else {
                    __half* C = (__half*)Cout;
                    *reinterpret_cast<__half2*>(&C[(size_t)r * ldc + c]) =
                        __floats2half2_rn(acc[i][j][0], acc[i][j][1]);
                    *reinterpret_cast<__half2*>(&C[(size_t)(r + 8) * ldc + c]) =
                        __floats2half2_rn(acc[i][j][2], acc[i][j][3]);
                }
            }
        }
        __syncthreads();
    }
}

constexpr int SM_G128 = (128 + 128) * GAW * 4 * 3;   // 61,440 B
constexpr int SM_G64  = (128 + 64)  * GAW * 4 * 3;   // 46,080 B

// ---------------- fused flash attention v5: direct reads from producers ----------------
// Q from g_qallh (contiguous 192-slice per row), K = up[...,0:128) ++ kv[...,512:576),
// V = up[...,128:320) (contiguous). No gather kernel, no Q/K/V copies.
constexpr int FBR = 128;
constexpr int FBC = 64;
constexpr int FQW = 100;
constexpr int FW_Q = FBR * FQW;
constexpr int FW_KV = FBC * FQW;
constexpr int FSTG = 2 * FW_KV;
constexpr int FSMEM = (FW_Q + 3 * FSTG) * 4;     // 204,800 B

__global__ void __launch_bounds__(256, 1)
flash_attn_kernel(float scale)
{
    extern __shared__ uint32_t sh[];
    uint32_t* Qs = sh;

    const int mb = (int)gridDim.x - 1 - (int)blockIdx.x;
    const int bh = blockIdx.y;
    const int b = bh / cH, h = bh % cH;
    const int m0 = mb * FBR;
    const int tid = threadIdx.x;
    const int lane = tid & 31, warp = tid >> 5;
    const int wr = warp * 16;
    const int qr = lane >> 2, qc = lane & 3;
    const int lr = lane & 7, lm = lane >> 3;

    // direct source bases (all 16B-aligned)
    const char* Qb  = (const char*)g_qallh + ((size_t)b * cL * cNQ + (size_t)h * cDQK) * 2;
    const char* upK = (const char*)g_uph   + ((size_t)b * cL * cNUP + (size_t)h * 320) * 2;
    const char* kvK = (const char*)g_kvh   + ((size_t)b * cL * cNKV + cRK) * 2;

    const uint32_t qs_addr = (uint32_t)__cvta_generic_to_shared(Qs);
    const uint32_t st_addr = qs_addr + FW_Q * 4;

    auto prefetchKV = [&](int kb, int st) {
        const uint32_t kb_s = st_addr + st * (FSTG * 4);
        const uint32_t vb_s = kb_s + FW_KV * 4;
#pragma unroll
        for (int n = 0; n < 6; n++) {
            int idx = tid + n * 256;
            int r = idx / 24, c = idx % 24;
            const size_t key = (size_t)(kb * FBC + r);
            const char* ksrc = (c < 16)
                ? upK + key * (cNUP * 2) + c * 16
                : kvK + key * (cNKV * 2) + (c - 16) * 16;
            cpa16(kb_s + r * (FQW * 4) + c * 16, ksrc);
            cpa16(vb_s + r * (FQW * 4) + c * 16, upK + 256 + key * (cNUP * 2) + c * 16);
        }
        cp_commit();
    };

    const int kbmax = 2 * mb + 1;

    prefetchKV(0, 0);
    // Q tile -> smem (rows strided by cNQ)
    for (int n = 0; n < 12; n++) {
        int idx = tid + n * 256;
        int r = idx / 24, c = idx % 24;
        uint4 v = *reinterpret_cast<const uint4*>(Qb + (size_t)(m0 + r) * (cNQ * 2) + c * 16);
        *reinterpret_cast<uint4*>((char*)Qs + r * (FQW * 4) + c * 16) = v;
    }
    if (1 <= kbmax) prefetchKV(1, 1);
    __syncthreads();

    // hoist Q fragments (loop-invariant)
    uint32_t qa[12][4];
#pragma unroll
    for (int ks = 0; ks < 12; ks++) {
        uint32_t addr = qs_addr +
            (uint32_t)(wr + (lm & 1) * 8 + lr) * (FQW * 4) +
            ks * 32 + (lm >> 1) * 16;
        ldm_x4(qa[ks][0], qa[ks][1], qa[ks][2], qa[ks][3], addr);
    }

    float oacc[24][4];
#pragma unroll
    for (int j = 0; j < 24; j++)
#pragma unroll
        for (int e = 0; e < 4; e++) oacc[j][e] = 0.0f;
    float mrow[2] = { -1e30f, -1e30f };
    float lrow[2] = { 0.0f, 0.0f };

    const int rowg0 = m0 + wr + qr;
    for (int kb = 0; kb <= kbmax; kb++) {
        if (kb < kbmax) cp_wait<1>(); else cp_wait<0>();
        __syncthreads();
        if (kb + 2 <= kbmax) prefetchKV(kb + 2, (kb + 2) % 3);

        const bool skip = (kb * FBC > m0 + wr + 15);
        if (!skip) {
            const uint32_t kbuf = st_addr + (kb % 3) * (FSTG * 4);
            const uint32_t vbuf = kbuf + FW_KV * 4;

            float sacc[8][4];
#pragma unroll
            for (int j = 0; j < 8; j++)
#pragma unroll
                for (int e = 0; e < 4; e++) sacc[j][e] = 0.0f;

#pragma unroll
            for (int ks = 0; ks < 12; ks++) {
#pragma unroll
                for (int p = 0; p < 4; p++) {
                    uint32_t b2[4];
                    uint32_t addr = kbuf +
                        (uint32_t)(p * 16 + (lm >> 1) * 8 + lr) * (FQW * 4) +
                        ks * 32 + (lm & 1) * 16;
                    ldm_x4(b2[0], b2[1], b2[2], b2[3], addr);
                    uint32_t b0[2] = { b2[0], b2[1] };
                    uint32_t b1[2] = { b2[2], b2[3] };
                    mma_f16(sacc[2 * p], qa[ks], b0);
                    mma_f16(sacc[2 * p + 1], qa[ks], b1);
                }
            }

            const bool diag = (kb * FBC + FBC - 1 > m0 + wr);
            float tmax[2] = { -1e30f, -1e30f };
#pragma unroll
            for (int j = 0; j < 8; j++) {
#pragma unroll
                for (int e = 0; e < 4; e++) {
                    float s = sacc[j][e] * scale;
                    if (diag) {
                        int col = kb * FBC + j * 8 + 2 * qc + (e & 1);
                        int row = rowg0 + 8 * (e >> 1);
                        if (col > row) s = -1e30f;
                    }
                    sacc[j][e] = s;
                    tmax[e >> 1] = fmaxf(tmax[e >> 1], s);
                }
            }
#pragma unroll
            for (int half = 0; half < 2; half++) {
                tmax[half] = fmaxf(tmax[half], __shfl_xor_sync(0xffffffffu, tmax[half], 1));
                tmax[half] = fmaxf(tmax[half], __shfl_xor_sync(0xffffffffu, tmax[half], 2));
            }

            float mnew[2], alf[2], psum[2] = { 0.0f, 0.0f };
#pragma unroll
            for (int half = 0; half < 2; half++) {
                mnew[half] = fmaxf(mrow[half], tmax[half]);
                alf[half] = __expf(mrow[half] - mnew[half]);
                mrow[half] = mnew[half];
            }

#pragma unroll
            for (int j = 0; j < 8; j++) {
                sacc[j][0] = __expf(sacc[j][0] - mnew[0]);
                sacc[j][1] = __expf(sacc[j][1] - mnew[0]);
                sacc[j][2] = __expf(sacc[j][2] - mnew[1]);
                sacc[j][3] = __expf(sacc[j][3] - mnew[1]);
                psum[0] += sacc[j][0] + sacc[j][1];
                psum[1] += sacc[j][2] + sacc[j][3];
            }
#pragma unroll
            for (int half = 0; half < 2; half++) {
                psum[half] += __shfl_xor_sync(0xffffffffu, psum[half], 1);
                psum[half] += __shfl_xor_sync(0xffffffffu, psum[half], 2);
                lrow[half] = lrow[half] * alf[half] + psum[half];
            }

#pragma unroll
            for (int j = 0; j < 24; j++) {
                oacc[j][0] *= alf[0];
                oacc[j][1] *= alf[0];
                oacc[j][2] *= alf[1];
                oacc[j][3] *= alf[1];
            }

            const int g = lane >> 3, lj = lane & 7;
            const uint32_t vrow_base = vbuf + ((g & 1) * 8 + lj) * (FQW * 4) + (g >> 1) * 16;
#pragma unroll
            for (int ks2 = 0; ks2 < 4; ks2++) {
                uint32_t pa[4] = {
                    pack_h2(sacc[2 * ks2][0],     sacc[2 * ks2][1]),
                    pack_h2(sacc[2 * ks2][2],     sacc[2 * ks2][3]),
                    pack_h2(sacc[2 * ks2 + 1][0], sacc[2 * ks2 + 1][1]),
                    pack_h2(sacc[2 * ks2 + 1][2], sacc[2 * ks2 + 1][3])
                };
                const uint32_t krow = vrow_base + ks2 * 16 * (FQW * 4);
#pragma unroll
                for (int jp = 0; jp < 12; jp++) {
                    uint32_t d0, d1, d2, d3;
                    ldm_x4_t(d0, d1, d2, d3, krow + jp * 32);
                    uint32_t b0[2] = { d0, d1 };
                    uint32_t b1[2] = { d2, d3 };
                    mma_f16(oacc[2 * jp], pa, b0);
                    mma_f16(oacc[2 * jp + 1], pa, b1);
                }
            }
        }
    }

    const float inv0 = 1.0f / lrow[0];
    const float inv1 = 1.0f / lrow[1];
    const size_t base0 = ((size_t)b * cL + (m0 + wr + qr)) * cNQ + (size_t)h * cDQK;
    const size_t base1 = base0 + 8 * cNQ;
#pragma unroll
    for (int j = 0; j < 24; j++) {
        const int c = j * 8 + 2 * qc;
        *reinterpret_cast<__half2*>(&g_AOh[base0 + c]) =
            __floats2half2_rn(oacc[j][0] * inv0, oacc[j][1] * inv0);
        *reinterpret_cast<__half2*>(&g_AOh[base1 + c]) =
            __floats2half2_rn(oacc[j][2] * inv1, oacc[j][3] * inv1);
    }
}

// ---------------- prep kernels ----------------
__global__ void f2h_kernel(const float* __restrict__ s, __half* __restrict__ d, size_t n)
{
    size_t i = ((size_t)blockIdx.x * blockDim.x + threadIdx.x) * 8;
    if (i >= n) return;
    float4 a = *reinterpret_cast<const float4*>(&s[i]);
    float4 b = *reinterpret_cast<const float4*>(&s[i + 4]);
    __half2 h[4] = { __floats2half2_rn(a.x, a.y), __floats2half2_rn(a.z, a.w),
                     __floats2half2_rn(b.x, b.y), __floats2half2_rn(b.z, b.w) };
    *reinterpret_cast<uint4*>(&d[i]) = *reinterpret_cast<uint4*>(h);
}

// dst[C][R] (half) = transpose of src[R][C] (float); tile 64 rows x 32 cols,
// dst writes are 16B-wide (64-half rows per tile).
__global__ void transpose_h_kernel(const float* __restrict__ src, __half* __restrict__ dst,
                                   int R, int C)
{
    __shared__ float t[32][65];
    const int c0 = blockIdx.x * 32, r0 = blockIdx.y * 64;
    const int x = threadIdx.x, y = threadIdx.y;   // 32 x 8
#pragma unroll
    for (int ry = 0; ry < 64; ry += 8)
        t[x][ry + y] = src[(size_t)(r0 + ry + y) * C + c0 + x];
    __syncthreads();
    const int tid = y * 32 + x;
    const int drow = tid >> 3;            // 0..31 (dst row = src col)
    const int seg  = (tid & 7) * 8;       // 8 halves per thread
    __half2 h[4];
#pragma unroll
    for (int k = 0; k < 4; k++)
        h[k] = __floats2half2_rn(t[drow][seg + 2 * k], t[drow][seg + 2 * k + 1]);
    *reinterpret_cast<uint4*>(&dst[(size_t)(c0 + drow) * R + r0 + seg]) =
        *reinterpret_cast<uint4*>(h);
}

// ---------------- RoPE (in-place on half, pre-flash) ----------------
__global__ void rope_q_kernel(const float* __restrict__ cosT, const float* __restrict__ sinT)
{
    int idx = blockIdx.x * blockDim.x + threadIdx.x;
    if (idx >= cM * cH * (cRD / 2)) return;
    int i = idx % (cRD / 2);
    int h = (idx / (cRD / 2)) % cH;
    int row = idx / ((cRD / 2) * cH);
    int l = row % cL;
    float c = cosT[l * (cRD / 2) + i];
    float s = sinT[l * (cRD / 2) + i];
    __half2* p = reinterpret_cast<__half2*>(&g_qallh[(size_t)row * cNQ + h * cDQK + cDH + 2 * i]);
    float2 v = __half22float2(*p);
    *p = __floats2half2_rn(v.x * c - v.y * s, v.x * s + v.y * c);
}

__global__ void rope_k_kernel(const float* __restrict__ cosT, const float* __restrict__ sinT)
{
    int idx = blockIdx.x * blockDim.x + threadIdx.x;
    if (idx >= cM * (cRD / 2)) return;
    int i = idx % (cRD / 2);
    int row = idx / (cRD / 2);
    int l = row % cL;
    float c = cosT[l * (cRD / 2) + i];
    float s = sinT[l * (cRD / 2) + i];
    __half2* p = reinterpret_cast<__half2*>(&g_kvh[(size_t)row * cNKV + cRK + 2 * i]);
    float2 v = __half22float2(*p);
    *p = __floats2half2_rn(v.x * c - v.y * s, v.x * s + v.y * c);
}

// ---------------- launch ----------------
extern "C" void kernel_launch(void* const* d_in, const int* in_sizes, int n_in,
                              void* d_out, int out_size)
{
    const float* x    = (const float*)d_in[0];
    const float* cosT = (const float*)d_in[1];
    const float* sinT = (const float*)d_in[2];
    const float* wq   = (const float*)d_in[3];
    const float* wkvd = (const float*)d_in[4];
    const float* wup  = (const float*)d_in[5];
    const float* wout = (const float*)d_in[6];
    float* out = (float*)d_out;

    __half *p_xh, *p_wqT, *p_wkvT, *p_wupT, *p_woT;
    __half *p_qall, *p_kv, *p_up, *p_ao;
    cudaGetSymbolAddress((void**)&p_xh,   g_xh);
    cudaGetSymbolAddress((void**)&p_wqT,  g_wqT);
    cudaGetSymbolAddress((void**)&p_wkvT, g_wkvT);
    cudaGetSymbolAddress((void**)&p_wupT, g_wupT);
    cudaGetSymbolAddress((void**)&p_woT,  g_woT);
    cudaGetSymbolAddress((void**)&p_qall, g_qallh);
    cudaGetSymbolAddress((void**)&p_kv,   g_kvh);
    cudaGetSymbolAddress((void**)&p_up,   g_uph);
    cudaGetSymbolAddress((void**)&p_ao,   g_AOh);

    cudaFuncSetAttribute(flash_attn_kernel,
                         cudaFuncAttributeMaxDynamicSharedMemorySize, FSMEM);
    cudaFuncSetAttribute((const void*)tgemm_h3<128, 64, 32, false>,
                         cudaFuncAttributeMaxDynamicSharedMemorySize, SM_G128);
    cudaFuncSetAttribute((const void*)tgemm_h3<64, 32, 32, false>,
                         cudaFuncAttributeMaxDynamicSharedMemorySize, SM_G64);
    cudaFuncSetAttribute((const void*)tgemm_h3<128, 64, 32, true>,
                         cudaFuncAttributeMaxDynamicSharedMemorySize, SM_G128);

    const float scale = 1.0f / sqrtf((float)cDQK);
    dim3 tblk(32, 8);

    // (1) x -> half
    f2h_kernel<<<(unsigned)(((size_t)cM * cE / 8 + 255) / 256), 256>>>(x, p_xh, (size_t)cM * cE);
    // (2)(3) transposes needed by wq / kv
    transpose_h_kernel<<<dim3(cNQ / 32, cE / 64), tblk>>>(wq, p_wqT, cE, cNQ);
    transpose_h_kernel<<<dim3(cNKV / 32, cE / 64), tblk>>>(wkvd, p_wkvT, cE, cNKV);
    // (4) q_all = x @ wq  — 4th launch: ncu capture lands here
    tgemm_h3<128, 64, 32, false><<<PGRID, 256, SM_G128>>>(
        p_xh, p_wqT, p_qall, cE, cE, cE, cNQ, cM / 128, cNQ / 128);
    // (5) kv_lat = x @ wkv_down
    tgemm_h3<64, 32, 32, false><<<PGRID, 256, SM_G64>>>(
        p_xh, p_wkvT, p_kv, cE, cE, cE, cNKV, cM / 128, cNKV / 64);
    // (6) wup transpose, (7) up = c_kv @ w_up
    transpose_h_kernel<<<dim3(cNUP / 32, cRK / 64), tblk>>>(wup, p_wupT, cRK, cNUP);
    tgemm_h3<128, 64, 32, false><<<PGRID, 256, SM_G128>>>(
        p_kv, p_wupT, p_up, cRK, cNKV, cRK, cNUP, cM / 128, cNUP / 128);
    // (8) wout transpose
    transpose_h_kernel<<<dim3(cE / 32, cNQ / 64), tblk>>>(wout, p_woT, cNQ, cE);
    // (9)(10) RoPE in place
    rope_q_kernel<<<(cM * cH * (cRD / 2) + 255) / 256, 256>>>(cosT, sinT);
    rope_k_kernel<<<(cM * (cRD / 2) + 255) / 256, 256>>>(cosT, sinT);
    // (11) fused flash attention (direct producer reads)
    flash_attn_kernel<<<dim3(cL / FBR, cBH), 256, FSMEM>>>(scale);
    // (12) out = AO @ w_out (fp32 output)
    tgemm_h3<128, 64, 32, true><<<PGRID, 256, SM_G128>>>(
        p_ao, p_woT, out, cNQ, cNQ, cNQ, cE, cM / 128, cE / 128);
}

// round 12
// speedup vs baseline: 3.1486x; 1.1641x over previous
#include <cuda_runtime.h>
#include <cuda_fp16.h>
#include <math.h>
#include <stdint.h>

// ---------------- problem constants ----------------
constexpr int cH   = 16;
constexpr int cDH  = 128;
constexpr int cRK  = 512;
constexpr int cRD  = 64;
constexpr int cB   = 2;
constexpr int cL   = 2048;
constexpr int cE   = 2048;
constexpr int cDQK = cDH + cRD;          // 192
constexpr int cNQ  = cH * cDQK;          // 3072
constexpr int cNKV = cRK + cRD;          // 576
constexpr int cNUP = cH * (2*cDH + cRD); // 5120 (per-head block of 320)
constexpr int cM   = cB * cL;            // 4096
constexpr int cBH  = cB * cH;            // 32
constexpr int PGRID = 296;               // persistent grid (2 per SM x 148)

// ---------------- scratch (half everywhere) ----------------
__device__ __half g_xh   [(size_t)cM * cE];
__device__ __half g_wqT  [(size_t)cNQ * cE];
__device__ __half g_wkvT [(size_t)cNKV * cE];
__device__ __half g_wupT [(size_t)cNUP * cRK];
__device__ __half g_woT  [(size_t)cE * cNQ];
__device__ __half g_qallh[(size_t)cM * cNQ];
__device__ __half g_kvh  [(size_t)cM * cNKV];
__device__ __half g_uph  [(size_t)cM * cNUP];
__device__ __half g_AOh  [(size_t)cM * cNQ];

// ---------------- low-level helpers ----------------
__device__ __forceinline__ void mma_f16(float* d, const uint32_t* a, const uint32_t* b) {
    asm volatile(
        "mma.sync.aligned.m16n8k16.row.col.f32.f16.f16.f32 "
        "{%0,%1,%2,%3},{%4,%5,%6,%7},{%8,%9},{%0,%1,%2,%3};"
        : "+f"(d[0]), "+f"(d[1]), "+f"(d[2]), "+f"(d[3])
        : "r"(a[0]), "r"(a[1]), "r"(a[2]), "r"(a[3]), "r"(b[0]), "r"(b[1]));
}
__device__ __forceinline__ void cpa16(uint32_t s, const void* g) {
    asm volatile("cp.async.cg.shared.global [%0], [%1], 16;\n" :: "r"(s), "l"(g));
}
__device__ __forceinline__ void cp_commit() {
    asm volatile("cp.async.commit_group;\n" ::: "memory");
}
template<int N>
__device__ __forceinline__ void cp_wait() {
    asm volatile("cp.async.wait_group %0;\n" :: "n"(N) : "memory");
}
__device__ __forceinline__ void ldm_x4(uint32_t& d0, uint32_t& d1, uint32_t& d2, uint32_t& d3,
                                       uint32_t addr) {
    asm volatile("ldmatrix.sync.aligned.m8n8.x4.shared.b16 {%0,%1,%2,%3},[%4];"
                 : "=r"(d0), "=r"(d1), "=r"(d2), "=r"(d3) : "r"(addr));
}
__device__ __forceinline__ void ldm_x4_t(uint32_t& d0, uint32_t& d1, uint32_t& d2, uint32_t& d3,
                                         uint32_t addr) {
    asm volatile("ldmatrix.sync.aligned.m8n8.x4.trans.shared.b16 {%0,%1,%2,%3},[%4];"
                 : "=r"(d0), "=r"(d1), "=r"(d2), "=r"(d3) : "r"(addr));
}
__device__ __forceinline__ uint32_t pack_h2(float a, float b) {
    __half2 h = __floats2half2_rn(a, b);
    return *reinterpret_cast<uint32_t*>(&h);
}

// ---------------- fp16 GEMM v4: TBK=64, 3-stage ring, persistent CTAs ----------------
// Stage row = 64 halves + pad: 36 words (144B) -> ldmatrix conflict-free (16k mod 128 distinct).
constexpr int GBW = 36;   // words per 64-half row

template<int TBN_, int WM, int WN, bool OUTF>
__global__ void __launch_bounds__(256, 2)
tgemm_h4(const __half* __restrict__ A, const __half* __restrict__ B,
         void* __restrict__ Cout, int K, int lda, int ldb, int ldc,
         int tilesM, int tilesN)
{
    constexpr int MI = WM / 16;
    constexpr int NJ = WN / 8;
    constexpr int WARPS_M = 128 / WM;
    constexpr int STAGE_W = (128 + TBN_) * GBW;

    extern __shared__ uint32_t smem[];

    const int tid  = threadIdx.x;
    const int lane = tid & 31;
    const int warp = tid >> 5;
    const int wm0 = (warp % WARPS_M) * WM;
    const int wn0 = (warp / WARPS_M) * WN;
    const int lr = lane & 7, lm = lane >> 3;
    const int qr = lane >> 2, qc = lane & 3;

    const uint32_t sbase = (uint32_t)__cvta_generic_to_shared(smem);

    const int NT = K / 64;
    const int ntiles = tilesM * tilesN;

    for (int t = blockIdx.x; t < ntiles; t += gridDim.x) {
        const int m0 = (t / tilesN) * 128;
        const int n0 = (t % tilesN) * TBN_;

        auto issueTile = [&](int k0, int st) {
            const uint32_t abase = sbase + st * (STAGE_W * 4);
            const uint32_t bbase = abase + 128 * (GBW * 4);
#pragma unroll
            for (int n = 0; n < 4; n++) {          // A: 128 rows x 8 chunks = 1024
                int idx = tid + n * 256;
                int row = idx >> 3, c = idx & 7;
                cpa16(abase + row * (GBW * 4) + c * 16,
                      (const char*)A + ((size_t)(m0 + row) * lda + k0) * 2 + c * 16);
            }
#pragma unroll
            for (int n = 0; n < TBN_ / 32; n++) {  // B: TBN rows x 8 chunks
                int idx = tid + n * 256;
                int row = idx >> 3, c = idx & 7;
                cpa16(bbase + row * (GBW * 4) + c * 16,
                      (const char*)B + ((size_t)(n0 + row) * ldb + k0) * 2 + c * 16);
            }
            cp_commit();
        };

        float acc[MI][NJ][4];
#pragma unroll
        for (int i = 0; i < MI; i++)
#pragma unroll
            for (int j = 0; j < NJ; j++)
#pragma unroll
                for (int r = 0; r < 4; r++) acc[i][j][r] = 0.0f;

        issueTile(0, 0);
        issueTile(64, 1);

        for (int kt = 0; kt < NT; kt++) {
            if (kt == NT - 1) cp_wait<0>(); else cp_wait<1>();
            __syncthreads();
            if (kt + 2 < NT) issueTile((kt + 2) * 64, (kt + 2) % 3);

            const int st = kt % 3;
            const uint32_t abase = sbase + st * (STAGE_W * 4);
            const uint32_t bbase = abase + 128 * (GBW * 4);

#pragma unroll
            for (int s = 0; s < 4; s++) {          // 4 x k16 per stage
                uint32_t a[MI][4], b[NJ][2];
#pragma unroll
                for (int i = 0; i < MI; i++) {
                    uint32_t addr = abase +
                        (uint32_t)(wm0 + i * 16 + (lm & 1) * 8 + lr) * (GBW * 4) +
                        s * 32 + (lm >> 1) * 16;
                    ldm_x4(a[i][0], a[i][1], a[i][2], a[i][3], addr);
                }
#pragma unroll
                for (int p = 0; p < NJ / 2; p++) {
                    uint32_t addr = bbase +
                        (uint32_t)(wn0 + p * 16 + (lm >> 1) * 8 + lr) * (GBW * 4) +
                        s * 32 + (lm & 1) * 16;
                    ldm_x4(b[2 * p][0], b[2 * p][1], b[2 * p + 1][0], b[2 * p + 1][1], addr);
                }
#pragma unroll
                for (int i = 0; i < MI; i++)
#pragma unroll
                    for (int j = 0; j < NJ; j++)
                        mma_f16(acc[i][j], a[i], b[j]);
            }
        }

#pragma unroll
        for (int i = 0; i < MI; i++) {
#pragma unroll
            for (int j = 0; j < NJ; j++) {
                const int r = m0 + wm0 + i * 16 + qr;
                const int c = n0 + wn0 + j * 8 + 2 * qc;
                if (OUTF) {
                    float* C = (float*)Cout;
                    float2 v0 = { acc[i][j][0], acc[i][j][1] };
                    float2 v1 = { acc[i][j][2], acc[i][j][3] };
                    *reinterpret_cast<float2*>(&C[(size_t)r * ldc + c]) = v0;
                    *reinterpret_cast<float2*>(&C[(size_t)(r + 8) * ldc + c]) = v1;
                } else {
                    __half* C = (__half*)Cout;
                    *reinterpret_cast<__half2*>(&C[(size_t)r * ldc + c]) =
                        __floats2half2_rn(acc[i][j][0], acc[i][j][1]);
                    *reinterpret_cast<__half2*>(&C[(size_t)(r + 8) * ldc + c]) =
                        __floats2half2_rn(acc[i][j][2], acc[i][j][3]);
                }
            }
        }
        __syncthreads();   // protect stage buffers before next tile's prologue
    }
}

constexpr int SM4_G128 = (128 + 128) * GBW * 4 * 3;   // 110,592 B
constexpr int SM4_G64  = (128 + 64)  * GBW * 4 * 3;   //  82,944 B

// ---------------- fused flash attention v5 (R11 winner, unchanged) ----------------
constexpr int FBR = 128;
constexpr int FBC = 64;
constexpr int FQW = 100;
constexpr int FW_Q = FBR * FQW;
constexpr int FW_KV = FBC * FQW;
constexpr int FSTG = 2 * FW_KV;
constexpr int FSMEM = (FW_Q + 3 * FSTG) * 4;     // 204,800 B

__global__ void __launch_bounds__(256, 1)
flash_attn_kernel(float scale)
{
    extern __shared__ uint32_t sh[];
    uint32_t* Qs = sh;

    const int mb = (int)gridDim.x - 1 - (int)blockIdx.x;
    const int bh = blockIdx.y;
    const int b = bh / cH, h = bh % cH;
    const int m0 = mb * FBR;
    const int tid = threadIdx.x;
    const int lane = tid & 31, warp = tid >> 5;
    const int wr = warp * 16;
    const int qr = lane >> 2, qc = lane & 3;
    const int lr = lane & 7, lm = lane >> 3;

    const char* Qb  = (const char*)g_qallh + ((size_t)b * cL * cNQ + (size_t)h * cDQK) * 2;
    const char* upK = (const char*)g_uph   + ((size_t)b * cL * cNUP + (size_t)h * 320) * 2;
    const char* kvK = (const char*)g_kvh   + ((size_t)b * cL * cNKV + cRK) * 2;

    const uint32_t qs_addr = (uint32_t)__cvta_generic_to_shared(Qs);
    const uint32_t st_addr = qs_addr + FW_Q * 4;

    auto prefetchKV = [&](int kb, int st) {
        const uint32_t kb_s = st_addr + st * (FSTG * 4);
        const uint32_t vb_s = kb_s + FW_KV * 4;
#pragma unroll
        for (int n = 0; n < 6; n++) {
            int idx = tid + n * 256;
            int r = idx / 24, c = idx % 24;
            const size_t key = (size_t)(kb * FBC + r);
            const char* ksrc = (c < 16)
                ? upK + key * (cNUP * 2) + c * 16
                : kvK + key * (cNKV * 2) + (c - 16) * 16;
            cpa16(kb_s + r * (FQW * 4) + c * 16, ksrc);
            cpa16(vb_s + r * (FQW * 4) + c * 16, upK + 256 + key * (cNUP * 2) + c * 16);
        }
        cp_commit();
    };

    const int kbmax = 2 * mb + 1;

    prefetchKV(0, 0);
    for (int n = 0; n < 12; n++) {
        int idx = tid + n * 256;
        int r = idx / 24, c = idx % 24;
        uint4 v = *reinterpret_cast<const uint4*>(Qb + (size_t)(m0 + r) * (cNQ * 2) + c * 16);
        *reinterpret_cast<uint4*>((char*)Qs + r * (FQW * 4) + c * 16) = v;
    }
    if (1 <= kbmax) prefetchKV(1, 1);
    __syncthreads();

    uint32_t qa[12][4];
#pragma unroll
    for (int ks = 0; ks < 12; ks++) {
        uint32_t addr = qs_addr +
            (uint32_t)(wr + (lm & 1) * 8 + lr) * (FQW * 4) +
            ks * 32 + (lm >> 1) * 16;
        ldm_x4(qa[ks][0], qa[ks][1], qa[ks][2], qa[ks][3], addr);
    }

    float oacc[24][4];
#pragma unroll
    for (int j = 0; j < 24; j++)
#pragma unroll
        for (int e = 0; e < 4; e++) oacc[j][e] = 0.0f;
    float mrow[2] = { -1e30f, -1e30f };
    float lrow[2] = { 0.0f, 0.0f };

    const int rowg0 = m0 + wr + qr;
    for (int kb = 0; kb <= kbmax; kb++) {
        if (kb < kbmax) cp_wait<1>(); else cp_wait<0>();
        __syncthreads();
        if (kb + 2 <= kbmax) prefetchKV(kb + 2, (kb + 2) % 3);

        const bool skip = (kb * FBC > m0 + wr + 15);
        if (!skip) {
            const uint32_t kbuf = st_addr + (kb % 3) * (FSTG * 4);
            const uint32_t vbuf = kbuf + FW_KV * 4;

            float sacc[8][4];
#pragma unroll
            for (int j = 0; j < 8; j++)
#pragma unroll
                for (int e = 0; e < 4; e++) sacc[j][e] = 0.0f;

#pragma unroll
            for (int ks = 0; ks < 12; ks++) {
#pragma unroll
                for (int p = 0; p < 4; p++) {
                    uint32_t b2[4];
                    uint32_t addr = kbuf +
                        (uint32_t)(p * 16 + (lm >> 1) * 8 + lr) * (FQW * 4) +
                        ks * 32 + (lm & 1) * 16;
                    ldm_x4(b2[0], b2[1], b2[2], b2[3], addr);
                    uint32_t b0[2] = { b2[0], b2[1] };
                    uint32_t b1[2] = { b2[2], b2[3] };
                    mma_f16(sacc[2 * p], qa[ks], b0);
                    mma_f16(sacc[2 * p + 1], qa[ks], b1);
                }
            }

            const bool diag = (kb * FBC + FBC - 1 > m0 + wr);
            float tmax[2] = { -1e30f, -1e30f };
#pragma unroll
            for (int j = 0; j < 8; j++) {
#pragma unroll
                for (int e = 0; e < 4; e++) {
                    float s = sacc[j][e] * scale;
                    if (diag) {
                        int col = kb * FBC + j * 8 + 2 * qc + (e & 1);
                        int row = rowg0 + 8 * (e >> 1);
                        if (col > row) s = -1e30f;
                    }
                    sacc[j][e] = s;
                    tmax[e >> 1] = fmaxf(tmax[e >> 1], s);
                }
            }
#pragma unroll
            for (int half = 0; half < 2; half++) {
                tmax[half] = fmaxf(tmax[half], __shfl_xor_sync(0xffffffffu, tmax[half], 1));
                tmax[half] = fmaxf(tmax[half], __shfl_xor_sync(0xffffffffu, tmax[half], 2));
            }

            float mnew[2], alf[2], psum[2] = { 0.0f, 0.0f };
#pragma unroll
            for (int half = 0; half < 2; half++) {
                mnew[half] = fmaxf(mrow[half], tmax[half]);
                alf[half] = __expf(mrow[half] - mnew[half]);
                mrow[half] = mnew[half];
            }

#pragma unroll
            for (int j = 0; j < 8; j++) {
                sacc[j][0] = __expf(sacc[j][0] - mnew[0]);
                sacc[j][1] = __expf(sacc[j][1] - mnew[0]);
                sacc[j][2] = __expf(sacc[j][2] - mnew[1]);
                sacc[j][3] = __expf(sacc[j][3] - mnew[1]);
                psum[0] += sacc[j][0] + sacc[j][1];
                psum[1] += sacc[j][2] + sacc[j][3];
            }
#pragma unroll
            for (int half = 0; half < 2; half++) {
                psum[half] += __shfl_xor_sync(0xffffffffu, psum[half], 1);
                psum[half] += __shfl_xor_sync(0xffffffffu, psum[half], 2);
                lrow[half] = lrow[half] * alf[half] + psum[half];
            }

#pragma unroll
            for (int j = 0; j < 24; j++) {
                oacc[j][0] *= alf[0];
                oacc[j][1] *= alf[0];
                oacc[j][2] *= alf[1];
                oacc[j][3] *= alf[1];
            }

            const int g = lane >> 3, lj = lane & 7;
            const uint32_t vrow_base = vbuf + ((g & 1) * 8 + lj) * (FQW * 4) + (g >> 1) * 16;
#pragma unroll
            for (int ks2 = 0; ks2 < 4; ks2++) {
                uint32_t pa[4] = {
                    pack_h2(sacc[2 * ks2][0],     sacc[2 * ks2][1]),
                    pack_h2(sacc[2 * ks2][2],     sacc[2 * ks2][3]),
                    pack_h2(sacc[2 * ks2 + 1][0], sacc[2 * ks2 + 1][1]),
                    pack_h2(sacc[2 * ks2 + 1][2], sacc[2 * ks2 + 1][3])
                };
                const uint32_t krow = vrow_base + ks2 * 16 * (FQW * 4);
#pragma unroll
                for (int jp = 0; jp < 12; jp++) {
                    uint32_t d0, d1, d2, d3;
                    ldm_x4_t(d0, d1, d2, d3, krow + jp * 32);
                    uint32_t b0[2] = { d0, d1 };
                    uint32_t b1[2] = { d2, d3 };
                    mma_f16(oacc[2 * jp], pa, b0);
                    mma_f16(oacc[2 * jp + 1], pa, b1);
                }
            }
        }
    }

    const float inv0 = 1.0f / lrow[0];
    const float inv1 = 1.0f / lrow[1];
    const size_t base0 = ((size_t)b * cL + (m0 + wr + qr)) * cNQ + (size_t)h * cDQK;
    const size_t base1 = base0 + 8 * cNQ;
#pragma unroll
    for (int j = 0; j < 24; j++) {
        const int c = j * 8 + 2 * qc;
        *reinterpret_cast<__half2*>(&g_AOh[base0 + c]) =
            __floats2half2_rn(oacc[j][0] * inv0, oacc[j][1] * inv0);
        *reinterpret_cast<__half2*>(&g_AOh[base1 + c]) =
            __floats2half2_rn(oacc[j][2] * inv1, oacc[j][3] * inv1);
    }
}

// ---------------- prep kernels ----------------
__global__ void f2h_kernel(const float* __restrict__ s, __half* __restrict__ d, size_t n)
{
    size_t i = ((size_t)blockIdx.x * blockDim.x + threadIdx.x) * 8;
    if (i >= n) return;
    float4 a = *reinterpret_cast<const float4*>(&s[i]);
    float4 b = *reinterpret_cast<const float4*>(&s[i + 4]);
    __half2 h[4] = { __floats2half2_rn(a.x, a.y), __floats2half2_rn(a.z, a.w),
                     __floats2half2_rn(b.x, b.y), __floats2half2_rn(b.z, b.w) };
    *reinterpret_cast<uint4*>(&d[i]) = *reinterpret_cast<uint4*>(h);
}

__global__ void transpose_h_kernel(const float* __restrict__ src, __half* __restrict__ dst,
                                   int R, int C)
{
    __shared__ float t[32][65];
    const int c0 = blockIdx.x * 32, r0 = blockIdx.y * 64;
    const int x = threadIdx.x, y = threadIdx.y;   // 32 x 8
#pragma unroll
    for (int ry = 0; ry < 64; ry += 8)
        t[x][ry + y] = src[(size_t)(r0 + ry + y) * C + c0 + x];
    __syncthreads();
    const int tid = y * 32 + x;
    const int drow = tid >> 3;
    const int seg  = (tid & 7) * 8;
    __half2 h[4];
#pragma unroll
    for (int k = 0; k < 4; k++)
        h[k] = __floats2half2_rn(t[drow][seg + 2 * k], t[drow][seg + 2 * k + 1]);
    *reinterpret_cast<uint4*>(&dst[(size_t)(c0 + drow) * R + r0 + seg]) =
        *reinterpret_cast<uint4*>(h);
}

// ---------------- RoPE (in-place on half) ----------------
__global__ void rope_q_kernel(const float* __restrict__ cosT, const float* __restrict__ sinT)
{
    int idx = blockIdx.x * blockDim.x + threadIdx.x;
    if (idx >= cM * cH * (cRD / 2)) return;
    int i = idx % (cRD / 2);
    int h = (idx / (cRD / 2)) % cH;
    int row = idx / ((cRD / 2) * cH);
    int l = row % cL;
    float c = cosT[l * (cRD / 2) + i];
    float s = sinT[l * (cRD / 2) + i];
    __half2* p = reinterpret_cast<__half2*>(&g_qallh[(size_t)row * cNQ + h * cDQK + cDH + 2 * i]);
    float2 v = __half22float2(*p);
    *p = __floats2half2_rn(v.x * c - v.y * s, v.x * s + v.y * c);
}

__global__ void rope_k_kernel(const float* __restrict__ cosT, const float* __restrict__ sinT)
{
    int idx = blockIdx.x * blockDim.x + threadIdx.x;
    if (idx >= cM * (cRD / 2)) return;
    int i = idx % (cRD / 2);
    int row = idx / (cRD / 2);
    int l = row % cL;
    float c = cosT[l * (cRD / 2) + i];
    float s = sinT[l * (cRD / 2) + i];
    __half2* p = reinterpret_cast<__half2*>(&g_kvh[(size_t)row * cNKV + cRK + 2 * i]);
    float2 v = __half22float2(*p);
    *p = __floats2half2_rn(v.x * c - v.y * s, v.x * s + v.y * c);
}

// ---------------- launch ----------------
extern "C" void kernel_launch(void* const* d_in, const int* in_sizes, int n_in,
                              void* d_out, int out_size)
{
    const float* x    = (const float*)d_in[0];
    const float* cosT = (const float*)d_in[1];
    const float* sinT = (const float*)d_in[2];
    const float* wq   = (const float*)d_in[3];
    const float* wkvd = (const float*)d_in[4];
    const float* wup  = (const float*)d_in[5];
    const float* wout = (const float*)d_in[6];
    float* out = (float*)d_out;

    __half *p_xh, *p_wqT, *p_wkvT, *p_wupT, *p_woT;
    __half *p_qall, *p_kv, *p_up, *p_ao;
    cudaGetSymbolAddress((void**)&p_xh,   g_xh);
    cudaGetSymbolAddress((void**)&p_wqT,  g_wqT);
    cudaGetSymbolAddress((void**)&p_wkvT, g_wkvT);
    cudaGetSymbolAddress((void**)&p_wupT, g_wupT);
    cudaGetSymbolAddress((void**)&p_woT,  g_woT);
    cudaGetSymbolAddress((void**)&p_qall, g_qallh);
    cudaGetSymbolAddress((void**)&p_kv,   g_kvh);
    cudaGetSymbolAddress((void**)&p_up,   g_uph);
    cudaGetSymbolAddress((void**)&p_ao,   g_AOh);

    cudaFuncSetAttribute(flash_attn_kernel,
                         cudaFuncAttributeMaxDynamicSharedMemorySize, FSMEM);
    cudaFuncSetAttribute((const void*)tgemm_h4<128, 64, 32, false>,
                         cudaFuncAttributeMaxDynamicSharedMemorySize, SM4_G128);
    cudaFuncSetAttribute((const void*)tgemm_h4<64, 32, 32, false>,
                         cudaFuncAttributeMaxDynamicSharedMemorySize, SM4_G64);
    cudaFuncSetAttribute((const void*)tgemm_h4<128, 64, 32, true>,
                         cudaFuncAttributeMaxDynamicSharedMemorySize, SM4_G128);

    const float scale = 1.0f / sqrtf((float)cDQK);
    dim3 tblk(32, 8);

    // (1) x -> half
    f2h_kernel<<<(unsigned)(((size_t)cM * cE / 8 + 255) / 256), 256>>>(x, p_xh, (size_t)cM * cE);
    // (2)(3) transposes needed by wq / kv
    transpose_h_kernel<<<dim3(cNQ / 32, cE / 64), tblk>>>(wq, p_wqT, cE, cNQ);
    transpose_h_kernel<<<dim3(cNKV / 32, cE / 64), tblk>>>(wkvd, p_wkvT, cE, cNKV);
    // (4) q_all = x @ wq  — ncu capture lands here
    tgemm_h4<128, 64, 32, false><<<PGRID, 256, SM4_G128>>>(
        p_xh, p_wqT, p_qall, cE, cE, cE, cNQ, cM / 128, cNQ / 128);
    // (5) kv_lat = x @ wkv_down
    tgemm_h4<64, 32, 32, false><<<PGRID, 256, SM4_G64>>>(
        p_xh, p_wkvT, p_kv, cE, cE, cE, cNKV, cM / 128, cNKV / 64);
    // (6) wup transpose, (7) up = c_kv @ w_up
    transpose_h_kernel<<<dim3(cNUP / 32, cRK / 64), tblk>>>(wup, p_wupT, cRK, cNUP);
    tgemm_h4<128, 64, 32, false><<<PGRID, 256, SM4_G128>>>(
        p_kv, p_wupT, p_up, cRK, cNKV, cRK, cNUP, cM / 128, cNUP / 128);
    // (8) wout transpose
    transpose_h_kernel<<<dim3(cE / 32, cNQ / 64), tblk>>>(wout, p_woT, cNQ, cE);
    // (9)(10) RoPE in place
    rope_q_kernel<<<(cM * cH * (cRD / 2) + 255) / 256, 256>>>(cosT, sinT);
    rope_k_kernel<<<(cM * (cRD / 2) + 255) / 256, 256>>>(cosT, sinT);
    // (11) fused flash attention (direct producer reads)
    flash_attn_kernel<<<dim3(cL / FBR, cBH), 256, FSMEM>>>(scale);
    // (12) out = AO @ w_out (fp32 output)
    tgemm_h4<128, 64, 32, true><<<PGRID, 256, SM4_G128>>>(
        p_ao, p_woT, out, cNQ, cNQ, cNQ, cE, cM / 128, cE / 128);
}